// round 1
// baseline (speedup 1.0000x reference)
#include <cuda_runtime.h>
#include <math.h>

#define CDIM   1024
#define TSEQ   2048
#define BATCH  2
#define NHEAD  16
#define HDIM   64
#define MMEM   64
#define HIDDEN 4096

// ---------------- scratch (device globals; no allocation) ----------------
__device__ float g_H   [BATCH*TSEQ*CDIM];      // 16 MB  LN1 out
__device__ float g_QKV [BATCH*TSEQ*3*CDIM];    // 48 MB
__device__ float g_MEMP[MMEM*CDIM];            // 256 KB projected memory
__device__ float g_ATTN[BATCH*TSEQ*CDIM];      // 16 MB  attention out
__device__ float g_X1  [BATCH*TSEQ*CDIM];      // 16 MB  x after attn residual
__device__ float g_H2  [BATCH*TSEQ*CDIM];      // 16 MB  LN2 out
__device__ float g_HID [BATCH*TSEQ*HIDDEN];    // 64 MB  fc1 out

// ---------------- LayerNorm ----------------
__global__ __launch_bounds__(256)
void ln_kernel(const float* __restrict__ x, const float* __restrict__ g,
               const float* __restrict__ b, float* __restrict__ y)
{
    __shared__ float red[18];
    const int row = blockIdx.x;
    const int tid = threadIdx.x;
    const float4 v = ((const float4*)(x + (size_t)row * CDIM))[tid];
    float s  = v.x + v.y + v.z + v.w;
    float ss = v.x*v.x + v.y*v.y + v.z*v.z + v.w*v.w;
    #pragma unroll
    for (int off = 16; off; off >>= 1) {
        s  += __shfl_xor_sync(0xffffffffu, s,  off);
        ss += __shfl_xor_sync(0xffffffffu, ss, off);
    }
    if ((tid & 31) == 0) { red[tid >> 5] = s; red[8 + (tid >> 5)] = ss; }
    __syncthreads();
    if (tid == 0) {
        float ts = 0.f, tss = 0.f;
        #pragma unroll
        for (int w = 0; w < 8; w++) { ts += red[w]; tss += red[8 + w]; }
        red[16] = ts; red[17] = tss;
    }
    __syncthreads();
    const float mu  = red[16] * (1.f / CDIM);
    const float var = red[17] * (1.f / CDIM) - mu * mu;
    const float inv = rsqrtf(var + 1e-5f);
    const float4 gv = ((const float4*)g)[tid];
    const float4 bv = ((const float4*)b)[tid];
    float4 o;
    o.x = (v.x - mu) * inv * gv.x + bv.x;
    o.y = (v.y - mu) * inv * gv.y + bv.y;
    o.z = (v.z - mu) * inv * gv.z + bv.z;
    o.w = (v.w - mu) * inv * gv.w + bv.w;
    ((float4*)(y + (size_t)row * CDIM))[tid] = o;
}

// ---------------- 128x128x8 SGEMM, fused epilogues ----------------
// EPI 0: C = A@B + bias
// EPI 1: C = A@B + bias + res
// EPI 2: C = gelu_exact(A@B + bias)
template<int EPI>
__global__ __launch_bounds__(256)
void sgemm_k(const float* __restrict__ A, const float* __restrict__ B,
             const float* __restrict__ bias, const float* __restrict__ res,
             float* __restrict__ C, int M, int N, int K)
{
    __shared__ float As[8][128];
    __shared__ float Bs[8][128];
    const int tid = threadIdx.x;
    const int bm  = blockIdx.y * 128;
    const int bn  = blockIdx.x * 128;
    const int tx  = tid & 15, ty = tid >> 4;
    const int arow = tid >> 1, acol = (tid & 1) << 2;
    const int brow = tid >> 5, bcol = (tid & 31) << 2;
    const float* Aptr = A + (size_t)(bm + arow) * K + acol;
    const float* Bptr = B + (size_t)brow * N + bn + bcol;

    float acc[8][8];
    #pragma unroll
    for (int i = 0; i < 8; i++)
        #pragma unroll
        for (int j = 0; j < 8; j++) acc[i][j] = 0.f;

    for (int k0 = 0; k0 < K; k0 += 8) {
        const float4 av = *(const float4*)(Aptr + k0);
        const float4 bv = *(const float4*)(Bptr + (size_t)k0 * N);
        __syncthreads();
        As[acol + 0][arow] = av.x;
        As[acol + 1][arow] = av.y;
        As[acol + 2][arow] = av.z;
        As[acol + 3][arow] = av.w;
        *(float4*)&Bs[brow][bcol] = bv;
        __syncthreads();
        #pragma unroll
        for (int kk = 0; kk < 8; kk++) {
            const float4 a0 = *(const float4*)&As[kk][ty * 4];
            const float4 a1 = *(const float4*)&As[kk][64 + ty * 4];
            const float4 b0 = *(const float4*)&Bs[kk][tx * 4];
            const float4 b1 = *(const float4*)&Bs[kk][64 + tx * 4];
            const float ar[8] = {a0.x,a0.y,a0.z,a0.w,a1.x,a1.y,a1.z,a1.w};
            const float br[8] = {b0.x,b0.y,b0.z,b0.w,b1.x,b1.y,b1.z,b1.w};
            #pragma unroll
            for (int i = 0; i < 8; i++)
                #pragma unroll
                for (int j = 0; j < 8; j++)
                    acc[i][j] = fmaf(ar[i], br[j], acc[i][j]);
        }
    }

    #pragma unroll
    for (int rh = 0; rh < 2; rh++)
    #pragma unroll
    for (int i = 0; i < 4; i++) {
        const int row = bm + rh * 64 + ty * 4 + i;
        #pragma unroll
        for (int ch = 0; ch < 2; ch++) {
            const int col = bn + ch * 64 + tx * 4;
            const float4 bsv = *(const float4*)(bias + col);
            const float bsa[4] = {bsv.x, bsv.y, bsv.z, bsv.w};
            float vv[4];
            #pragma unroll
            for (int j = 0; j < 4; j++) {
                float v = acc[rh * 4 + i][ch * 4 + j] + bsa[j];
                if (EPI == 1) v += res[(size_t)row * N + col + j];
                if (EPI == 2) v = 0.5f * v * (1.0f + erff(v * 0.70710678118654752f));
                vv[j] = v;
            }
            *(float4*)(C + (size_t)row * N + col) = make_float4(vv[0], vv[1], vv[2], vv[3]);
        }
    }
}

// ---------------- memory projection: (64x1024)@(1024x1024)+bias ----------------
__global__ __launch_bounds__(256)
void memproj_kernel(const float* __restrict__ A, const float* __restrict__ B,
                    const float* __restrict__ bias, float* __restrict__ C)
{
    __shared__ float Ast[16][64];
    __shared__ float Bs [16][64];
    const int tid = threadIdx.x;
    const int tx = tid & 15, ty = tid >> 4;
    const int bn = blockIdx.x * 64;
    const int ar = tid >> 2, ak = (tid & 3) << 2;
    const int bk = tid >> 4, bc = (tid & 15) << 2;

    float acc[4][4];
    #pragma unroll
    for (int i = 0; i < 4; i++)
        #pragma unroll
        for (int j = 0; j < 4; j++) acc[i][j] = 0.f;

    for (int k0 = 0; k0 < CDIM; k0 += 16) {
        const float4 av = *(const float4*)(A + (size_t)ar * CDIM + k0 + ak);
        const float4 bv = *(const float4*)(B + (size_t)(k0 + bk) * CDIM + bn + bc);
        __syncthreads();
        Ast[ak + 0][ar] = av.x;
        Ast[ak + 1][ar] = av.y;
        Ast[ak + 2][ar] = av.z;
        Ast[ak + 3][ar] = av.w;
        *(float4*)&Bs[bk][bc] = bv;
        __syncthreads();
        #pragma unroll
        for (int kk = 0; kk < 16; kk++) {
            const float4 a = *(const float4*)&Ast[kk][ty * 4];
            const float4 b = *(const float4*)&Bs[kk][tx * 4];
            const float arr[4] = {a.x, a.y, a.z, a.w};
            const float brr[4] = {b.x, b.y, b.z, b.w};
            #pragma unroll
            for (int i = 0; i < 4; i++)
                #pragma unroll
                for (int j = 0; j < 4; j++)
                    acc[i][j] = fmaf(arr[i], brr[j], acc[i][j]);
        }
    }
    #pragma unroll
    for (int i = 0; i < 4; i++) {
        const int col = bn + tx * 4;
        const float4 bsv = *(const float4*)(bias + col);
        float4 o;
        o.x = acc[i][0] + bsv.x;
        o.y = acc[i][1] + bsv.y;
        o.z = acc[i][2] + bsv.z;
        o.w = acc[i][3] + bsv.w;
        *(float4*)(C + (size_t)(ty * 4 + i) * CDIM + col) = o;
    }
}

// ---------------- flash attention + compressive-memory read ----------------
// grid (T/64, H, B), 256 threads, 48KB static smem.
__global__ __launch_bounds__(256)
void attn_kernel(const float* __restrict__ qkv, const float* __restrict__ memp,
                 float* __restrict__ out)
{
    __shared__ float Qts[64 * 64];   // [d][r]
    __shared__ float KV [64 * 64];   // K: [d][c] ; V: [key][d]
    __shared__ float Ps [64 * 64];   // [r][key]

    const int tid = threadIdx.x;
    const int tx = tid & 15, ty = tid >> 4;
    const int qt = blockIdx.x, h = blockIdx.y, b = blockIdx.z;
    const int row0 = qt * 64;
    const int lr  = tid >> 2;          // 0..63 load row
    const int ld0 = (tid & 3) << 4;    // 0,16,32,48

    // Q transposed + pre-scaled by 1/sqrt(D)
    {
        const float* qp = qkv + ((size_t)(b * TSEQ + row0 + lr)) * (3 * CDIM) + h * 64 + ld0;
        #pragma unroll
        for (int j = 0; j < 16; j += 4) {
            const float4 v = *(const float4*)(qp + j);
            Qts[(ld0 + j + 0) * 64 + lr] = v.x * 0.125f;
            Qts[(ld0 + j + 1) * 64 + lr] = v.y * 0.125f;
            Qts[(ld0 + j + 2) * 64 + lr] = v.z * 0.125f;
            Qts[(ld0 + j + 3) * 64 + lr] = v.w * 0.125f;
        }
    }

    float m_i[4], l_i[4], acc[4][4];
    #pragma unroll
    for (int i = 0; i < 4; i++) {
        m_i[i] = -1e30f; l_i[i] = 0.f;
        #pragma unroll
        for (int j = 0; j < 4; j++) acc[i][j] = 0.f;
    }

    for (int kc = 0; kc < TSEQ; kc += 64) {
        __syncthreads();
        {   // K chunk, transposed
            const float* kp = qkv + ((size_t)(b * TSEQ + kc + lr)) * (3 * CDIM) + CDIM + h * 64 + ld0;
            #pragma unroll
            for (int j = 0; j < 16; j += 4) {
                const float4 v = *(const float4*)(kp + j);
                KV[(ld0 + j + 0) * 64 + lr] = v.x;
                KV[(ld0 + j + 1) * 64 + lr] = v.y;
                KV[(ld0 + j + 2) * 64 + lr] = v.z;
                KV[(ld0 + j + 3) * 64 + lr] = v.w;
            }
        }
        __syncthreads();

        float s[4][4];
        #pragma unroll
        for (int i = 0; i < 4; i++)
            #pragma unroll
            for (int j = 0; j < 4; j++) s[i][j] = 0.f;

        #pragma unroll 8
        for (int d = 0; d < 64; d++) {
            const float4 qa = *(const float4*)&Qts[d * 64 + ty * 4];
            const float4 kb = *(const float4*)&KV [d * 64 + tx * 4];
            const float qr[4] = {qa.x, qa.y, qa.z, qa.w};
            const float kr[4] = {kb.x, kb.y, kb.z, kb.w};
            #pragma unroll
            for (int i = 0; i < 4; i++)
                #pragma unroll
                for (int j = 0; j < 4; j++)
                    s[i][j] = fmaf(qr[i], kr[j], s[i][j]);
        }

        // online softmax update
        #pragma unroll
        for (int i = 0; i < 4; i++) {
            float cm = fmaxf(fmaxf(s[i][0], s[i][1]), fmaxf(s[i][2], s[i][3]));
            #pragma unroll
            for (int off = 1; off < 16; off <<= 1)
                cm = fmaxf(cm, __shfl_xor_sync(0xffffffffu, cm, off, 16));
            const float mn = fmaxf(m_i[i], cm);
            const float f  = __expf(m_i[i] - mn);
            m_i[i] = mn;
            l_i[i] *= f;
            float rs = 0.f;
            #pragma unroll
            for (int j = 0; j < 4; j++) {
                s[i][j] = __expf(s[i][j] - mn);
                rs += s[i][j];
                acc[i][j] *= f;
            }
            #pragma unroll
            for (int off = 1; off < 16; off <<= 1)
                rs += __shfl_xor_sync(0xffffffffu, rs, off, 16);
            l_i[i] += rs;
        }

        __syncthreads();   // all K reads done -> reuse KV for V; prior Ps reads long done
        #pragma unroll
        for (int i = 0; i < 4; i++)
            *(float4*)&Ps[(ty * 4 + i) * 64 + tx * 4] = make_float4(s[i][0], s[i][1], s[i][2], s[i][3]);
        {   // V chunk, natural layout
            const float* vp = qkv + ((size_t)(b * TSEQ + kc + lr)) * (3 * CDIM) + 2 * CDIM + h * 64 + ld0;
            #pragma unroll
            for (int j = 0; j < 16; j += 4)
                *(float4*)&KV[lr * 64 + ld0 + j] = *(const float4*)(vp + j);
        }
        __syncthreads();

        #pragma unroll 4
        for (int k4 = 0; k4 < 64; k4 += 4) {
            float pr[4][4], vr[4][4];
            #pragma unroll
            for (int kk = 0; kk < 4; kk++) {
                const float4 v = *(const float4*)&KV[(k4 + kk) * 64 + tx * 4];
                vr[kk][0] = v.x; vr[kk][1] = v.y; vr[kk][2] = v.z; vr[kk][3] = v.w;
            }
            #pragma unroll
            for (int i = 0; i < 4; i++) {
                const float4 p = *(const float4*)&Ps[(ty * 4 + i) * 64 + k4];
                pr[i][0] = p.x; pr[i][1] = p.y; pr[i][2] = p.z; pr[i][3] = p.w;
            }
            #pragma unroll
            for (int kk = 0; kk < 4; kk++)
                #pragma unroll
                for (int i = 0; i < 4; i++)
                    #pragma unroll
                    for (int j = 0; j < 4; j++)
                        acc[i][j] = fmaf(pr[i][kk], vr[kk][j], acc[i][j]);
        }
    }

    // ---- compressive memory attention (independent softmax over M=64) ----
    __syncthreads();
    {   // mem K transposed
        const float* mp = memp + (size_t)lr * CDIM + h * 64 + ld0;
        #pragma unroll
        for (int j = 0; j < 16; j += 4) {
            const float4 v = *(const float4*)(mp + j);
            KV[(ld0 + j + 0) * 64 + lr] = v.x;
            KV[(ld0 + j + 1) * 64 + lr] = v.y;
            KV[(ld0 + j + 2) * 64 + lr] = v.z;
            KV[(ld0 + j + 3) * 64 + lr] = v.w;
        }
    }
    __syncthreads();

    float s2[4][4];
    #pragma unroll
    for (int i = 0; i < 4; i++)
        #pragma unroll
        for (int j = 0; j < 4; j++) s2[i][j] = 0.f;

    #pragma unroll 8
    for (int d = 0; d < 64; d++) {
        const float4 qa = *(const float4*)&Qts[d * 64 + ty * 4];
        const float4 kb = *(const float4*)&KV [d * 64 + tx * 4];
        const float qr[4] = {qa.x, qa.y, qa.z, qa.w};
        const float kr[4] = {kb.x, kb.y, kb.z, kb.w};
        #pragma unroll
        for (int i = 0; i < 4; i++)
            #pragma unroll
            for (int j = 0; j < 4; j++)
                s2[i][j] = fmaf(qr[i], kr[j], s2[i][j]);
    }

    float l2[4];
    #pragma unroll
    for (int i = 0; i < 4; i++) {
        float cm = fmaxf(fmaxf(s2[i][0], s2[i][1]), fmaxf(s2[i][2], s2[i][3]));
        #pragma unroll
        for (int off = 1; off < 16; off <<= 1)
            cm = fmaxf(cm, __shfl_xor_sync(0xffffffffu, cm, off, 16));
        float rs = 0.f;
        #pragma unroll
        for (int j = 0; j < 4; j++) {
            s2[i][j] = __expf(s2[i][j] - cm);
            rs += s2[i][j];
        }
        #pragma unroll
        for (int off = 1; off < 16; off <<= 1)
            rs += __shfl_xor_sync(0xffffffffu, rs, off, 16);
        l2[i] = rs;
    }

    __syncthreads();
    #pragma unroll
    for (int i = 0; i < 4; i++)
        *(float4*)&Ps[(ty * 4 + i) * 64 + tx * 4] = make_float4(s2[i][0], s2[i][1], s2[i][2], s2[i][3]);
    {   // mem V natural layout
        const float* mp = memp + (size_t)lr * CDIM + h * 64 + ld0;
        #pragma unroll
        for (int j = 0; j < 16; j += 4)
            *(float4*)&KV[lr * 64 + ld0 + j] = *(const float4*)(mp + j);
    }
    __syncthreads();

    float acc2[4][4];
    #pragma unroll
    for (int i = 0; i < 4; i++)
        #pragma unroll
        for (int j = 0; j < 4; j++) acc2[i][j] = 0.f;

    #pragma unroll 4
    for (int k4 = 0; k4 < 64; k4 += 4) {
        float pr[4][4], vr[4][4];
        #pragma unroll
        for (int kk = 0; kk < 4; kk++) {
            const float4 v = *(const float4*)&KV[(k4 + kk) * 64 + tx * 4];
            vr[kk][0] = v.x; vr[kk][1] = v.y; vr[kk][2] = v.z; vr[kk][3] = v.w;
        }
        #pragma unroll
        for (int i = 0; i < 4; i++) {
            const float4 p = *(const float4*)&Ps[(ty * 4 + i) * 64 + k4];
            pr[i][0] = p.x; pr[i][1] = p.y; pr[i][2] = p.z; pr[i][3] = p.w;
        }
        #pragma unroll
        for (int kk = 0; kk < 4; kk++)
            #pragma unroll
            for (int i = 0; i < 4; i++)
                #pragma unroll
                for (int j = 0; j < 4; j++)
                    acc2[i][j] = fmaf(pr[i][kk], vr[kk][j], acc2[i][j]);
    }

    // out = local/l + mem/l2
    #pragma unroll
    for (int i = 0; i < 4; i++) {
        const float inv1 = 1.f / l_i[i];
        const float inv2 = 1.f / l2[i];
        float4 o;
        o.x = acc[i][0] * inv1 + acc2[i][0] * inv2;
        o.y = acc[i][1] * inv1 + acc2[i][1] * inv2;
        o.z = acc[i][2] * inv1 + acc2[i][2] * inv2;
        o.w = acc[i][3] * inv1 + acc2[i][3] * inv2;
        *(float4*)(out + ((size_t)(b * TSEQ + row0 + ty * 4 + i)) * CDIM + h * 64 + tx * 4) = o;
    }
}

// ---------------- launch ----------------
extern "C" void kernel_launch(void* const* d_in, const int* in_sizes, int n_in,
                              void* d_out, int out_size)
{
    const float* x      = (const float*)d_in[0];
    const float* memory = (const float*)d_in[1];
    const float* ln1_g  = (const float*)d_in[2];
    const float* ln1_b  = (const float*)d_in[3];
    const float* w_qkv  = (const float*)d_in[4];
    const float* b_qkv  = (const float*)d_in[5];
    const float* w_out  = (const float*)d_in[6];
    const float* b_out  = (const float*)d_in[7];
    const float* w_mem  = (const float*)d_in[8];
    const float* b_mem  = (const float*)d_in[9];
    const float* ln2_g  = (const float*)d_in[10];
    const float* ln2_b  = (const float*)d_in[11];
    const float* w_fc1  = (const float*)d_in[12];
    const float* b_fc1  = (const float*)d_in[13];
    const float* w_fc2  = (const float*)d_in[14];
    const float* b_fc2  = (const float*)d_in[15];
    float* out = (float*)d_out;

    float *pH, *pQKV, *pMEMP, *pATTN, *pX1, *pH2, *pHID;
    cudaGetSymbolAddress((void**)&pH,    g_H);
    cudaGetSymbolAddress((void**)&pQKV,  g_QKV);
    cudaGetSymbolAddress((void**)&pMEMP, g_MEMP);
    cudaGetSymbolAddress((void**)&pATTN, g_ATTN);
    cudaGetSymbolAddress((void**)&pX1,   g_X1);
    cudaGetSymbolAddress((void**)&pH2,   g_H2);
    cudaGetSymbolAddress((void**)&pHID,  g_HID);

    const int ROWS = BATCH * TSEQ;  // 4096

    ln_kernel<<<ROWS, 256>>>(x, ln1_g, ln1_b, pH);
    memproj_kernel<<<CDIM / 64, 256>>>(memory, w_mem, b_mem, pMEMP);
    sgemm_k<0><<<dim3(3 * CDIM / 128, ROWS / 128), 256>>>(pH, w_qkv, b_qkv, nullptr, pQKV,
                                                          ROWS, 3 * CDIM, CDIM);
    attn_kernel<<<dim3(TSEQ / 64, NHEAD, BATCH), 256>>>(pQKV, pMEMP, pATTN);
    sgemm_k<1><<<dim3(CDIM / 128, ROWS / 128), 256>>>(pATTN, w_out, b_out, x, pX1,
                                                      ROWS, CDIM, CDIM);
    ln_kernel<<<ROWS, 256>>>(pX1, ln2_g, ln2_b, pH2);
    sgemm_k<2><<<dim3(HIDDEN / 128, ROWS / 128), 256>>>(pH2, w_fc1, b_fc1, nullptr, pHID,
                                                        ROWS, HIDDEN, CDIM);
    sgemm_k<1><<<dim3(CDIM / 128, ROWS / 128), 256>>>(pHID, w_fc2, b_fc2, pX1, out,
                                                      ROWS, CDIM, HIDDEN);
}

// round 3
// speedup vs baseline: 1.9202x; 1.9202x over previous
#include <cuda_runtime.h>
#include <math.h>
#include <stdint.h>

#define CDIM   1024
#define TSEQ   2048
#define BATCH  2
#define NHEAD  16
#define HDIM   64
#define MMEM   64
#define HIDDEN 4096

// ---------------- scratch (device globals; no allocation) ----------------
__device__ float g_H    [BATCH*TSEQ*CDIM];
__device__ float g_QKV  [BATCH*TSEQ*3*CDIM];
__device__ float g_MEMP [MMEM*CDIM];
__device__ float g_ATTN [BATCH*TSEQ*CDIM];
__device__ float g_X1   [BATCH*TSEQ*CDIM];
__device__ float g_H2   [BATCH*TSEQ*CDIM];
__device__ float g_HID  [BATCH*TSEQ*HIDDEN];
__device__ float g_WQKVT[3*CDIM*CDIM];
__device__ float g_WOUTT[CDIM*CDIM];
__device__ float g_WFC1T[HIDDEN*CDIM];
__device__ float g_WFC2T[CDIM*HIDDEN];

__device__ __forceinline__ float to_tf32(float x) {
    float y; asm("cvt.rna.tf32.f32 %0, %1;" : "=f"(y) : "f"(x)); return y;
}

// ---------------- LayerNorm (output rounded to tf32) ----------------
__global__ __launch_bounds__(256)
void ln_kernel(const float* __restrict__ x, const float* __restrict__ g,
               const float* __restrict__ b, float* __restrict__ y)
{
    __shared__ float red[18];
    const int row = blockIdx.x;
    const int tid = threadIdx.x;
    const float4 v = ((const float4*)(x + (size_t)row * CDIM))[tid];
    float s  = v.x + v.y + v.z + v.w;
    float ss = v.x*v.x + v.y*v.y + v.z*v.z + v.w*v.w;
    #pragma unroll
    for (int off = 16; off; off >>= 1) {
        s  += __shfl_xor_sync(0xffffffffu, s,  off);
        ss += __shfl_xor_sync(0xffffffffu, ss, off);
    }
    if ((tid & 31) == 0) { red[tid >> 5] = s; red[8 + (tid >> 5)] = ss; }
    __syncthreads();
    if (tid == 0) {
        float ts = 0.f, tss = 0.f;
        #pragma unroll
        for (int w = 0; w < 8; w++) { ts += red[w]; tss += red[8 + w]; }
        red[16] = ts; red[17] = tss;
    }
    __syncthreads();
    const float mu  = red[16] * (1.f / CDIM);
    const float var = red[17] * (1.f / CDIM) - mu * mu;
    const float inv = rsqrtf(var + 1e-5f);
    const float4 gv = ((const float4*)g)[tid];
    const float4 bv = ((const float4*)b)[tid];
    float4 o;
    o.x = to_tf32((v.x - mu) * inv * gv.x + bv.x);
    o.y = to_tf32((v.y - mu) * inv * gv.y + bv.y);
    o.z = to_tf32((v.z - mu) * inv * gv.z + bv.z);
    o.w = to_tf32((v.w - mu) * inv * gv.w + bv.w);
    ((float4*)(y + (size_t)row * CDIM))[tid] = o;
}

// ---------------- weight transpose + tf32 round: D[n][k] = tf32(S[k][n]) ----------------
__global__ __launch_bounds__(256)
void transpose_tf32(const float* __restrict__ S, float* __restrict__ D, int K, int N)
{
    __shared__ float t[32][33];
    const int bx = blockIdx.x * 32;   // n
    const int by = blockIdx.y * 32;   // k
    const int x = threadIdx.x & 31, y = threadIdx.x >> 5;
    #pragma unroll
    for (int i = 0; i < 32; i += 8)
        t[y + i][x] = S[(size_t)(by + y + i) * N + bx + x];
    __syncthreads();
    #pragma unroll
    for (int i = 0; i < 32; i += 8)
        D[(size_t)(bx + y + i) * K + by + x] = to_tf32(t[x][y + i]);
}

// ---------------- tf32 mma.sync GEMM: C[M,N] = A[M,K] @ Bt[N,K]^T ----------------
// A row-major [M][K] (tf32-rounded), Bt row-major [N][K] (tf32-rounded).
// 256 thr = 8 warps (2 x 4), warp tile 64x32, mma m16n8k8, BK=32.
// EPI 0: +bias ; EPI 1: +bias+res ; EPI 2: tf32(gelu(+bias))
#define SKEW 36

__device__ __forceinline__ void mma_tf32(float* c, uint32_t a0, uint32_t a1,
                                         uint32_t a2, uint32_t a3,
                                         uint32_t b0, uint32_t b1)
{
    asm volatile(
        "mma.sync.aligned.m16n8k8.row.col.f32.tf32.tf32.f32 "
        "{%0,%1,%2,%3}, {%4,%5,%6,%7}, {%8,%9}, {%0,%1,%2,%3};"
        : "+f"(c[0]), "+f"(c[1]), "+f"(c[2]), "+f"(c[3])
        : "r"(a0), "r"(a1), "r"(a2), "r"(a3), "r"(b0), "r"(b1));
}

template<int EPI>
__global__ __launch_bounds__(256, 2)
void gemm_mma(const float* __restrict__ A, const float* __restrict__ Bt,
              const float* __restrict__ bias, const float* __restrict__ res,
              float* __restrict__ C, int M, int N, int K)
{
    __shared__ float As[128][SKEW];
    __shared__ float Bs[128][SKEW];

    const int tid = threadIdx.x;
    const int wid = tid >> 5, lane = tid & 31;
    const int wm = (wid & 1) * 64;        // warp row offset
    const int wn = (wid >> 1) * 32;       // warp col offset
    const int bm = blockIdx.y * 128;
    const int bn = blockIdx.x * 128;

    const int lrow = tid >> 3;            // 0..31
    const int lcol = (tid & 7) << 2;      // 0,4,...,28
    const float* Ap = A  + (size_t)(bm + lrow) * K + lcol;
    const float* Bp = Bt + (size_t)(bn + lrow) * K + lcol;

    const int qr = lane >> 2;             // 0..7
    const int qc = lane & 3;              // 0..3

    float acc[4][4][4];
    #pragma unroll
    for (int i = 0; i < 4; i++)
        #pragma unroll
        for (int j = 0; j < 4; j++)
            #pragma unroll
            for (int r = 0; r < 4; r++) acc[i][j][r] = 0.f;

    for (int k0 = 0; k0 < K; k0 += 32) {
        float4 av[4], bv[4];
        #pragma unroll
        for (int p = 0; p < 4; p++) {
            av[p] = *(const float4*)(Ap + (size_t)(p * 32) * K + k0);
            bv[p] = *(const float4*)(Bp + (size_t)(p * 32) * K + k0);
        }
        __syncthreads();
        #pragma unroll
        for (int p = 0; p < 4; p++) {
            *(float4*)&As[lrow + p * 32][lcol] = av[p];
            *(float4*)&Bs[lrow + p * 32][lcol] = bv[p];
        }
        __syncthreads();

        #pragma unroll
        for (int ks = 0; ks < 4; ks++) {
            const int kk = ks * 8;
            uint32_t bf[4][2];
            #pragma unroll
            for (int nt = 0; nt < 4; nt++) {
                const int n0 = wn + nt * 8 + qr;
                bf[nt][0] = __float_as_uint(Bs[n0][kk + qc]);
                bf[nt][1] = __float_as_uint(Bs[n0][kk + qc + 4]);
            }
            #pragma unroll
            for (int mt = 0; mt < 4; mt++) {
                const int m0 = wm + mt * 16 + qr;
                const uint32_t a0 = __float_as_uint(As[m0][kk + qc]);
                const uint32_t a1 = __float_as_uint(As[m0 + 8][kk + qc]);
                const uint32_t a2 = __float_as_uint(As[m0][kk + qc + 4]);
                const uint32_t a3 = __float_as_uint(As[m0 + 8][kk + qc + 4]);
                #pragma unroll
                for (int nt = 0; nt < 4; nt++)
                    mma_tf32(acc[mt][nt], a0, a1, a2, a3, bf[nt][0], bf[nt][1]);
            }
        }
    }

    // ---- epilogue: c0,c1 -> (row, col..col+1) ; c2,c3 -> (row+8, ...) ----
    #pragma unroll
    for (int mt = 0; mt < 4; mt++) {
        #pragma unroll
        for (int half = 0; half < 2; half++) {
            const int row = bm + wm + mt * 16 + qr + half * 8;
            float* Crow = C + (size_t)row * N;
            const float* Rrow = res + (size_t)row * N;
            #pragma unroll
            for (int nt = 0; nt < 4; nt++) {
                const int col = bn + wn + nt * 8 + qc * 2;
                float v0 = acc[mt][nt][half * 2 + 0] + bias[col];
                float v1 = acc[mt][nt][half * 2 + 1] + bias[col + 1];
                if (EPI == 1) {
                    const float2 rv = *(const float2*)(Rrow + col);
                    v0 += rv.x; v1 += rv.y;
                }
                if (EPI == 2) {
                    v0 = to_tf32(0.5f * v0 * (1.0f + erff(v0 * 0.70710678118654752f)));
                    v1 = to_tf32(0.5f * v1 * (1.0f + erff(v1 * 0.70710678118654752f)));
                }
                *(float2*)(Crow + col) = make_float2(v0, v1);
            }
        }
    }
}

// ---------------- memory projection: (64x1024)@(1024x1024)+bias ----------------
__global__ __launch_bounds__(256)
void memproj_kernel(const float* __restrict__ A, const float* __restrict__ B,
                    const float* __restrict__ bias, float* __restrict__ C)
{
    __shared__ float Ast[16][64];
    __shared__ float Bs [16][64];
    const int tid = threadIdx.x;
    const int tx = tid & 15, ty = tid >> 4;
    const int bn = blockIdx.x * 64;
    const int ar = tid >> 2, ak = (tid & 3) << 2;
    const int bk = tid >> 4, bc = (tid & 15) << 2;

    float acc[4][4];
    #pragma unroll
    for (int i = 0; i < 4; i++)
        #pragma unroll
        for (int j = 0; j < 4; j++) acc[i][j] = 0.f;

    for (int k0 = 0; k0 < CDIM; k0 += 16) {
        const float4 av = *(const float4*)(A + (size_t)ar * CDIM + k0 + ak);
        const float4 bv = *(const float4*)(B + (size_t)(k0 + bk) * CDIM + bn + bc);
        __syncthreads();
        Ast[ak + 0][ar] = av.x;
        Ast[ak + 1][ar] = av.y;
        Ast[ak + 2][ar] = av.z;
        Ast[ak + 3][ar] = av.w;
        *(float4*)&Bs[bk][bc] = bv;
        __syncthreads();
        #pragma unroll
        for (int kk = 0; kk < 16; kk++) {
            const float4 a = *(const float4*)&Ast[kk][ty * 4];
            const float4 b = *(const float4*)&Bs[kk][tx * 4];
            const float arr[4] = {a.x, a.y, a.z, a.w};
            const float brr[4] = {b.x, b.y, b.z, b.w};
            #pragma unroll
            for (int i = 0; i < 4; i++)
                #pragma unroll
                for (int j = 0; j < 4; j++)
                    acc[i][j] = fmaf(arr[i], brr[j], acc[i][j]);
        }
    }
    #pragma unroll
    for (int i = 0; i < 4; i++) {
        const int col = bn + tx * 4;
        const float4 bsv = *(const float4*)(bias + col);
        float4 o;
        o.x = acc[i][0] + bsv.x;
        o.y = acc[i][1] + bsv.y;
        o.z = acc[i][2] + bsv.z;
        o.w = acc[i][3] + bsv.w;
        *(float4*)(C + (size_t)(ty * 4 + i) * CDIM + col) = o;
    }
}

// ---------------- flash attention + compressive-memory read (fp32 SIMT) ----------------
__global__ __launch_bounds__(256)
void attn_kernel(const float* __restrict__ qkv, const float* __restrict__ memp,
                 float* __restrict__ out)
{
    __shared__ float Qts[64 * 64];
    __shared__ float KV [64 * 64];
    __shared__ float Ps [64 * 64];

    const int tid = threadIdx.x;
    const int tx = tid & 15, ty = tid >> 4;
    const int qt = blockIdx.x, h = blockIdx.y, b = blockIdx.z;
    const int row0 = qt * 64;
    const int lr  = tid >> 2;
    const int ld0 = (tid & 3) << 4;

    {
        const float* qp = qkv + ((size_t)(b * TSEQ + row0 + lr)) * (3 * CDIM) + h * 64 + ld0;
        #pragma unroll
        for (int j = 0; j < 16; j += 4) {
            const float4 v = *(const float4*)(qp + j);
            Qts[(ld0 + j + 0) * 64 + lr] = v.x * 0.125f;
            Qts[(ld0 + j + 1) * 64 + lr] = v.y * 0.125f;
            Qts[(ld0 + j + 2) * 64 + lr] = v.z * 0.125f;
            Qts[(ld0 + j + 3) * 64 + lr] = v.w * 0.125f;
        }
    }

    float m_i[4], l_i[4], acc[4][4];
    #pragma unroll
    for (int i = 0; i < 4; i++) {
        m_i[i] = -1e30f; l_i[i] = 0.f;
        #pragma unroll
        for (int j = 0; j < 4; j++) acc[i][j] = 0.f;
    }

    for (int kc = 0; kc < TSEQ; kc += 64) {
        __syncthreads();
        {
            const float* kp = qkv + ((size_t)(b * TSEQ + kc + lr)) * (3 * CDIM) + CDIM + h * 64 + ld0;
            #pragma unroll
            for (int j = 0; j < 16; j += 4) {
                const float4 v = *(const float4*)(kp + j);
                KV[(ld0 + j + 0) * 64 + lr] = v.x;
                KV[(ld0 + j + 1) * 64 + lr] = v.y;
                KV[(ld0 + j + 2) * 64 + lr] = v.z;
                KV[(ld0 + j + 3) * 64 + lr] = v.w;
            }
        }
        __syncthreads();

        float s[4][4];
        #pragma unroll
        for (int i = 0; i < 4; i++)
            #pragma unroll
            for (int j = 0; j < 4; j++) s[i][j] = 0.f;

        #pragma unroll 8
        for (int d = 0; d < 64; d++) {
            const float4 qa = *(const float4*)&Qts[d * 64 + ty * 4];
            const float4 kb = *(const float4*)&KV [d * 64 + tx * 4];
            const float qr4[4] = {qa.x, qa.y, qa.z, qa.w};
            const float kr[4] = {kb.x, kb.y, kb.z, kb.w};
            #pragma unroll
            for (int i = 0; i < 4; i++)
                #pragma unroll
                for (int j = 0; j < 4; j++)
                    s[i][j] = fmaf(qr4[i], kr[j], s[i][j]);
        }

        #pragma unroll
        for (int i = 0; i < 4; i++) {
            float cm = fmaxf(fmaxf(s[i][0], s[i][1]), fmaxf(s[i][2], s[i][3]));
            #pragma unroll
            for (int off = 1; off < 16; off <<= 1)
                cm = fmaxf(cm, __shfl_xor_sync(0xffffffffu, cm, off, 16));
            const float mn = fmaxf(m_i[i], cm);
            const float f  = __expf(m_i[i] - mn);
            m_i[i] = mn;
            l_i[i] *= f;
            float rs = 0.f;
            #pragma unroll
            for (int j = 0; j < 4; j++) {
                s[i][j] = __expf(s[i][j] - mn);
                rs += s[i][j];
                acc[i][j] *= f;
            }
            #pragma unroll
            for (int off = 1; off < 16; off <<= 1)
                rs += __shfl_xor_sync(0xffffffffu, rs, off, 16);
            l_i[i] += rs;
        }

        __syncthreads();
        #pragma unroll
        for (int i = 0; i < 4; i++)
            *(float4*)&Ps[(ty * 4 + i) * 64 + tx * 4] = make_float4(s[i][0], s[i][1], s[i][2], s[i][3]);
        {
            const float* vp = qkv + ((size_t)(b * TSEQ + kc + lr)) * (3 * CDIM) + 2 * CDIM + h * 64 + ld0;
            #pragma unroll
            for (int j = 0; j < 16; j += 4)
                *(float4*)&KV[lr * 64 + ld0 + j] = *(const float4*)(vp + j);
        }
        __syncthreads();

        #pragma unroll 4
        for (int k4 = 0; k4 < 64; k4 += 4) {
            float pr[4][4], vr[4][4];
            #pragma unroll
            for (int kk = 0; kk < 4; kk++) {
                const float4 v = *(const float4*)&KV[(k4 + kk) * 64 + tx * 4];
                vr[kk][0] = v.x; vr[kk][1] = v.y; vr[kk][2] = v.z; vr[kk][3] = v.w;
            }
            #pragma unroll
            for (int i = 0; i < 4; i++) {
                const float4 p = *(const float4*)&Ps[(ty * 4 + i) * 64 + k4];
                pr[i][0] = p.x; pr[i][1] = p.y; pr[i][2] = p.z; pr[i][3] = p.w;
            }
            #pragma unroll
            for (int kk = 0; kk < 4; kk++)
                #pragma unroll
                for (int i = 0; i < 4; i++)
                    #pragma unroll
                    for (int j = 0; j < 4; j++)
                        acc[i][j] = fmaf(pr[i][kk], vr[kk][j], acc[i][j]);
        }
    }

    // ---- compressive memory attention ----
    __syncthreads();
    {
        const float* mp = memp + (size_t)lr * CDIM + h * 64 + ld0;
        #pragma unroll
        for (int j = 0; j < 16; j += 4) {
            const float4 v = *(const float4*)(mp + j);
            KV[(ld0 + j + 0) * 64 + lr] = v.x;
            KV[(ld0 + j + 1) * 64 + lr] = v.y;
            KV[(ld0 + j + 2) * 64 + lr] = v.z;
            KV[(ld0 + j + 3) * 64 + lr] = v.w;
        }
    }
    __syncthreads();

    float s2[4][4];
    #pragma unroll
    for (int i = 0; i < 4; i++)
        #pragma unroll
        for (int j = 0; j < 4; j++) s2[i][j] = 0.f;

    #pragma unroll 8
    for (int d = 0; d < 64; d++) {
        const float4 qa = *(const float4*)&Qts[d * 64 + ty * 4];
        const float4 kb = *(const float4*)&KV [d * 64 + tx * 4];
        const float qr4[4] = {qa.x, qa.y, qa.z, qa.w};
        const float kr[4] = {kb.x, kb.y, kb.z, kb.w};
        #pragma unroll
        for (int i = 0; i < 4; i++)
            #pragma unroll
            for (int j = 0; j < 4; j++)
                s2[i][j] = fmaf(qr4[i], kr[j], s2[i][j]);
    }

    float l2[4];
    #pragma unroll
    for (int i = 0; i < 4; i++) {
        float cm = fmaxf(fmaxf(s2[i][0], s2[i][1]), fmaxf(s2[i][2], s2[i][3]));
        #pragma unroll
        for (int off = 1; off < 16; off <<= 1)
            cm = fmaxf(cm, __shfl_xor_sync(0xffffffffu, cm, off, 16));
        float rs = 0.f;
        #pragma unroll
        for (int j = 0; j < 4; j++) {
            s2[i][j] = __expf(s2[i][j] - cm);
            rs += s2[i][j];
        }
        #pragma unroll
        for (int off = 1; off < 16; off <<= 1)
            rs += __shfl_xor_sync(0xffffffffu, rs, off, 16);
        l2[i] = rs;
    }

    __syncthreads();
    #pragma unroll
    for (int i = 0; i < 4; i++)
        *(float4*)&Ps[(ty * 4 + i) * 64 + tx * 4] = make_float4(s2[i][0], s2[i][1], s2[i][2], s2[i][3]);
    {
        const float* mp = memp + (size_t)lr * CDIM + h * 64 + ld0;
        #pragma unroll
        for (int j = 0; j < 16; j += 4)
            *(float4*)&KV[lr * 64 + ld0 + j] = *(const float4*)(mp + j);
    }
    __syncthreads();

    float acc2[4][4];
    #pragma unroll
    for (int i = 0; i < 4; i++)
        #pragma unroll
        for (int j = 0; j < 4; j++) acc2[i][j] = 0.f;

    #pragma unroll 4
    for (int k4 = 0; k4 < 64; k4 += 4) {
        float pr[4][4], vr[4][4];
        #pragma unroll
        for (int kk = 0; kk < 4; kk++) {
            const float4 v = *(const float4*)&KV[(k4 + kk) * 64 + tx * 4];
            vr[kk][0] = v.x; vr[kk][1] = v.y; vr[kk][2] = v.z; vr[kk][3] = v.w;
        }
        #pragma unroll
        for (int i = 0; i < 4; i++) {
            const float4 p = *(const float4*)&Ps[(ty * 4 + i) * 64 + k4];
            pr[i][0] = p.x; pr[i][1] = p.y; pr[i][2] = p.z; pr[i][3] = p.w;
        }
        #pragma unroll
        for (int kk = 0; kk < 4; kk++)
            #pragma unroll
            for (int i = 0; i < 4; i++)
                #pragma unroll
                for (int j = 0; j < 4; j++)
                    acc2[i][j] = fmaf(pr[i][kk], vr[kk][j], acc2[i][j]);
    }

    // out = local/l + mem/l2, rounded to tf32 (feeds tf32 out-proj GEMM)
    #pragma unroll
    for (int i = 0; i < 4; i++) {
        const float inv1 = 1.f / l_i[i];
        const float inv2 = 1.f / l2[i];
        float4 o;
        o.x = to_tf32(acc[i][0] * inv1 + acc2[i][0] * inv2);
        o.y = to_tf32(acc[i][1] * inv1 + acc2[i][1] * inv2);
        o.z = to_tf32(acc[i][2] * inv1 + acc2[i][2] * inv2);
        o.w = to_tf32(acc[i][3] * inv1 + acc2[i][3] * inv2);
        *(float4*)(out + ((size_t)(b * TSEQ + row0 + ty * 4 + i)) * CDIM + h * 64 + tx * 4) = o;
    }
}

// ---------------- launch ----------------
extern "C" void kernel_launch(void* const* d_in, const int* in_sizes, int n_in,
                              void* d_out, int out_size)
{
    const float* x      = (const float*)d_in[0];
    const float* memory = (const float*)d_in[1];
    const float* ln1_g  = (const float*)d_in[2];
    const float* ln1_b  = (const float*)d_in[3];
    const float* w_qkv  = (const float*)d_in[4];
    const float* b_qkv  = (const float*)d_in[5];
    const float* w_out  = (const float*)d_in[6];
    const float* b_out  = (const float*)d_in[7];
    const float* w_mem  = (const float*)d_in[8];
    const float* b_mem  = (const float*)d_in[9];
    const float* ln2_g  = (const float*)d_in[10];
    const float* ln2_b  = (const float*)d_in[11];
    const float* w_fc1  = (const float*)d_in[12];
    const float* b_fc1  = (const float*)d_in[13];
    const float* w_fc2  = (const float*)d_in[14];
    const float* b_fc2  = (const float*)d_in[15];
    float* out = (float*)d_out;

    float *pH, *pQKV, *pMEMP, *pATTN, *pX1, *pH2, *pHID;
    float *pWQKVT, *pWOUTT, *pWFC1T, *pWFC2T;
    cudaGetSymbolAddress((void**)&pH,     g_H);
    cudaGetSymbolAddress((void**)&pQKV,   g_QKV);
    cudaGetSymbolAddress((void**)&pMEMP,  g_MEMP);
    cudaGetSymbolAddress((void**)&pATTN,  g_ATTN);
    cudaGetSymbolAddress((void**)&pX1,    g_X1);
    cudaGetSymbolAddress((void**)&pH2,    g_H2);
    cudaGetSymbolAddress((void**)&pHID,   g_HID);
    cudaGetSymbolAddress((void**)&pWQKVT, g_WQKVT);
    cudaGetSymbolAddress((void**)&pWOUTT, g_WOUTT);
    cudaGetSymbolAddress((void**)&pWFC1T, g_WFC1T);
    cudaGetSymbolAddress((void**)&pWFC2T, g_WFC2T);

    const int ROWS = BATCH * TSEQ;  // 4096

    // weight transposes (+ tf32 rounding)
    transpose_tf32<<<dim3(3 * CDIM / 32, CDIM / 32), 256>>>(w_qkv, pWQKVT, CDIM, 3 * CDIM);
    transpose_tf32<<<dim3(CDIM / 32, CDIM / 32), 256>>>(w_out, pWOUTT, CDIM, CDIM);
    transpose_tf32<<<dim3(HIDDEN / 32, CDIM / 32), 256>>>(w_fc1, pWFC1T, CDIM, HIDDEN);
    transpose_tf32<<<dim3(CDIM / 32, HIDDEN / 32), 256>>>(w_fc2, pWFC2T, HIDDEN, CDIM);

    ln_kernel<<<ROWS, 256>>>(x, ln1_g, ln1_b, pH);
    memproj_kernel<<<CDIM / 64, 256>>>(memory, w_mem, b_mem, pMEMP);

    gemm_mma<0><<<dim3(3 * CDIM / 128, ROWS / 128), 256>>>(
        pH, pWQKVT, b_qkv, nullptr, pQKV, ROWS, 3 * CDIM, CDIM);

    attn_kernel<<<dim3(TSEQ / 64, NHEAD, BATCH), 256>>>(pQKV, pMEMP, pATTN);

    gemm_mma<1><<<dim3(CDIM / 128, ROWS / 128), 256>>>(
        pATTN, pWOUTT, b_out, x, pX1, ROWS, CDIM, CDIM);

    ln_kernel<<<ROWS, 256>>>(pX1, ln2_g, ln2_b, pH2);

    gemm_mma<2><<<dim3(HIDDEN / 128, ROWS / 128), 256>>>(
        pH2, pWFC1T, b_fc1, nullptr, pHID, ROWS, HIDDEN, CDIM);

    gemm_mma<1><<<dim3(CDIM / 128, ROWS / 128), 256>>>(
        pHID, pWFC2T, b_fc2, pX1, out, ROWS, CDIM, HIDDEN);
}

// round 4
// speedup vs baseline: 2.9481x; 1.5353x over previous
#include <cuda_runtime.h>
#include <math.h>
#include <stdint.h>

#define CDIM   1024
#define TSEQ   2048
#define BATCH  2
#define NHEAD  16
#define HDIM   64
#define MMEM   64
#define HIDDEN 4096

// ---------------- scratch (device globals; no allocation) ----------------
__device__ float g_H    [BATCH*TSEQ*CDIM];
__device__ float g_QKV  [BATCH*TSEQ*3*CDIM];
__device__ float g_MEMP [MMEM*CDIM];
__device__ float g_ATTN [BATCH*TSEQ*CDIM];
__device__ float g_X1   [BATCH*TSEQ*CDIM];
__device__ float g_H2   [BATCH*TSEQ*CDIM];
__device__ float g_HID  [BATCH*TSEQ*HIDDEN];
__device__ float g_WQKVT[3*CDIM*CDIM];
__device__ float g_WOUTT[CDIM*CDIM];
__device__ float g_WFC1T[HIDDEN*CDIM];
__device__ float g_WFC2T[CDIM*HIDDEN];

__device__ __forceinline__ float to_tf32(float x) {
    float y; asm("cvt.rna.tf32.f32 %0, %1;" : "=f"(y) : "f"(x)); return y;
}

__device__ __forceinline__ void mma_tf32(float* c, uint32_t a0, uint32_t a1,
                                         uint32_t a2, uint32_t a3,
                                         uint32_t b0, uint32_t b1)
{
    asm volatile(
        "mma.sync.aligned.m16n8k8.row.col.f32.tf32.tf32.f32 "
        "{%0,%1,%2,%3}, {%4,%5,%6,%7}, {%8,%9}, {%0,%1,%2,%3};"
        : "+f"(c[0]), "+f"(c[1]), "+f"(c[2]), "+f"(c[3])
        : "r"(a0), "r"(a1), "r"(a2), "r"(a3), "r"(b0), "r"(b1));
}

// ---------------- LayerNorm (output rounded to tf32) ----------------
__global__ __launch_bounds__(256)
void ln_kernel(const float* __restrict__ x, const float* __restrict__ g,
               const float* __restrict__ b, float* __restrict__ y)
{
    __shared__ float red[18];
    const int row = blockIdx.x;
    const int tid = threadIdx.x;
    const float4 v = ((const float4*)(x + (size_t)row * CDIM))[tid];
    float s  = v.x + v.y + v.z + v.w;
    float ss = v.x*v.x + v.y*v.y + v.z*v.z + v.w*v.w;
    #pragma unroll
    for (int off = 16; off; off >>= 1) {
        s  += __shfl_xor_sync(0xffffffffu, s,  off);
        ss += __shfl_xor_sync(0xffffffffu, ss, off);
    }
    if ((tid & 31) == 0) { red[tid >> 5] = s; red[8 + (tid >> 5)] = ss; }
    __syncthreads();
    if (tid == 0) {
        float ts = 0.f, tss = 0.f;
        #pragma unroll
        for (int w = 0; w < 8; w++) { ts += red[w]; tss += red[8 + w]; }
        red[16] = ts; red[17] = tss;
    }
    __syncthreads();
    const float mu  = red[16] * (1.f / CDIM);
    const float var = red[17] * (1.f / CDIM) - mu * mu;
    const float inv = rsqrtf(var + 1e-5f);
    const float4 gv = ((const float4*)g)[tid];
    const float4 bv = ((const float4*)b)[tid];
    float4 o;
    o.x = to_tf32((v.x - mu) * inv * gv.x + bv.x);
    o.y = to_tf32((v.y - mu) * inv * gv.y + bv.y);
    o.z = to_tf32((v.z - mu) * inv * gv.z + bv.z);
    o.w = to_tf32((v.w - mu) * inv * gv.w + bv.w);
    ((float4*)(y + (size_t)row * CDIM))[tid] = o;
}

// ---------------- weight transpose + tf32 round ----------------
__global__ __launch_bounds__(256)
void transpose_tf32(const float* __restrict__ S, float* __restrict__ D, int K, int N)
{
    __shared__ float t[32][33];
    const int bx = blockIdx.x * 32;
    const int by = blockIdx.y * 32;
    const int x = threadIdx.x & 31, y = threadIdx.x >> 5;
    #pragma unroll
    for (int i = 0; i < 32; i += 8)
        t[y + i][x] = S[(size_t)(by + y + i) * N + bx + x];
    __syncthreads();
    #pragma unroll
    for (int i = 0; i < 32; i += 8)
        D[(size_t)(bx + y + i) * K + by + x] = to_tf32(t[x][y + i]);
}

// ---------------- tf32 mma.sync GEMM (proven in R3) ----------------
#define SKEW 36

template<int EPI>
__global__ __launch_bounds__(256, 2)
void gemm_mma(const float* __restrict__ A, const float* __restrict__ Bt,
              const float* __restrict__ bias, const float* __restrict__ res,
              float* __restrict__ C, int M, int N, int K)
{
    __shared__ float As[128][SKEW];
    __shared__ float Bs[128][SKEW];

    const int tid = threadIdx.x;
    const int wid = tid >> 5, lane = tid & 31;
    const int wm = (wid & 1) * 64;
    const int wn = (wid >> 1) * 32;
    const int bm = blockIdx.y * 128;
    const int bn = blockIdx.x * 128;

    const int lrow = tid >> 3;
    const int lcol = (tid & 7) << 2;
    const float* Ap = A  + (size_t)(bm + lrow) * K + lcol;
    const float* Bp = Bt + (size_t)(bn + lrow) * K + lcol;

    const int qr = lane >> 2;
    const int qc = lane & 3;

    float acc[4][4][4];
    #pragma unroll
    for (int i = 0; i < 4; i++)
        #pragma unroll
        for (int j = 0; j < 4; j++)
            #pragma unroll
            for (int r = 0; r < 4; r++) acc[i][j][r] = 0.f;

    for (int k0 = 0; k0 < K; k0 += 32) {
        float4 av[4], bv[4];
        #pragma unroll
        for (int p = 0; p < 4; p++) {
            av[p] = *(const float4*)(Ap + (size_t)(p * 32) * K + k0);
            bv[p] = *(const float4*)(Bp + (size_t)(p * 32) * K + k0);
        }
        __syncthreads();
        #pragma unroll
        for (int p = 0; p < 4; p++) {
            *(float4*)&As[lrow + p * 32][lcol] = av[p];
            *(float4*)&Bs[lrow + p * 32][lcol] = bv[p];
        }
        __syncthreads();

        #pragma unroll
        for (int ks = 0; ks < 4; ks++) {
            const int kk = ks * 8;
            uint32_t bf[4][2];
            #pragma unroll
            for (int nt = 0; nt < 4; nt++) {
                const int n0 = wn + nt * 8 + qr;
                bf[nt][0] = __float_as_uint(Bs[n0][kk + qc]);
                bf[nt][1] = __float_as_uint(Bs[n0][kk + qc + 4]);
            }
            #pragma unroll
            for (int mt = 0; mt < 4; mt++) {
                const int m0 = wm + mt * 16 + qr;
                const uint32_t a0 = __float_as_uint(As[m0][kk + qc]);
                const uint32_t a1 = __float_as_uint(As[m0 + 8][kk + qc]);
                const uint32_t a2 = __float_as_uint(As[m0][kk + qc + 4]);
                const uint32_t a3 = __float_as_uint(As[m0 + 8][kk + qc + 4]);
                #pragma unroll
                for (int nt = 0; nt < 4; nt++)
                    mma_tf32(acc[mt][nt], a0, a1, a2, a3, bf[nt][0], bf[nt][1]);
            }
        }
    }

    #pragma unroll
    for (int mt = 0; mt < 4; mt++) {
        #pragma unroll
        for (int half = 0; half < 2; half++) {
            const int row = bm + wm + mt * 16 + qr + half * 8;
            float* Crow = C + (size_t)row * N;
            const float* Rrow = res + (size_t)row * N;
            #pragma unroll
            for (int nt = 0; nt < 4; nt++) {
                const int col = bn + wn + nt * 8 + qc * 2;
                float v0 = acc[mt][nt][half * 2 + 0] + bias[col];
                float v1 = acc[mt][nt][half * 2 + 1] + bias[col + 1];
                if (EPI == 1) {
                    const float2 rv = *(const float2*)(Rrow + col);
                    v0 += rv.x; v1 += rv.y;
                }
                if (EPI == 2) {
                    v0 = to_tf32(0.5f * v0 * (1.0f + erff(v0 * 0.70710678118654752f)));
                    v1 = to_tf32(0.5f * v1 * (1.0f + erff(v1 * 0.70710678118654752f)));
                }
                *(float2*)(Crow + col) = make_float2(v0, v1);
            }
        }
    }
}

// ---------------- memory projection: (64x1024)@(1024x1024)+bias ----------------
__global__ __launch_bounds__(256)
void memproj_kernel(const float* __restrict__ A, const float* __restrict__ B,
                    const float* __restrict__ bias, float* __restrict__ C)
{
    __shared__ float Ast[16][64];
    __shared__ float Bs [16][64];
    const int tid = threadIdx.x;
    const int tx = tid & 15, ty = tid >> 4;
    const int bn = blockIdx.x * 64;
    const int ar = tid >> 2, ak = (tid & 3) << 2;
    const int bk = tid >> 4, bc = (tid & 15) << 2;

    float acc[4][4];
    #pragma unroll
    for (int i = 0; i < 4; i++)
        #pragma unroll
        for (int j = 0; j < 4; j++) acc[i][j] = 0.f;

    for (int k0 = 0; k0 < CDIM; k0 += 16) {
        const float4 av = *(const float4*)(A + (size_t)ar * CDIM + k0 + ak);
        const float4 bv = *(const float4*)(B + (size_t)(k0 + bk) * CDIM + bn + bc);
        __syncthreads();
        Ast[ak + 0][ar] = av.x;
        Ast[ak + 1][ar] = av.y;
        Ast[ak + 2][ar] = av.z;
        Ast[ak + 3][ar] = av.w;
        *(float4*)&Bs[bk][bc] = bv;
        __syncthreads();
        #pragma unroll
        for (int kk = 0; kk < 16; kk++) {
            const float4 a = *(const float4*)&Ast[kk][ty * 4];
            const float4 b = *(const float4*)&Bs[kk][tx * 4];
            const float arr[4] = {a.x, a.y, a.z, a.w};
            const float brr[4] = {b.x, b.y, b.z, b.w};
            #pragma unroll
            for (int i = 0; i < 4; i++)
                #pragma unroll
                for (int j = 0; j < 4; j++)
                    acc[i][j] = fmaf(arr[i], brr[j], acc[i][j]);
        }
    }
    #pragma unroll
    for (int i = 0; i < 4; i++) {
        const int col = bn + tx * 4;
        const float4 bsv = *(const float4*)(bias + col);
        float4 o;
        o.x = acc[i][0] + bsv.x;
        o.y = acc[i][1] + bsv.y;
        o.z = acc[i][2] + bsv.z;
        o.w = acc[i][3] + bsv.w;
        *(float4*)(C + (size_t)(ty * 4 + i) * CDIM + col) = o;
    }
}

// ---------------- tf32 mma attention ----------------
#define QT   128
#define KC   64
#define DPAD 68

// smem float layout: Qs[128][68] | Ks[64][68] | Vt[64][68] | Ps[128][68]
#define ATTN_SMEM ((128*DPAD + 64*DPAD + 64*DPAD + 128*DPAD) * 4)

__device__ __forceinline__ void load_kv_chunk(const float* __restrict__ kbase,
                                              const float* __restrict__ vbase,
                                              size_t rstride, float* Ks, float* Vt, int tid)
{
    const int r  = tid >> 2;
    const int c0 = (tid & 3) * 16;
    const float* kp = kbase + (size_t)r * rstride + c0;
    #pragma unroll
    for (int j = 0; j < 16; j += 4) {
        const float4 v = *(const float4*)(kp + j);
        Ks[r * DPAD + c0 + j + 0] = to_tf32(v.x);
        Ks[r * DPAD + c0 + j + 1] = to_tf32(v.y);
        Ks[r * DPAD + c0 + j + 2] = to_tf32(v.z);
        Ks[r * DPAD + c0 + j + 3] = to_tf32(v.w);
    }
    const float* vp = vbase + (size_t)r * rstride + c0;
    #pragma unroll
    for (int j = 0; j < 16; j += 4) {
        const float4 v = *(const float4*)(vp + j);
        Vt[(c0 + j + 0) * DPAD + r] = to_tf32(v.x);
        Vt[(c0 + j + 1) * DPAD + r] = to_tf32(v.y);
        Vt[(c0 + j + 2) * DPAD + r] = to_tf32(v.z);
        Vt[(c0 + j + 3) * DPAD + r] = to_tf32(v.w);
    }
}

// C[16x64] += A[16x64(k)] @ B: A rows m0.., B fragment from Bsm ([n][DPAD] layout)
__device__ __forceinline__ void tile_mma_16x64(const float* __restrict__ Asm, int m0,
                                               const float* __restrict__ Bsm,
                                               int qr, int qc, float acc[8][4])
{
    #pragma unroll
    for (int ks = 0; ks < 8; ks++) {
        const int kk = ks * 8;
        const uint32_t a0 = __float_as_uint(Asm[(m0 + qr)     * DPAD + kk + qc]);
        const uint32_t a1 = __float_as_uint(Asm[(m0 + qr + 8) * DPAD + kk + qc]);
        const uint32_t a2 = __float_as_uint(Asm[(m0 + qr)     * DPAD + kk + qc + 4]);
        const uint32_t a3 = __float_as_uint(Asm[(m0 + qr + 8) * DPAD + kk + qc + 4]);
        #pragma unroll
        for (int nt = 0; nt < 8; nt++) {
            const uint32_t b0 = __float_as_uint(Bsm[(nt * 8 + qr) * DPAD + kk + qc]);
            const uint32_t b1 = __float_as_uint(Bsm[(nt * 8 + qr) * DPAD + kk + qc + 4]);
            mma_tf32(acc[nt], a0, a1, a2, a3, b0, b1);
        }
    }
}

__global__ __launch_bounds__(256)
void attn_mma(const float* __restrict__ qkv, const float* __restrict__ memp,
              float* __restrict__ out)
{
    extern __shared__ float sm[];
    float* Qs = sm;
    float* Ks = sm + 128 * DPAD;
    float* Vt = Ks + 64 * DPAD;
    float* Ps = Vt + 64 * DPAD;

    const int tid  = threadIdx.x;
    const int wid  = tid >> 5, lane = tid & 31;
    const int qr   = lane >> 2, qc = lane & 3;
    const int m0   = wid * 16;
    const int h    = blockIdx.y, b = blockIdx.z;
    const int row0 = blockIdx.x * QT;

    // load Q (pre-scaled, tf32-rounded)
    {
        const int r  = tid >> 1;
        const int c0 = (tid & 1) * 32;
        const float* qp = qkv + ((size_t)(b * TSEQ + row0 + r)) * (3 * CDIM) + h * 64 + c0;
        #pragma unroll
        for (int j = 0; j < 32; j += 4) {
            const float4 v = *(const float4*)(qp + j);
            Qs[r * DPAD + c0 + j + 0] = to_tf32(v.x * 0.125f);
            Qs[r * DPAD + c0 + j + 1] = to_tf32(v.y * 0.125f);
            Qs[r * DPAD + c0 + j + 2] = to_tf32(v.z * 0.125f);
            Qs[r * DPAD + c0 + j + 3] = to_tf32(v.w * 0.125f);
        }
    }

    float mM[2] = {-1e30f, -1e30f};
    float lL[2] = {0.f, 0.f};
    float oacc[8][4];
    #pragma unroll
    for (int nt = 0; nt < 8; nt++)
        #pragma unroll
        for (int r = 0; r < 4; r++) oacc[nt][r] = 0.f;

    for (int kc = 0; kc < TSEQ; kc += KC) {
        __syncthreads();   // previous PV reads of Ks/Vt finished
        load_kv_chunk(qkv + ((size_t)(b * TSEQ + kc)) * (3 * CDIM) + CDIM + h * 64,
                      qkv + ((size_t)(b * TSEQ + kc)) * (3 * CDIM) + 2 * CDIM + h * 64,
                      3 * CDIM, Ks, Vt, tid);
        __syncthreads();

        float sacc[8][4];
        #pragma unroll
        for (int nt = 0; nt < 8; nt++)
            #pragma unroll
            for (int r = 0; r < 4; r++) sacc[nt][r] = 0.f;
        tile_mma_16x64(Qs, m0, Ks, qr, qc, sacc);

        // online softmax (rows qr -> [0], qr+8 -> [1]); quad-local
        float mx0 = -1e30f, mx1 = -1e30f;
        #pragma unroll
        for (int nt = 0; nt < 8; nt++) {
            mx0 = fmaxf(mx0, fmaxf(sacc[nt][0], sacc[nt][1]));
            mx1 = fmaxf(mx1, fmaxf(sacc[nt][2], sacc[nt][3]));
        }
        #pragma unroll
        for (int off = 1; off < 4; off <<= 1) {
            mx0 = fmaxf(mx0, __shfl_xor_sync(0xffffffffu, mx0, off));
            mx1 = fmaxf(mx1, __shfl_xor_sync(0xffffffffu, mx1, off));
        }
        const float mn0 = fmaxf(mM[0], mx0);
        const float mn1 = fmaxf(mM[1], mx1);
        const float f0 = __expf(mM[0] - mn0);
        const float f1 = __expf(mM[1] - mn1);
        mM[0] = mn0; mM[1] = mn1;

        float rs0 = 0.f, rs1 = 0.f;
        #pragma unroll
        for (int nt = 0; nt < 8; nt++) {
            const float p0 = to_tf32(__expf(sacc[nt][0] - mn0));
            const float p1 = to_tf32(__expf(sacc[nt][1] - mn0));
            const float p2 = to_tf32(__expf(sacc[nt][2] - mn1));
            const float p3 = to_tf32(__expf(sacc[nt][3] - mn1));
            sacc[nt][0] = p0; sacc[nt][1] = p1; sacc[nt][2] = p2; sacc[nt][3] = p3;
            rs0 += p0 + p1; rs1 += p2 + p3;
        }
        #pragma unroll
        for (int off = 1; off < 4; off <<= 1) {
            rs0 += __shfl_xor_sync(0xffffffffu, rs0, off);
            rs1 += __shfl_xor_sync(0xffffffffu, rs1, off);
        }
        lL[0] = lL[0] * f0 + rs0;
        lL[1] = lL[1] * f1 + rs1;
        #pragma unroll
        for (int nt = 0; nt < 8; nt++) {
            oacc[nt][0] *= f0; oacc[nt][1] *= f0;
            oacc[nt][2] *= f1; oacc[nt][3] *= f1;
        }

        // P -> smem (warp-local rows)
        #pragma unroll
        for (int nt = 0; nt < 8; nt++) {
            *(float2*)&Ps[(m0 + qr)     * DPAD + nt * 8 + 2 * qc] = make_float2(sacc[nt][0], sacc[nt][1]);
            *(float2*)&Ps[(m0 + qr + 8) * DPAD + nt * 8 + 2 * qc] = make_float2(sacc[nt][2], sacc[nt][3]);
        }
        __syncwarp();

        tile_mma_16x64(Ps, m0, Vt, qr, qc, oacc);
    }

    // ---- compressive memory attention (one chunk, independent softmax) ----
    __syncthreads();
    load_kv_chunk(memp + h * 64, memp + h * 64, CDIM, Ks, Vt, tid);
    __syncthreads();

    float sacc[8][4];
    #pragma unroll
    for (int nt = 0; nt < 8; nt++)
        #pragma unroll
        for (int r = 0; r < 4; r++) sacc[nt][r] = 0.f;
    tile_mma_16x64(Qs, m0, Ks, qr, qc, sacc);

    float mx0 = -1e30f, mx1 = -1e30f;
    #pragma unroll
    for (int nt = 0; nt < 8; nt++) {
        mx0 = fmaxf(mx0, fmaxf(sacc[nt][0], sacc[nt][1]));
        mx1 = fmaxf(mx1, fmaxf(sacc[nt][2], sacc[nt][3]));
    }
    #pragma unroll
    for (int off = 1; off < 4; off <<= 1) {
        mx0 = fmaxf(mx0, __shfl_xor_sync(0xffffffffu, mx0, off));
        mx1 = fmaxf(mx1, __shfl_xor_sync(0xffffffffu, mx1, off));
    }
    float rs0 = 0.f, rs1 = 0.f;
    #pragma unroll
    for (int nt = 0; nt < 8; nt++) {
        const float p0 = to_tf32(__expf(sacc[nt][0] - mx0));
        const float p1 = to_tf32(__expf(sacc[nt][1] - mx0));
        const float p2 = to_tf32(__expf(sacc[nt][2] - mx1));
        const float p3 = to_tf32(__expf(sacc[nt][3] - mx1));
        sacc[nt][0] = p0; sacc[nt][1] = p1; sacc[nt][2] = p2; sacc[nt][3] = p3;
        rs0 += p0 + p1; rs1 += p2 + p3;
    }
    #pragma unroll
    for (int off = 1; off < 4; off <<= 1) {
        rs0 += __shfl_xor_sync(0xffffffffu, rs0, off);
        rs1 += __shfl_xor_sync(0xffffffffu, rs1, off);
    }

    #pragma unroll
    for (int nt = 0; nt < 8; nt++) {
        *(float2*)&Ps[(m0 + qr)     * DPAD + nt * 8 + 2 * qc] = make_float2(sacc[nt][0], sacc[nt][1]);
        *(float2*)&Ps[(m0 + qr + 8) * DPAD + nt * 8 + 2 * qc] = make_float2(sacc[nt][2], sacc[nt][3]);
    }
    __syncwarp();

    float oacc2[8][4];
    #pragma unroll
    for (int nt = 0; nt < 8; nt++)
        #pragma unroll
        for (int r = 0; r < 4; r++) oacc2[nt][r] = 0.f;
    tile_mma_16x64(Ps, m0, Vt, qr, qc, oacc2);

    // out = oacc/l + oacc2/l2, tf32-rounded
    const float i0 = 1.f / lL[0], i1 = 1.f / lL[1];
    const float j0 = 1.f / rs0,   j1 = 1.f / rs1;
    #pragma unroll
    for (int nt = 0; nt < 8; nt++) {
        const int col = h * 64 + nt * 8 + 2 * qc;
        const int r0 = b * TSEQ + row0 + m0 + qr;
        float2 v0, v1;
        v0.x = to_tf32(oacc[nt][0] * i0 + oacc2[nt][0] * j0);
        v0.y = to_tf32(oacc[nt][1] * i0 + oacc2[nt][1] * j0);
        v1.x = to_tf32(oacc[nt][2] * i1 + oacc2[nt][2] * j1);
        v1.y = to_tf32(oacc[nt][3] * i1 + oacc2[nt][3] * j1);
        *(float2*)(out + (size_t)r0 * CDIM + col)       = v0;
        *(float2*)(out + (size_t)(r0 + 8) * CDIM + col) = v1;
    }
}

// ---------------- launch ----------------
extern "C" void kernel_launch(void* const* d_in, const int* in_sizes, int n_in,
                              void* d_out, int out_size)
{
    const float* x      = (const float*)d_in[0];
    const float* memory = (const float*)d_in[1];
    const float* ln1_g  = (const float*)d_in[2];
    const float* ln1_b  = (const float*)d_in[3];
    const float* w_qkv  = (const float*)d_in[4];
    const float* b_qkv  = (const float*)d_in[5];
    const float* w_out  = (const float*)d_in[6];
    const float* b_out  = (const float*)d_in[7];
    const float* w_mem  = (const float*)d_in[8];
    const float* b_mem  = (const float*)d_in[9];
    const float* ln2_g  = (const float*)d_in[10];
    const float* ln2_b  = (const float*)d_in[11];
    const float* w_fc1  = (const float*)d_in[12];
    const float* b_fc1  = (const float*)d_in[13];
    const float* w_fc2  = (const float*)d_in[14];
    const float* b_fc2  = (const float*)d_in[15];
    float* out = (float*)d_out;

    float *pH, *pQKV, *pMEMP, *pATTN, *pX1, *pH2, *pHID;
    float *pWQKVT, *pWOUTT, *pWFC1T, *pWFC2T;
    cudaGetSymbolAddress((void**)&pH,     g_H);
    cudaGetSymbolAddress((void**)&pQKV,   g_QKV);
    cudaGetSymbolAddress((void**)&pMEMP,  g_MEMP);
    cudaGetSymbolAddress((void**)&pATTN,  g_ATTN);
    cudaGetSymbolAddress((void**)&pX1,    g_X1);
    cudaGetSymbolAddress((void**)&pH2,    g_H2);
    cudaGetSymbolAddress((void**)&pHID,   g_HID);
    cudaGetSymbolAddress((void**)&pWQKVT, g_WQKVT);
    cudaGetSymbolAddress((void**)&pWOUTT, g_WOUTT);
    cudaGetSymbolAddress((void**)&pWFC1T, g_WFC1T);
    cudaGetSymbolAddress((void**)&pWFC2T, g_WFC2T);

    cudaFuncSetAttribute(attn_mma, cudaFuncAttributeMaxDynamicSharedMemorySize, ATTN_SMEM);

    const int ROWS = BATCH * TSEQ;  // 4096

    transpose_tf32<<<dim3(3 * CDIM / 32, CDIM / 32), 256>>>(w_qkv, pWQKVT, CDIM, 3 * CDIM);
    transpose_tf32<<<dim3(CDIM / 32, CDIM / 32), 256>>>(w_out, pWOUTT, CDIM, CDIM);
    transpose_tf32<<<dim3(HIDDEN / 32, CDIM / 32), 256>>>(w_fc1, pWFC1T, CDIM, HIDDEN);
    transpose_tf32<<<dim3(CDIM / 32, HIDDEN / 32), 256>>>(w_fc2, pWFC2T, HIDDEN, CDIM);

    ln_kernel<<<ROWS, 256>>>(x, ln1_g, ln1_b, pH);
    memproj_kernel<<<CDIM / 64, 256>>>(memory, w_mem, b_mem, pMEMP);

    gemm_mma<0><<<dim3(3 * CDIM / 128, ROWS / 128), 256>>>(
        pH, pWQKVT, b_qkv, nullptr, pQKV, ROWS, 3 * CDIM, CDIM);

    attn_mma<<<dim3(TSEQ / QT, NHEAD, BATCH), 256, ATTN_SMEM>>>(pQKV, pMEMP, pATTN);

    gemm_mma<1><<<dim3(CDIM / 128, ROWS / 128), 256>>>(
        pATTN, pWOUTT, b_out, x, pX1, ROWS, CDIM, CDIM);

    ln_kernel<<<ROWS, 256>>>(pX1, ln2_g, ln2_b, pH2);

    gemm_mma<2><<<dim3(HIDDEN / 128, ROWS / 128), 256>>>(
        pH2, pWFC1T, b_fc1, nullptr, pHID, ROWS, HIDDEN, CDIM);

    gemm_mma<1><<<dim3(CDIM / 128, ROWS / 128), 256>>>(
        pHID, pWFC2T, b_fc2, pX1, out, ROWS, CDIM, HIDDEN);
}

// round 5
// speedup vs baseline: 3.0835x; 1.0459x over previous
#include <cuda_runtime.h>
#include <math.h>
#include <stdint.h>

#define CDIM   1024
#define TSEQ   2048
#define BATCH  2
#define NHEAD  16
#define HDIM   64
#define MMEM   64
#define HIDDEN 4096

// ---------------- scratch (device globals; no allocation) ----------------
__device__ float g_H    [BATCH*TSEQ*CDIM];
__device__ float g_QKV  [BATCH*TSEQ*3*CDIM];
__device__ float g_MEMP [MMEM*CDIM];
__device__ float g_ATTN [BATCH*TSEQ*CDIM];
__device__ float g_X1   [BATCH*TSEQ*CDIM];
__device__ float g_H2   [BATCH*TSEQ*CDIM];
__device__ float g_HID  [BATCH*TSEQ*HIDDEN];
__device__ float g_WQKVT[3*CDIM*CDIM];
__device__ float g_WOUTT[CDIM*CDIM];
__device__ float g_WFC1T[HIDDEN*CDIM];
__device__ float g_WFC2T[CDIM*HIDDEN];

__device__ __forceinline__ float to_tf32(float x) {
    float y; asm("cvt.rna.tf32.f32 %0, %1;" : "=f"(y) : "f"(x)); return y;
}

__device__ __forceinline__ uint32_t smem_u32(const void* p) {
    uint32_t a;
    asm("{ .reg .u64 t; cvta.to.shared.u64 t, %1; cvt.u32.u64 %0, t; }" : "=r"(a) : "l"(p));
    return a;
}

__device__ __forceinline__ void cp16(uint32_t dst, const float* src) {
    asm volatile("cp.async.cg.shared.global [%0], [%1], 16;" :: "r"(dst), "l"(src));
}

__device__ __forceinline__ void mma_tf32(float* c, uint32_t a0, uint32_t a1,
                                         uint32_t a2, uint32_t a3,
                                         uint32_t b0, uint32_t b1)
{
    asm volatile(
        "mma.sync.aligned.m16n8k8.row.col.f32.tf32.tf32.f32 "
        "{%0,%1,%2,%3}, {%4,%5,%6,%7}, {%8,%9}, {%0,%1,%2,%3};"
        : "+f"(c[0]), "+f"(c[1]), "+f"(c[2]), "+f"(c[3])
        : "r"(a0), "r"(a1), "r"(a2), "r"(a3), "r"(b0), "r"(b1));
}

// ---------------- LayerNorm (output rounded to tf32) ----------------
__global__ __launch_bounds__(256)
void ln_kernel(const float* __restrict__ x, const float* __restrict__ g,
               const float* __restrict__ b, float* __restrict__ y)
{
    __shared__ float red[18];
    const int row = blockIdx.x;
    const int tid = threadIdx.x;
    const float4 v = ((const float4*)(x + (size_t)row * CDIM))[tid];
    float s  = v.x + v.y + v.z + v.w;
    float ss = v.x*v.x + v.y*v.y + v.z*v.z + v.w*v.w;
    #pragma unroll
    for (int off = 16; off; off >>= 1) {
        s  += __shfl_xor_sync(0xffffffffu, s,  off);
        ss += __shfl_xor_sync(0xffffffffu, ss, off);
    }
    if ((tid & 31) == 0) { red[tid >> 5] = s; red[8 + (tid >> 5)] = ss; }
    __syncthreads();
    if (tid == 0) {
        float ts = 0.f, tss = 0.f;
        #pragma unroll
        for (int w = 0; w < 8; w++) { ts += red[w]; tss += red[8 + w]; }
        red[16] = ts; red[17] = tss;
    }
    __syncthreads();
    const float mu  = red[16] * (1.f / CDIM);
    const float var = red[17] * (1.f / CDIM) - mu * mu;
    const float inv = rsqrtf(var + 1e-5f);
    const float4 gv = ((const float4*)g)[tid];
    const float4 bv = ((const float4*)b)[tid];
    float4 o;
    o.x = to_tf32((v.x - mu) * inv * gv.x + bv.x);
    o.y = to_tf32((v.y - mu) * inv * gv.y + bv.y);
    o.z = to_tf32((v.z - mu) * inv * gv.z + bv.z);
    o.w = to_tf32((v.w - mu) * inv * gv.w + bv.w);
    ((float4*)(y + (size_t)row * CDIM))[tid] = o;
}

// ---------------- weight transpose + tf32 round ----------------
__global__ __launch_bounds__(256)
void transpose_tf32(const float* __restrict__ S, float* __restrict__ D, int K, int N)
{
    __shared__ float t[32][33];
    const int bx = blockIdx.x * 32;
    const int by = blockIdx.y * 32;
    const int x = threadIdx.x & 31, y = threadIdx.x >> 5;
    #pragma unroll
    for (int i = 0; i < 32; i += 8)
        t[y + i][x] = S[(size_t)(by + y + i) * N + bx + x];
    __syncthreads();
    #pragma unroll
    for (int i = 0; i < 32; i += 8)
        D[(size_t)(bx + y + i) * K + by + x] = to_tf32(t[x][y + i]);
}

// ---------------- tf32 mma.sync GEMM, cp.async double-buffered ----------------
#define SKEW 36
#define GSMEM_FLOATS (4 * 128 * SKEW)          // 2 stages x (A+B) x 128 x SKEW
#define GSMEM_BYTES  (GSMEM_FLOATS * 4)        // 73728

template<int EPI>
__global__ __launch_bounds__(256, 2)
void gemm_mma(const float* __restrict__ A, const float* __restrict__ Bt,
              const float* __restrict__ bias, const float* __restrict__ res,
              float* __restrict__ C, int M, int N, int K)
{
    extern __shared__ float sgm[];
    // layout: Astage0 | Astage1 | Bstage0 | Bstage1, each 128*SKEW floats
    const uint32_t sAa = smem_u32(sgm);
    const uint32_t sBa = sAa + 2u * 128u * SKEW * 4u;

    const int tid = threadIdx.x;
    const int wid = tid >> 5, lane = tid & 31;
    const int wm = (wid & 1) * 64;
    const int wn = (wid >> 1) * 32;
    const int bm = blockIdx.y * 128;
    const int bn = blockIdx.x * 128;

    const int lrow = tid >> 3;            // 0..31
    const int lcol = (tid & 7) << 2;      // 0..28
    const float* Ap = A  + (size_t)(bm + lrow) * K + lcol;
    const float* Bp = Bt + (size_t)(bn + lrow) * K + lcol;
    const uint32_t soff = ((uint32_t)lrow * SKEW + (uint32_t)lcol) * 4u;

    const int qr = lane >> 2;
    const int qc = lane & 3;
    const int nchunk = K / 32;

    float acc[4][4][4];
    #pragma unroll
    for (int i = 0; i < 4; i++)
        #pragma unroll
        for (int j = 0; j < 4; j++)
            #pragma unroll
            for (int r = 0; r < 4; r++) acc[i][j][r] = 0.f;

    // prefetch chunk 0 into stage 0
    {
        const uint32_t da = sAa + soff;
        const uint32_t db = sBa + soff;
        #pragma unroll
        for (int p = 0; p < 4; p++) {
            cp16(da + p * 32 * SKEW * 4, Ap + (size_t)(p * 32) * K);
            cp16(db + p * 32 * SKEW * 4, Bp + (size_t)(p * 32) * K);
        }
        asm volatile("cp.async.commit_group;");
    }

    for (int ch = 0; ch < nchunk; ch++) {
        // issue next chunk into the other stage
        if (ch + 1 < nchunk) {
            const int sn = (ch + 1) & 1;
            const int k0 = (ch + 1) * 32;
            const uint32_t da = sAa + (uint32_t)sn * 128u * SKEW * 4u + soff;
            const uint32_t db = sBa + (uint32_t)sn * 128u * SKEW * 4u + soff;
            #pragma unroll
            for (int p = 0; p < 4; p++) {
                cp16(da + p * 32 * SKEW * 4, Ap + (size_t)(p * 32) * K + k0);
                cp16(db + p * 32 * SKEW * 4, Bp + (size_t)(p * 32) * K + k0);
            }
        }
        asm volatile("cp.async.commit_group;");
        asm volatile("cp.async.wait_group 1;");
        __syncthreads();

        const int st = ch & 1;
        const float* Asm = sgm + (size_t)st * 128 * SKEW;
        const float* Bsm = sgm + (size_t)(2 + st) * 128 * SKEW;

        #pragma unroll
        for (int ks = 0; ks < 4; ks++) {
            const int kk = ks * 8;
            uint32_t bf[4][2];
            #pragma unroll
            for (int nt = 0; nt < 4; nt++) {
                const int n0 = wn + nt * 8 + qr;
                bf[nt][0] = __float_as_uint(Bsm[n0 * SKEW + kk + qc]);
                bf[nt][1] = __float_as_uint(Bsm[n0 * SKEW + kk + qc + 4]);
            }
            #pragma unroll
            for (int mt = 0; mt < 4; mt++) {
                const int m0 = wm + mt * 16 + qr;
                const uint32_t a0 = __float_as_uint(Asm[m0 * SKEW + kk + qc]);
                const uint32_t a1 = __float_as_uint(Asm[(m0 + 8) * SKEW + kk + qc]);
                const uint32_t a2 = __float_as_uint(Asm[m0 * SKEW + kk + qc + 4]);
                const uint32_t a3 = __float_as_uint(Asm[(m0 + 8) * SKEW + kk + qc + 4]);
                #pragma unroll
                for (int nt = 0; nt < 4; nt++)
                    mma_tf32(acc[mt][nt], a0, a1, a2, a3, bf[nt][0], bf[nt][1]);
            }
        }
        __syncthreads();
    }

    #pragma unroll
    for (int mt = 0; mt < 4; mt++) {
        #pragma unroll
        for (int half = 0; half < 2; half++) {
            const int row = bm + wm + mt * 16 + qr + half * 8;
            float* Crow = C + (size_t)row * N;
            const float* Rrow = res + (size_t)row * N;
            #pragma unroll
            for (int nt = 0; nt < 4; nt++) {
                const int col = bn + wn + nt * 8 + qc * 2;
                float v0 = acc[mt][nt][half * 2 + 0] + bias[col];
                float v1 = acc[mt][nt][half * 2 + 1] + bias[col + 1];
                if (EPI == 1) {
                    const float2 rv = *(const float2*)(Rrow + col);
                    v0 += rv.x; v1 += rv.y;
                }
                if (EPI == 2) {
                    v0 = to_tf32(0.5f * v0 * (1.0f + erff(v0 * 0.70710678118654752f)));
                    v1 = to_tf32(0.5f * v1 * (1.0f + erff(v1 * 0.70710678118654752f)));
                }
                *(float2*)(Crow + col) = make_float2(v0, v1);
            }
        }
    }
}

// ---------------- memory projection: (64x1024)@(1024x1024)+bias ----------------
__global__ __launch_bounds__(256)
void memproj_kernel(const float* __restrict__ A, const float* __restrict__ B,
                    const float* __restrict__ bias, float* __restrict__ C)
{
    __shared__ float Ast[16][64];
    __shared__ float Bs [16][64];
    const int tid = threadIdx.x;
    const int tx = tid & 15, ty = tid >> 4;
    const int bn = blockIdx.x * 64;
    const int ar = tid >> 2, ak = (tid & 3) << 2;
    const int bk = tid >> 4, bc = (tid & 15) << 2;

    float acc[4][4];
    #pragma unroll
    for (int i = 0; i < 4; i++)
        #pragma unroll
        for (int j = 0; j < 4; j++) acc[i][j] = 0.f;

    for (int k0 = 0; k0 < CDIM; k0 += 16) {
        const float4 av = *(const float4*)(A + (size_t)ar * CDIM + k0 + ak);
        const float4 bv = *(const float4*)(B + (size_t)(k0 + bk) * CDIM + bn + bc);
        __syncthreads();
        Ast[ak + 0][ar] = av.x;
        Ast[ak + 1][ar] = av.y;
        Ast[ak + 2][ar] = av.z;
        Ast[ak + 3][ar] = av.w;
        *(float4*)&Bs[bk][bc] = bv;
        __syncthreads();
        #pragma unroll
        for (int kk = 0; kk < 16; kk++) {
            const float4 a = *(const float4*)&Ast[kk][ty * 4];
            const float4 b = *(const float4*)&Bs[kk][tx * 4];
            const float arr[4] = {a.x, a.y, a.z, a.w};
            const float brr[4] = {b.x, b.y, b.z, b.w};
            #pragma unroll
            for (int i = 0; i < 4; i++)
                #pragma unroll
                for (int j = 0; j < 4; j++)
                    acc[i][j] = fmaf(arr[i], brr[j], acc[i][j]);
        }
    }
    #pragma unroll
    for (int i = 0; i < 4; i++) {
        const int col = bn + tx * 4;
        const float4 bsv = *(const float4*)(bias + col);
        float4 o;
        o.x = acc[i][0] + bsv.x;
        o.y = acc[i][1] + bsv.y;
        o.z = acc[i][2] + bsv.z;
        o.w = acc[i][3] + bsv.w;
        *(float4*)(C + (size_t)(ty * 4 + i) * CDIM + col) = o;
    }
}

// ---------------- tf32 mma attention (proven in R4) ----------------
#define QT   128
#define KC   64
#define DPAD 68
#define ATTN_SMEM ((128*DPAD + 64*DPAD + 64*DPAD + 128*DPAD) * 4)

__device__ __forceinline__ void load_kv_chunk(const float* __restrict__ kbase,
                                              const float* __restrict__ vbase,
                                              size_t rstride, float* Ks, float* Vt, int tid)
{
    const int r  = tid >> 2;
    const int c0 = (tid & 3) * 16;
    const float* kp = kbase + (size_t)r * rstride + c0;
    #pragma unroll
    for (int j = 0; j < 16; j += 4) {
        const float4 v = *(const float4*)(kp + j);
        Ks[r * DPAD + c0 + j + 0] = to_tf32(v.x);
        Ks[r * DPAD + c0 + j + 1] = to_tf32(v.y);
        Ks[r * DPAD + c0 + j + 2] = to_tf32(v.z);
        Ks[r * DPAD + c0 + j + 3] = to_tf32(v.w);
    }
    const float* vp = vbase + (size_t)r * rstride + c0;
    #pragma unroll
    for (int j = 0; j < 16; j += 4) {
        const float4 v = *(const float4*)(vp + j);
        Vt[(c0 + j + 0) * DPAD + r] = to_tf32(v.x);
        Vt[(c0 + j + 1) * DPAD + r] = to_tf32(v.y);
        Vt[(c0 + j + 2) * DPAD + r] = to_tf32(v.z);
        Vt[(c0 + j + 3) * DPAD + r] = to_tf32(v.w);
    }
}

__device__ __forceinline__ void tile_mma_16x64(const float* __restrict__ Asm, int m0,
                                               const float* __restrict__ Bsm,
                                               int qr, int qc, float acc[8][4])
{
    #pragma unroll
    for (int ks = 0; ks < 8; ks++) {
        const int kk = ks * 8;
        const uint32_t a0 = __float_as_uint(Asm[(m0 + qr)     * DPAD + kk + qc]);
        const uint32_t a1 = __float_as_uint(Asm[(m0 + qr + 8) * DPAD + kk + qc]);
        const uint32_t a2 = __float_as_uint(Asm[(m0 + qr)     * DPAD + kk + qc + 4]);
        const uint32_t a3 = __float_as_uint(Asm[(m0 + qr + 8) * DPAD + kk + qc + 4]);
        #pragma unroll
        for (int nt = 0; nt < 8; nt++) {
            const uint32_t b0 = __float_as_uint(Bsm[(nt * 8 + qr) * DPAD + kk + qc]);
            const uint32_t b1 = __float_as_uint(Bsm[(nt * 8 + qr) * DPAD + kk + qc + 4]);
            mma_tf32(acc[nt], a0, a1, a2, a3, b0, b1);
        }
    }
}

__global__ __launch_bounds__(256)
void attn_mma(const float* __restrict__ qkv, const float* __restrict__ memp,
              float* __restrict__ out)
{
    extern __shared__ float sm[];
    float* Qs = sm;
    float* Ks = sm + 128 * DPAD;
    float* Vt = Ks + 64 * DPAD;
    float* Ps = Vt + 64 * DPAD;

    const int tid  = threadIdx.x;
    const int wid  = tid >> 5, lane = tid & 31;
    const int qr   = lane >> 2, qc = lane & 3;
    const int m0   = wid * 16;
    const int h    = blockIdx.y, b = blockIdx.z;
    const int row0 = blockIdx.x * QT;

    {
        const int r  = tid >> 1;
        const int c0 = (tid & 1) * 32;
        const float* qp = qkv + ((size_t)(b * TSEQ + row0 + r)) * (3 * CDIM) + h * 64 + c0;
        #pragma unroll
        for (int j = 0; j < 32; j += 4) {
            const float4 v = *(const float4*)(qp + j);
            Qs[r * DPAD + c0 + j + 0] = to_tf32(v.x * 0.125f);
            Qs[r * DPAD + c0 + j + 1] = to_tf32(v.y * 0.125f);
            Qs[r * DPAD + c0 + j + 2] = to_tf32(v.z * 0.125f);
            Qs[r * DPAD + c0 + j + 3] = to_tf32(v.w * 0.125f);
        }
    }

    float mM[2] = {-1e30f, -1e30f};
    float lL[2] = {0.f, 0.f};
    float oacc[8][4];
    #pragma unroll
    for (int nt = 0; nt < 8; nt++)
        #pragma unroll
        for (int r = 0; r < 4; r++) oacc[nt][r] = 0.f;

    for (int kc = 0; kc < TSEQ; kc += KC) {
        __syncthreads();
        load_kv_chunk(qkv + ((size_t)(b * TSEQ + kc)) * (3 * CDIM) + CDIM + h * 64,
                      qkv + ((size_t)(b * TSEQ + kc)) * (3 * CDIM) + 2 * CDIM + h * 64,
                      3 * CDIM, Ks, Vt, tid);
        __syncthreads();

        float sacc[8][4];
        #pragma unroll
        for (int nt = 0; nt < 8; nt++)
            #pragma unroll
            for (int r = 0; r < 4; r++) sacc[nt][r] = 0.f;
        tile_mma_16x64(Qs, m0, Ks, qr, qc, sacc);

        float mx0 = -1e30f, mx1 = -1e30f;
        #pragma unroll
        for (int nt = 0; nt < 8; nt++) {
            mx0 = fmaxf(mx0, fmaxf(sacc[nt][0], sacc[nt][1]));
            mx1 = fmaxf(mx1, fmaxf(sacc[nt][2], sacc[nt][3]));
        }
        #pragma unroll
        for (int off = 1; off < 4; off <<= 1) {
            mx0 = fmaxf(mx0, __shfl_xor_sync(0xffffffffu, mx0, off));
            mx1 = fmaxf(mx1, __shfl_xor_sync(0xffffffffu, mx1, off));
        }
        const float mn0 = fmaxf(mM[0], mx0);
        const float mn1 = fmaxf(mM[1], mx1);
        const float f0 = __expf(mM[0] - mn0);
        const float f1 = __expf(mM[1] - mn1);
        mM[0] = mn0; mM[1] = mn1;

        float rs0 = 0.f, rs1 = 0.f;
        #pragma unroll
        for (int nt = 0; nt < 8; nt++) {
            const float p0 = to_tf32(__expf(sacc[nt][0] - mn0));
            const float p1 = to_tf32(__expf(sacc[nt][1] - mn0));
            const float p2 = to_tf32(__expf(sacc[nt][2] - mn1));
            const float p3 = to_tf32(__expf(sacc[nt][3] - mn1));
            sacc[nt][0] = p0; sacc[nt][1] = p1; sacc[nt][2] = p2; sacc[nt][3] = p3;
            rs0 += p0 + p1; rs1 += p2 + p3;
        }
        #pragma unroll
        for (int off = 1; off < 4; off <<= 1) {
            rs0 += __shfl_xor_sync(0xffffffffu, rs0, off);
            rs1 += __shfl_xor_sync(0xffffffffu, rs1, off);
        }
        lL[0] = lL[0] * f0 + rs0;
        lL[1] = lL[1] * f1 + rs1;
        #pragma unroll
        for (int nt = 0; nt < 8; nt++) {
            oacc[nt][0] *= f0; oacc[nt][1] *= f0;
            oacc[nt][2] *= f1; oacc[nt][3] *= f1;
        }

        #pragma unroll
        for (int nt = 0; nt < 8; nt++) {
            *(float2*)&Ps[(m0 + qr)     * DPAD + nt * 8 + 2 * qc] = make_float2(sacc[nt][0], sacc[nt][1]);
            *(float2*)&Ps[(m0 + qr + 8) * DPAD + nt * 8 + 2 * qc] = make_float2(sacc[nt][2], sacc[nt][3]);
        }
        __syncwarp();

        tile_mma_16x64(Ps, m0, Vt, qr, qc, oacc);
    }

    // ---- compressive memory attention ----
    __syncthreads();
    load_kv_chunk(memp + h * 64, memp + h * 64, CDIM, Ks, Vt, tid);
    __syncthreads();

    float sacc[8][4];
    #pragma unroll
    for (int nt = 0; nt < 8; nt++)
        #pragma unroll
        for (int r = 0; r < 4; r++) sacc[nt][r] = 0.f;
    tile_mma_16x64(Qs, m0, Ks, qr, qc, sacc);

    float mx0 = -1e30f, mx1 = -1e30f;
    #pragma unroll
    for (int nt = 0; nt < 8; nt++) {
        mx0 = fmaxf(mx0, fmaxf(sacc[nt][0], sacc[nt][1]));
        mx1 = fmaxf(mx1, fmaxf(sacc[nt][2], sacc[nt][3]));
    }
    #pragma unroll
    for (int off = 1; off < 4; off <<= 1) {
        mx0 = fmaxf(mx0, __shfl_xor_sync(0xffffffffu, mx0, off));
        mx1 = fmaxf(mx1, __shfl_xor_sync(0xffffffffu, mx1, off));
    }
    float rs0 = 0.f, rs1 = 0.f;
    #pragma unroll
    for (int nt = 0; nt < 8; nt++) {
        const float p0 = to_tf32(__expf(sacc[nt][0] - mx0));
        const float p1 = to_tf32(__expf(sacc[nt][1] - mx0));
        const float p2 = to_tf32(__expf(sacc[nt][2] - mx1));
        const float p3 = to_tf32(__expf(sacc[nt][3] - mx1));
        sacc[nt][0] = p0; sacc[nt][1] = p1; sacc[nt][2] = p2; sacc[nt][3] = p3;
        rs0 += p0 + p1; rs1 += p2 + p3;
    }
    #pragma unroll
    for (int off = 1; off < 4; off <<= 1) {
        rs0 += __shfl_xor_sync(0xffffffffu, rs0, off);
        rs1 += __shfl_xor_sync(0xffffffffu, rs1, off);
    }

    #pragma unroll
    for (int nt = 0; nt < 8; nt++) {
        *(float2*)&Ps[(m0 + qr)     * DPAD + nt * 8 + 2 * qc] = make_float2(sacc[nt][0], sacc[nt][1]);
        *(float2*)&Ps[(m0 + qr + 8) * DPAD + nt * 8 + 2 * qc] = make_float2(sacc[nt][2], sacc[nt][3]);
    }
    __syncwarp();

    float oacc2[8][4];
    #pragma unroll
    for (int nt = 0; nt < 8; nt++)
        #pragma unroll
        for (int r = 0; r < 4; r++) oacc2[nt][r] = 0.f;
    tile_mma_16x64(Ps, m0, Vt, qr, qc, oacc2);

    const float i0 = 1.f / lL[0], i1 = 1.f / lL[1];
    const float j0 = 1.f / rs0,   j1 = 1.f / rs1;
    #pragma unroll
    for (int nt = 0; nt < 8; nt++) {
        const int col = h * 64 + nt * 8 + 2 * qc;
        const int r0 = b * TSEQ + row0 + m0 + qr;
        float2 v0, v1;
        v0.x = to_tf32(oacc[nt][0] * i0 + oacc2[nt][0] * j0);
        v0.y = to_tf32(oacc[nt][1] * i0 + oacc2[nt][1] * j0);
        v1.x = to_tf32(oacc[nt][2] * i1 + oacc2[nt][2] * j1);
        v1.y = to_tf32(oacc[nt][3] * i1 + oacc2[nt][3] * j1);
        *(float2*)(out + (size_t)r0 * CDIM + col)       = v0;
        *(float2*)(out + (size_t)(r0 + 8) * CDIM + col) = v1;
    }
}

// ---------------- launch ----------------
extern "C" void kernel_launch(void* const* d_in, const int* in_sizes, int n_in,
                              void* d_out, int out_size)
{
    const float* x      = (const float*)d_in[0];
    const float* memory = (const float*)d_in[1];
    const float* ln1_g  = (const float*)d_in[2];
    const float* ln1_b  = (const float*)d_in[3];
    const float* w_qkv  = (const float*)d_in[4];
    const float* b_qkv  = (const float*)d_in[5];
    const float* w_out  = (const float*)d_in[6];
    const float* b_out  = (const float*)d_in[7];
    const float* w_mem  = (const float*)d_in[8];
    const float* b_mem  = (const float*)d_in[9];
    const float* ln2_g  = (const float*)d_in[10];
    const float* ln2_b  = (const float*)d_in[11];
    const float* w_fc1  = (const float*)d_in[12];
    const float* b_fc1  = (const float*)d_in[13];
    const float* w_fc2  = (const float*)d_in[14];
    const float* b_fc2  = (const float*)d_in[15];
    float* out = (float*)d_out;

    float *pH, *pQKV, *pMEMP, *pATTN, *pX1, *pH2, *pHID;
    float *pWQKVT, *pWOUTT, *pWFC1T, *pWFC2T;
    cudaGetSymbolAddress((void**)&pH,     g_H);
    cudaGetSymbolAddress((void**)&pQKV,   g_QKV);
    cudaGetSymbolAddress((void**)&pMEMP,  g_MEMP);
    cudaGetSymbolAddress((void**)&pATTN,  g_ATTN);
    cudaGetSymbolAddress((void**)&pX1,    g_X1);
    cudaGetSymbolAddress((void**)&pH2,    g_H2);
    cudaGetSymbolAddress((void**)&pHID,   g_HID);
    cudaGetSymbolAddress((void**)&pWQKVT, g_WQKVT);
    cudaGetSymbolAddress((void**)&pWOUTT, g_WOUTT);
    cudaGetSymbolAddress((void**)&pWFC1T, g_WFC1T);
    cudaGetSymbolAddress((void**)&pWFC2T, g_WFC2T);

    cudaFuncSetAttribute(attn_mma, cudaFuncAttributeMaxDynamicSharedMemorySize, ATTN_SMEM);
    cudaFuncSetAttribute(gemm_mma<0>, cudaFuncAttributeMaxDynamicSharedMemorySize, GSMEM_BYTES);
    cudaFuncSetAttribute(gemm_mma<1>, cudaFuncAttributeMaxDynamicSharedMemorySize, GSMEM_BYTES);
    cudaFuncSetAttribute(gemm_mma<2>, cudaFuncAttributeMaxDynamicSharedMemorySize, GSMEM_BYTES);

    const int ROWS = BATCH * TSEQ;  // 4096

    transpose_tf32<<<dim3(3 * CDIM / 32, CDIM / 32), 256>>>(w_qkv, pWQKVT, CDIM, 3 * CDIM);
    transpose_tf32<<<dim3(CDIM / 32, CDIM / 32), 256>>>(w_out, pWOUTT, CDIM, CDIM);
    transpose_tf32<<<dim3(HIDDEN / 32, CDIM / 32), 256>>>(w_fc1, pWFC1T, CDIM, HIDDEN);
    transpose_tf32<<<dim3(CDIM / 32, HIDDEN / 32), 256>>>(w_fc2, pWFC2T, HIDDEN, CDIM);

    ln_kernel<<<ROWS, 256>>>(x, ln1_g, ln1_b, pH);
    memproj_kernel<<<CDIM / 64, 256>>>(memory, w_mem, b_mem, pMEMP);

    gemm_mma<0><<<dim3(3 * CDIM / 128, ROWS / 128), 256, GSMEM_BYTES>>>(
        pH, pWQKVT, b_qkv, nullptr, pQKV, ROWS, 3 * CDIM, CDIM);

    attn_mma<<<dim3(TSEQ / QT, NHEAD, BATCH), 256, ATTN_SMEM>>>(pQKV, pMEMP, pATTN);

    gemm_mma<1><<<dim3(CDIM / 128, ROWS / 128), 256, GSMEM_BYTES>>>(
        pATTN, pWOUTT, b_out, x, pX1, ROWS, CDIM, CDIM);

    ln_kernel<<<ROWS, 256>>>(pX1, ln2_g, ln2_b, pH2);

    gemm_mma<2><<<dim3(HIDDEN / 128, ROWS / 128), 256, GSMEM_BYTES>>>(
        pH2, pWFC1T, b_fc1, nullptr, pHID, ROWS, HIDDEN, CDIM);

    gemm_mma<1><<<dim3(CDIM / 128, ROWS / 128), 256, GSMEM_BYTES>>>(
        pHID, pWFC2T, b_fc2, pX1, out, ROWS, CDIM, HIDDEN);
}

// round 6
// speedup vs baseline: 3.9953x; 1.2957x over previous
#include <cuda_runtime.h>
#include <cuda_fp16.h>
#include <math.h>
#include <stdint.h>

#define CDIM   1024
#define TSEQ   2048
#define BATCH  2
#define NHEAD  16
#define HDIM   64
#define MMEM   64
#define HIDDEN 4096

// ---------------- scratch (device globals; no allocation) ----------------
__device__ __half g_H    [BATCH*TSEQ*CDIM];      // LN1 out (half)
__device__ float  g_QKV  [BATCH*TSEQ*3*CDIM];    // qkv (fp32, attention reads)
__device__ float  g_MEMP [MMEM*CDIM];
__device__ __half g_ATTN [BATCH*TSEQ*CDIM];      // attention out (half)
__device__ float  g_X1   [BATCH*TSEQ*CDIM];      // residual stream (fp32)
__device__ __half g_H2   [BATCH*TSEQ*CDIM];      // LN2 out (half)
__device__ __half g_HID  [BATCH*TSEQ*HIDDEN];    // fc1 out (half)
__device__ __half g_WQKVT[3*CDIM*CDIM];
__device__ __half g_WOUTT[CDIM*CDIM];
__device__ __half g_WFC1T[HIDDEN*CDIM];
__device__ __half g_WFC2T[CDIM*HIDDEN];

__device__ __forceinline__ float to_tf32(float x) {
    float y; asm("cvt.rna.tf32.f32 %0, %1;" : "=f"(y) : "f"(x)); return y;
}
__device__ __forceinline__ uint32_t smem_u32(const void* p) {
    uint32_t a;
    asm("{ .reg .u64 t; cvta.to.shared.u64 t, %1; cvt.u32.u64 %0, t; }" : "=r"(a) : "l"(p));
    return a;
}
__device__ __forceinline__ void cp16(uint32_t dst, const void* src) {
    asm volatile("cp.async.cg.shared.global [%0], [%1], 16;" :: "r"(dst), "l"(src));
}
__device__ __forceinline__ void mma_tf32(float* c, uint32_t a0, uint32_t a1,
                                         uint32_t a2, uint32_t a3,
                                         uint32_t b0, uint32_t b1)
{
    asm volatile(
        "mma.sync.aligned.m16n8k8.row.col.f32.tf32.tf32.f32 "
        "{%0,%1,%2,%3}, {%4,%5,%6,%7}, {%8,%9}, {%0,%1,%2,%3};"
        : "+f"(c[0]), "+f"(c[1]), "+f"(c[2]), "+f"(c[3])
        : "r"(a0), "r"(a1), "r"(a2), "r"(a3), "r"(b0), "r"(b1));
}
__device__ __forceinline__ void mma_f16(float* c, uint32_t a0, uint32_t a1,
                                        uint32_t a2, uint32_t a3,
                                        uint32_t b0, uint32_t b1)
{
    asm volatile(
        "mma.sync.aligned.m16n8k16.row.col.f32.f16.f16.f32 "
        "{%0,%1,%2,%3}, {%4,%5,%6,%7}, {%8,%9}, {%0,%1,%2,%3};"
        : "+f"(c[0]), "+f"(c[1]), "+f"(c[2]), "+f"(c[3])
        : "r"(a0), "r"(a1), "r"(a2), "r"(a3), "r"(b0), "r"(b1));
}

// ---------------- LayerNorm (half output) ----------------
__global__ __launch_bounds__(256)
void ln_kernel(const float* __restrict__ x, const float* __restrict__ g,
               const float* __restrict__ b, __half* __restrict__ y)
{
    __shared__ float red[18];
    const int row = blockIdx.x;
    const int tid = threadIdx.x;
    const float4 v = ((const float4*)(x + (size_t)row * CDIM))[tid];
    float s  = v.x + v.y + v.z + v.w;
    float ss = v.x*v.x + v.y*v.y + v.z*v.z + v.w*v.w;
    #pragma unroll
    for (int off = 16; off; off >>= 1) {
        s  += __shfl_xor_sync(0xffffffffu, s,  off);
        ss += __shfl_xor_sync(0xffffffffu, ss, off);
    }
    if ((tid & 31) == 0) { red[tid >> 5] = s; red[8 + (tid >> 5)] = ss; }
    __syncthreads();
    if (tid == 0) {
        float ts = 0.f, tss = 0.f;
        #pragma unroll
        for (int w = 0; w < 8; w++) { ts += red[w]; tss += red[8 + w]; }
        red[16] = ts; red[17] = tss;
    }
    __syncthreads();
    const float mu  = red[16] * (1.f / CDIM);
    const float var = red[17] * (1.f / CDIM) - mu * mu;
    const float inv = rsqrtf(var + 1e-5f);
    const float4 gv = ((const float4*)g)[tid];
    const float4 bv = ((const float4*)b)[tid];
    __half2 h01 = __floats2half2_rn((v.x - mu) * inv * gv.x + bv.x,
                                    (v.y - mu) * inv * gv.y + bv.y);
    __half2 h23 = __floats2half2_rn((v.z - mu) * inv * gv.z + bv.z,
                                    (v.w - mu) * inv * gv.w + bv.w);
    __half2* yp = (__half2*)(y + (size_t)row * CDIM + tid * 4);
    yp[0] = h01; yp[1] = h23;
}

// ---------------- weight transpose + half convert: D[n][k] = h(S[k][n]) ----------------
__global__ __launch_bounds__(256)
void transpose_h(const float* __restrict__ S, __half* __restrict__ D, int K, int N)
{
    __shared__ float t[32][33];
    const int bx = blockIdx.x * 32;
    const int by = blockIdx.y * 32;
    const int x = threadIdx.x & 31, y = threadIdx.x >> 5;
    #pragma unroll
    for (int i = 0; i < 32; i += 8)
        t[y + i][x] = S[(size_t)(by + y + i) * N + bx + x];
    __syncthreads();
    #pragma unroll
    for (int i = 0; i < 32; i += 8)
        D[(size_t)(bx + y + i) * K + by + x] = __float2half_rn(t[x][y + i]);
}

// ---------------- fp16 mma.sync GEMM, cp.async double-buffered ----------------
#define SKEWH 40
#define GST   (128 * SKEWH)                       // halfs per stage per matrix
#define GSMEM_BYTES (4 * GST * 2)                 // 40960 B

template<int EPI, typename TOut>
__global__ __launch_bounds__(256, 2)
void gemm_mma(const __half* __restrict__ A, const __half* __restrict__ Bt,
              const float* __restrict__ bias, const float* __restrict__ res,
              TOut* __restrict__ C, int M, int N, int K)
{
    extern __shared__ __half sgm[];
    // layout: A stage0 | A stage1 | B stage0 | B stage1
    const uint32_t sAa = smem_u32(sgm);
    const uint32_t sBa = sAa + 2u * GST * 2u;

    const int tid = threadIdx.x;
    const int wid = tid >> 5, lane = tid & 31;
    const int wm = (wid & 1) * 64;
    const int wn = (wid >> 1) * 32;
    const int bm = blockIdx.y * 128;
    const int bn = blockIdx.x * 128;

    const int lrow = tid >> 2;            // 0..63
    const int lcol = (tid & 3) << 3;      // halfs: 0,8,16,24
    const __half* Ap = A  + (size_t)(bm + lrow) * K + lcol;
    const __half* Bp = Bt + (size_t)(bn + lrow) * K + lcol;
    const uint32_t soff = ((uint32_t)lrow * SKEWH + (uint32_t)lcol) * 2u;

    const int qr = lane >> 2;
    const int qc = lane & 3;
    const int nchunk = K / 32;

    float acc[4][4][4];
    #pragma unroll
    for (int i = 0; i < 4; i++)
        #pragma unroll
        for (int j = 0; j < 4; j++)
            #pragma unroll
            for (int r = 0; r < 4; r++) acc[i][j][r] = 0.f;

    // prefetch chunk 0 into stage 0
    {
        #pragma unroll
        for (int p = 0; p < 2; p++) {
            cp16(sAa + soff + p * 64 * SKEWH * 2, Ap + (size_t)(p * 64) * K);
            cp16(sBa + soff + p * 64 * SKEWH * 2, Bp + (size_t)(p * 64) * K);
        }
        asm volatile("cp.async.commit_group;");
    }

    for (int ch = 0; ch < nchunk; ch++) {
        if (ch + 1 < nchunk) {
            const int sn = (ch + 1) & 1;
            const int k0 = (ch + 1) * 32;
            #pragma unroll
            for (int p = 0; p < 2; p++) {
                cp16(sAa + (uint32_t)sn * GST * 2u + soff + p * 64 * SKEWH * 2,
                     Ap + (size_t)(p * 64) * K + k0);
                cp16(sBa + (uint32_t)sn * GST * 2u + soff + p * 64 * SKEWH * 2,
                     Bp + (size_t)(p * 64) * K + k0);
            }
        }
        asm volatile("cp.async.commit_group;");
        asm volatile("cp.async.wait_group 1;");
        __syncthreads();

        const int st = ch & 1;
        const __half* Asm = sgm + (size_t)st * GST;
        const __half* Bsm = sgm + (size_t)(2 + st) * GST;

        #pragma unroll
        for (int ks = 0; ks < 2; ks++) {
            const int kk = ks * 16;
            uint32_t bf[4][2];
            #pragma unroll
            for (int nt = 0; nt < 4; nt++) {
                const int n0 = wn + nt * 8 + qr;
                bf[nt][0] = *(const uint32_t*)&Bsm[n0 * SKEWH + kk + 2 * qc];
                bf[nt][1] = *(const uint32_t*)&Bsm[n0 * SKEWH + kk + 8 + 2 * qc];
            }
            #pragma unroll
            for (int mt = 0; mt < 4; mt++) {
                const int m0 = wm + mt * 16 + qr;
                const uint32_t a0 = *(const uint32_t*)&Asm[m0 * SKEWH + kk + 2 * qc];
                const uint32_t a1 = *(const uint32_t*)&Asm[(m0 + 8) * SKEWH + kk + 2 * qc];
                const uint32_t a2 = *(const uint32_t*)&Asm[m0 * SKEWH + kk + 8 + 2 * qc];
                const uint32_t a3 = *(const uint32_t*)&Asm[(m0 + 8) * SKEWH + kk + 8 + 2 * qc];
                #pragma unroll
                for (int nt = 0; nt < 4; nt++)
                    mma_f16(acc[mt][nt], a0, a1, a2, a3, bf[nt][0], bf[nt][1]);
            }
        }
        __syncthreads();
    }

    #pragma unroll
    for (int mt = 0; mt < 4; mt++) {
        #pragma unroll
        for (int half_ = 0; half_ < 2; half_++) {
            const int row = bm + wm + mt * 16 + qr + half_ * 8;
            const float* Rrow = res + (size_t)row * N;
            #pragma unroll
            for (int nt = 0; nt < 4; nt++) {
                const int col = bn + wn + nt * 8 + qc * 2;
                float v0 = acc[mt][nt][half_ * 2 + 0] + bias[col];
                float v1 = acc[mt][nt][half_ * 2 + 1] + bias[col + 1];
                if (EPI == 1) {
                    const float2 rv = *(const float2*)(Rrow + col);
                    v0 += rv.x; v1 += rv.y;
                }
                if (EPI == 2) {
                    v0 = 0.5f * v0 * (1.0f + erff(v0 * 0.70710678118654752f));
                    v1 = 0.5f * v1 * (1.0f + erff(v1 * 0.70710678118654752f));
                }
                TOut* Crow = C + (size_t)row * N;
                if (sizeof(TOut) == 2) {
                    *(__half2*)((__half*)Crow + col) = __floats2half2_rn(v0, v1);
                } else {
                    *(float2*)((float*)Crow + col) = make_float2(v0, v1);
                }
            }
        }
    }
}

// ---------------- memory projection: (64x1024)@(1024x1024)+bias ----------------
__global__ __launch_bounds__(256)
void memproj_kernel(const float* __restrict__ A, const float* __restrict__ B,
                    const float* __restrict__ bias, float* __restrict__ C)
{
    __shared__ float Ast[16][64];
    __shared__ float Bs [16][64];
    const int tid = threadIdx.x;
    const int tx = tid & 15, ty = tid >> 4;
    const int bn = blockIdx.x * 64;
    const int ar = tid >> 2, ak = (tid & 3) << 2;
    const int bk = tid >> 4, bc = (tid & 15) << 2;

    float acc[4][4];
    #pragma unroll
    for (int i = 0; i < 4; i++)
        #pragma unroll
        for (int j = 0; j < 4; j++) acc[i][j] = 0.f;

    for (int k0 = 0; k0 < CDIM; k0 += 16) {
        const float4 av = *(const float4*)(A + (size_t)ar * CDIM + k0 + ak);
        const float4 bv = *(const float4*)(B + (size_t)(k0 + bk) * CDIM + bn + bc);
        __syncthreads();
        Ast[ak + 0][ar] = av.x;
        Ast[ak + 1][ar] = av.y;
        Ast[ak + 2][ar] = av.z;
        Ast[ak + 3][ar] = av.w;
        *(float4*)&Bs[bk][bc] = bv;
        __syncthreads();
        #pragma unroll
        for (int kk = 0; kk < 16; kk++) {
            const float4 a = *(const float4*)&Ast[kk][ty * 4];
            const float4 b = *(const float4*)&Bs[kk][tx * 4];
            const float arr[4] = {a.x, a.y, a.z, a.w};
            const float brr[4] = {b.x, b.y, b.z, b.w};
            #pragma unroll
            for (int i = 0; i < 4; i++)
                #pragma unroll
                for (int j = 0; j < 4; j++)
                    acc[i][j] = fmaf(arr[i], brr[j], acc[i][j]);
        }
    }
    #pragma unroll
    for (int i = 0; i < 4; i++) {
        const int col = bn + tx * 4;
        const float4 bsv = *(const float4*)(bias + col);
        float4 o;
        o.x = acc[i][0] + bsv.x;
        o.y = acc[i][1] + bsv.y;
        o.z = acc[i][2] + bsv.z;
        o.w = acc[i][3] + bsv.w;
        *(float4*)(C + (size_t)(ty * 4 + i) * CDIM + col) = o;
    }
}

// ---------------- tf32 mma attention (R4-proven; half output) ----------------
#define QT   128
#define KC   64
#define DPAD 68
#define ATTN_SMEM ((128*DPAD + 64*DPAD + 64*DPAD + 128*DPAD) * 4)

__device__ __forceinline__ void load_kv_chunk(const float* __restrict__ kbase,
                                              const float* __restrict__ vbase,
                                              size_t rstride, float* Ks, float* Vt, int tid)
{
    const int r  = tid >> 2;
    const int c0 = (tid & 3) * 16;
    const float* kp = kbase + (size_t)r * rstride + c0;
    #pragma unroll
    for (int j = 0; j < 16; j += 4) {
        const float4 v = *(const float4*)(kp + j);
        Ks[r * DPAD + c0 + j + 0] = to_tf32(v.x);
        Ks[r * DPAD + c0 + j + 1] = to_tf32(v.y);
        Ks[r * DPAD + c0 + j + 2] = to_tf32(v.z);
        Ks[r * DPAD + c0 + j + 3] = to_tf32(v.w);
    }
    const float* vp = vbase + (size_t)r * rstride + c0;
    #pragma unroll
    for (int j = 0; j < 16; j += 4) {
        const float4 v = *(const float4*)(vp + j);
        Vt[(c0 + j + 0) * DPAD + r] = to_tf32(v.x);
        Vt[(c0 + j + 1) * DPAD + r] = to_tf32(v.y);
        Vt[(c0 + j + 2) * DPAD + r] = to_tf32(v.z);
        Vt[(c0 + j + 3) * DPAD + r] = to_tf32(v.w);
    }
}

__device__ __forceinline__ void tile_mma_16x64(const float* __restrict__ Asm, int m0,
                                               const float* __restrict__ Bsm,
                                               int qr, int qc, float acc[8][4])
{
    #pragma unroll
    for (int ks = 0; ks < 8; ks++) {
        const int kk = ks * 8;
        const uint32_t a0 = __float_as_uint(Asm[(m0 + qr)     * DPAD + kk + qc]);
        const uint32_t a1 = __float_as_uint(Asm[(m0 + qr + 8) * DPAD + kk + qc]);
        const uint32_t a2 = __float_as_uint(Asm[(m0 + qr)     * DPAD + kk + qc + 4]);
        const uint32_t a3 = __float_as_uint(Asm[(m0 + qr + 8) * DPAD + kk + qc + 4]);
        #pragma unroll
        for (int nt = 0; nt < 8; nt++) {
            const uint32_t b0 = __float_as_uint(Bsm[(nt * 8 + qr) * DPAD + kk + qc]);
            const uint32_t b1 = __float_as_uint(Bsm[(nt * 8 + qr) * DPAD + kk + qc + 4]);
            mma_tf32(acc[nt], a0, a1, a2, a3, b0, b1);
        }
    }
}

__global__ __launch_bounds__(256)
void attn_mma(const float* __restrict__ qkv, const float* __restrict__ memp,
              __half* __restrict__ out)
{
    extern __shared__ float sm[];
    float* Qs = sm;
    float* Ks = sm + 128 * DPAD;
    float* Vt = Ks + 64 * DPAD;
    float* Ps = Vt + 64 * DPAD;

    const int tid  = threadIdx.x;
    const int wid  = tid >> 5, lane = tid & 31;
    const int qr   = lane >> 2, qc = lane & 3;
    const int m0   = wid * 16;
    const int h    = blockIdx.y, b = blockIdx.z;
    const int row0 = blockIdx.x * QT;

    {
        const int r  = tid >> 1;
        const int c0 = (tid & 1) * 32;
        const float* qp = qkv + ((size_t)(b * TSEQ + row0 + r)) * (3 * CDIM) + h * 64 + c0;
        #pragma unroll
        for (int j = 0; j < 32; j += 4) {
            const float4 v = *(const float4*)(qp + j);
            Qs[r * DPAD + c0 + j + 0] = to_tf32(v.x * 0.125f);
            Qs[r * DPAD + c0 + j + 1] = to_tf32(v.y * 0.125f);
            Qs[r * DPAD + c0 + j + 2] = to_tf32(v.z * 0.125f);
            Qs[r * DPAD + c0 + j + 3] = to_tf32(v.w * 0.125f);
        }
    }

    float mM[2] = {-1e30f, -1e30f};
    float lL[2] = {0.f, 0.f};
    float oacc[8][4];
    #pragma unroll
    for (int nt = 0; nt < 8; nt++)
        #pragma unroll
        for (int r = 0; r < 4; r++) oacc[nt][r] = 0.f;

    for (int kc = 0; kc < TSEQ; kc += KC) {
        __syncthreads();
        load_kv_chunk(qkv + ((size_t)(b * TSEQ + kc)) * (3 * CDIM) + CDIM + h * 64,
                      qkv + ((size_t)(b * TSEQ + kc)) * (3 * CDIM) + 2 * CDIM + h * 64,
                      3 * CDIM, Ks, Vt, tid);
        __syncthreads();

        float sacc[8][4];
        #pragma unroll
        for (int nt = 0; nt < 8; nt++)
            #pragma unroll
            for (int r = 0; r < 4; r++) sacc[nt][r] = 0.f;
        tile_mma_16x64(Qs, m0, Ks, qr, qc, sacc);

        float mx0 = -1e30f, mx1 = -1e30f;
        #pragma unroll
        for (int nt = 0; nt < 8; nt++) {
            mx0 = fmaxf(mx0, fmaxf(sacc[nt][0], sacc[nt][1]));
            mx1 = fmaxf(mx1, fmaxf(sacc[nt][2], sacc[nt][3]));
        }
        #pragma unroll
        for (int off = 1; off < 4; off <<= 1) {
            mx0 = fmaxf(mx0, __shfl_xor_sync(0xffffffffu, mx0, off));
            mx1 = fmaxf(mx1, __shfl_xor_sync(0xffffffffu, mx1, off));
        }
        const float mn0 = fmaxf(mM[0], mx0);
        const float mn1 = fmaxf(mM[1], mx1);
        const float f0 = __expf(mM[0] - mn0);
        const float f1 = __expf(mM[1] - mn1);
        mM[0] = mn0; mM[1] = mn1;

        float rs0 = 0.f, rs1 = 0.f;
        #pragma unroll
        for (int nt = 0; nt < 8; nt++) {
            const float p0 = to_tf32(__expf(sacc[nt][0] - mn0));
            const float p1 = to_tf32(__expf(sacc[nt][1] - mn0));
            const float p2 = to_tf32(__expf(sacc[nt][2] - mn1));
            const float p3 = to_tf32(__expf(sacc[nt][3] - mn1));
            sacc[nt][0] = p0; sacc[nt][1] = p1; sacc[nt][2] = p2; sacc[nt][3] = p3;
            rs0 += p0 + p1; rs1 += p2 + p3;
        }
        #pragma unroll
        for (int off = 1; off < 4; off <<= 1) {
            rs0 += __shfl_xor_sync(0xffffffffu, rs0, off);
            rs1 += __shfl_xor_sync(0xffffffffu, rs1, off);
        }
        lL[0] = lL[0] * f0 + rs0;
        lL[1] = lL[1] * f1 + rs1;
        #pragma unroll
        for (int nt = 0; nt < 8; nt++) {
            oacc[nt][0] *= f0; oacc[nt][1] *= f0;
            oacc[nt][2] *= f1; oacc[nt][3] *= f1;
        }

        #pragma unroll
        for (int nt = 0; nt < 8; nt++) {
            *(float2*)&Ps[(m0 + qr)     * DPAD + nt * 8 + 2 * qc] = make_float2(sacc[nt][0], sacc[nt][1]);
            *(float2*)&Ps[(m0 + qr + 8) * DPAD + nt * 8 + 2 * qc] = make_float2(sacc[nt][2], sacc[nt][3]);
        }
        __syncwarp();

        tile_mma_16x64(Ps, m0, Vt, qr, qc, oacc);
    }

    // ---- compressive memory attention ----
    __syncthreads();
    load_kv_chunk(memp + h * 64, memp + h * 64, CDIM, Ks, Vt, tid);
    __syncthreads();

    float sacc[8][4];
    #pragma unroll
    for (int nt = 0; nt < 8; nt++)
        #pragma unroll
        for (int r = 0; r < 4; r++) sacc[nt][r] = 0.f;
    tile_mma_16x64(Qs, m0, Ks, qr, qc, sacc);

    float mx0 = -1e30f, mx1 = -1e30f;
    #pragma unroll
    for (int nt = 0; nt < 8; nt++) {
        mx0 = fmaxf(mx0, fmaxf(sacc[nt][0], sacc[nt][1]));
        mx1 = fmaxf(mx1, fmaxf(sacc[nt][2], sacc[nt][3]));
    }
    #pragma unroll
    for (int off = 1; off < 4; off <<= 1) {
        mx0 = fmaxf(mx0, __shfl_xor_sync(0xffffffffu, mx0, off));
        mx1 = fmaxf(mx1, __shfl_xor_sync(0xffffffffu, mx1, off));
    }
    float rs0 = 0.f, rs1 = 0.f;
    #pragma unroll
    for (int nt = 0; nt < 8; nt++) {
        const float p0 = to_tf32(__expf(sacc[nt][0] - mx0));
        const float p1 = to_tf32(__expf(sacc[nt][1] - mx0));
        const float p2 = to_tf32(__expf(sacc[nt][2] - mx1));
        const float p3 = to_tf32(__expf(sacc[nt][3] - mx1));
        sacc[nt][0] = p0; sacc[nt][1] = p1; sacc[nt][2] = p2; sacc[nt][3] = p3;
        rs0 += p0 + p1; rs1 += p2 + p3;
    }
    #pragma unroll
    for (int off = 1; off < 4; off <<= 1) {
        rs0 += __shfl_xor_sync(0xffffffffu, rs0, off);
        rs1 += __shfl_xor_sync(0xffffffffu, rs1, off);
    }

    #pragma unroll
    for (int nt = 0; nt < 8; nt++) {
        *(float2*)&Ps[(m0 + qr)     * DPAD + nt * 8 + 2 * qc] = make_float2(sacc[nt][0], sacc[nt][1]);
        *(float2*)&Ps[(m0 + qr + 8) * DPAD + nt * 8 + 2 * qc] = make_float2(sacc[nt][2], sacc[nt][3]);
    }
    __syncwarp();

    float oacc2[8][4];
    #pragma unroll
    for (int nt = 0; nt < 8; nt++)
        #pragma unroll
        for (int r = 0; r < 4; r++) oacc2[nt][r] = 0.f;
    tile_mma_16x64(Ps, m0, Vt, qr, qc, oacc2);

    const float i0 = 1.f / lL[0], i1 = 1.f / lL[1];
    const float j0 = 1.f / rs0,   j1 = 1.f / rs1;
    #pragma unroll
    for (int nt = 0; nt < 8; nt++) {
        const int col = h * 64 + nt * 8 + 2 * qc;
        const int r0 = b * TSEQ + row0 + m0 + qr;
        *(__half2*)(out + (size_t)r0 * CDIM + col) =
            __floats2half2_rn(oacc[nt][0] * i0 + oacc2[nt][0] * j0,
                              oacc[nt][1] * i0 + oacc2[nt][1] * j0);
        *(__half2*)(out + (size_t)(r0 + 8) * CDIM + col) =
            __floats2half2_rn(oacc[nt][2] * i1 + oacc2[nt][2] * j1,
                              oacc[nt][3] * i1 + oacc2[nt][3] * j1);
    }
}

// ---------------- launch ----------------
extern "C" void kernel_launch(void* const* d_in, const int* in_sizes, int n_in,
                              void* d_out, int out_size)
{
    const float* x      = (const float*)d_in[0];
    const float* memory = (const float*)d_in[1];
    const float* ln1_g  = (const float*)d_in[2];
    const float* ln1_b  = (const float*)d_in[3];
    const float* w_qkv  = (const float*)d_in[4];
    const float* b_qkv  = (const float*)d_in[5];
    const float* w_out  = (const float*)d_in[6];
    const float* b_out  = (const float*)d_in[7];
    const float* w_mem  = (const float*)d_in[8];
    const float* b_mem  = (const float*)d_in[9];
    const float* ln2_g  = (const float*)d_in[10];
    const float* ln2_b  = (const float*)d_in[11];
    const float* w_fc1  = (const float*)d_in[12];
    const float* b_fc1  = (const float*)d_in[13];
    const float* w_fc2  = (const float*)d_in[14];
    const float* b_fc2  = (const float*)d_in[15];
    float* out = (float*)d_out;

    __half *pH, *pATTN, *pH2, *pHID, *pWQKVT, *pWOUTT, *pWFC1T, *pWFC2T;
    float *pQKV, *pMEMP, *pX1;
    cudaGetSymbolAddress((void**)&pH,     g_H);
    cudaGetSymbolAddress((void**)&pQKV,   g_QKV);
    cudaGetSymbolAddress((void**)&pMEMP,  g_MEMP);
    cudaGetSymbolAddress((void**)&pATTN,  g_ATTN);
    cudaGetSymbolAddress((void**)&pX1,    g_X1);
    cudaGetSymbolAddress((void**)&pH2,    g_H2);
    cudaGetSymbolAddress((void**)&pHID,   g_HID);
    cudaGetSymbolAddress((void**)&pWQKVT, g_WQKVT);
    cudaGetSymbolAddress((void**)&pWOUTT, g_WOUTT);
    cudaGetSymbolAddress((void**)&pWFC1T, g_WFC1T);
    cudaGetSymbolAddress((void**)&pWFC2T, g_WFC2T);

    cudaFuncSetAttribute(attn_mma, cudaFuncAttributeMaxDynamicSharedMemorySize, ATTN_SMEM);
    cudaFuncSetAttribute(gemm_mma<0, float>,  cudaFuncAttributeMaxDynamicSharedMemorySize, GSMEM_BYTES);
    cudaFuncSetAttribute(gemm_mma<1, float>,  cudaFuncAttributeMaxDynamicSharedMemorySize, GSMEM_BYTES);
    cudaFuncSetAttribute(gemm_mma<2, __half>, cudaFuncAttributeMaxDynamicSharedMemorySize, GSMEM_BYTES);

    const int ROWS = BATCH * TSEQ;  // 4096

    transpose_h<<<dim3(3 * CDIM / 32, CDIM / 32), 256>>>(w_qkv, pWQKVT, CDIM, 3 * CDIM);
    transpose_h<<<dim3(CDIM / 32, CDIM / 32), 256>>>(w_out, pWOUTT, CDIM, CDIM);
    transpose_h<<<dim3(HIDDEN / 32, CDIM / 32), 256>>>(w_fc1, pWFC1T, CDIM, HIDDEN);
    transpose_h<<<dim3(CDIM / 32, HIDDEN / 32), 256>>>(w_fc2, pWFC2T, HIDDEN, CDIM);

    ln_kernel<<<ROWS, 256>>>(x, ln1_g, ln1_b, pH);
    memproj_kernel<<<CDIM / 64, 256>>>(memory, w_mem, b_mem, pMEMP);

    gemm_mma<0, float><<<dim3(3 * CDIM / 128, ROWS / 128), 256, GSMEM_BYTES>>>(
        pH, pWQKVT, b_qkv, nullptr, pQKV, ROWS, 3 * CDIM, CDIM);

    attn_mma<<<dim3(TSEQ / QT, NHEAD, BATCH), 256, ATTN_SMEM>>>(pQKV, pMEMP, pATTN);

    gemm_mma<1, float><<<dim3(CDIM / 128, ROWS / 128), 256, GSMEM_BYTES>>>(
        pATTN, pWOUTT, b_out, x, pX1, ROWS, CDIM, CDIM);

    ln_kernel<<<ROWS, 256>>>(pX1, ln2_g, ln2_b, pH2);

    gemm_mma<2, __half><<<dim3(HIDDEN / 128, ROWS / 128), 256, GSMEM_BYTES>>>(
        pH2, pWFC1T, b_fc1, nullptr, pHID, ROWS, HIDDEN, CDIM);

    gemm_mma<1, float><<<dim3(CDIM / 128, ROWS / 128), 256, GSMEM_BYTES>>>(
        pHID, pWFC2T, b_fc2, pX1, out, ROWS, CDIM, HIDDEN);
}

// round 7
// speedup vs baseline: 4.6681x; 1.1684x over previous
#include <cuda_runtime.h>
#include <cuda_fp16.h>
#include <math.h>
#include <stdint.h>

#define CDIM   1024
#define TSEQ   2048
#define BATCH  2
#define NHEAD  16
#define HDIM   64
#define MMEM   64
#define HIDDEN 4096

// ---------------- scratch (device globals; no allocation) ----------------
__device__ __half g_H    [BATCH*TSEQ*CDIM];      // LN1 out (half)
__device__ __half g_QKV  [BATCH*TSEQ*3*CDIM];    // qkv (half)
__device__ __half g_MEMP [MMEM*CDIM];            // projected memory (half)
__device__ __half g_ATTN [BATCH*TSEQ*CDIM];      // attention out (half)
__device__ float  g_X1   [BATCH*TSEQ*CDIM];      // residual stream (fp32)
__device__ __half g_H2   [BATCH*TSEQ*CDIM];      // LN2 out (half)
__device__ __half g_HID  [BATCH*TSEQ*HIDDEN];    // fc1 out (half)
__device__ __half g_WQKVT[3*CDIM*CDIM];
__device__ __half g_WOUTT[CDIM*CDIM];
__device__ __half g_WFC1T[HIDDEN*CDIM];
__device__ __half g_WFC2T[CDIM*HIDDEN];

__device__ __forceinline__ uint32_t smem_u32(const void* p) {
    uint32_t a;
    asm("{ .reg .u64 t; cvta.to.shared.u64 t, %1; cvt.u32.u64 %0, t; }" : "=r"(a) : "l"(p));
    return a;
}
__device__ __forceinline__ void cp16(uint32_t dst, const void* src) {
    asm volatile("cp.async.cg.shared.global [%0], [%1], 16;" :: "r"(dst), "l"(src));
}
__device__ __forceinline__ void mma_f16(float* c, uint32_t a0, uint32_t a1,
                                        uint32_t a2, uint32_t a3,
                                        uint32_t b0, uint32_t b1)
{
    asm volatile(
        "mma.sync.aligned.m16n8k16.row.col.f32.f16.f16.f32 "
        "{%0,%1,%2,%3}, {%4,%5,%6,%7}, {%8,%9}, {%0,%1,%2,%3};"
        : "+f"(c[0]), "+f"(c[1]), "+f"(c[2]), "+f"(c[3])
        : "r"(a0), "r"(a1), "r"(a2), "r"(a3), "r"(b0), "r"(b1));
}

// ---------------- LayerNorm (half output) ----------------
__global__ __launch_bounds__(256)
void ln_kernel(const float* __restrict__ x, const float* __restrict__ g,
               const float* __restrict__ b, __half* __restrict__ y)
{
    __shared__ float red[18];
    const int row = blockIdx.x;
    const int tid = threadIdx.x;
    const float4 v = ((const float4*)(x + (size_t)row * CDIM))[tid];
    float s  = v.x + v.y + v.z + v.w;
    float ss = v.x*v.x + v.y*v.y + v.z*v.z + v.w*v.w;
    #pragma unroll
    for (int off = 16; off; off >>= 1) {
        s  += __shfl_xor_sync(0xffffffffu, s,  off);
        ss += __shfl_xor_sync(0xffffffffu, ss, off);
    }
    if ((tid & 31) == 0) { red[tid >> 5] = s; red[8 + (tid >> 5)] = ss; }
    __syncthreads();
    if (tid == 0) {
        float ts = 0.f, tss = 0.f;
        #pragma unroll
        for (int w = 0; w < 8; w++) { ts += red[w]; tss += red[8 + w]; }
        red[16] = ts; red[17] = tss;
    }
    __syncthreads();
    const float mu  = red[16] * (1.f / CDIM);
    const float var = red[17] * (1.f / CDIM) - mu * mu;
    const float inv = rsqrtf(var + 1e-5f);
    const float4 gv = ((const float4*)g)[tid];
    const float4 bv = ((const float4*)b)[tid];
    __half2 h01 = __floats2half2_rn((v.x - mu) * inv * gv.x + bv.x,
                                    (v.y - mu) * inv * gv.y + bv.y);
    __half2 h23 = __floats2half2_rn((v.z - mu) * inv * gv.z + bv.z,
                                    (v.w - mu) * inv * gv.w + bv.w);
    __half2* yp = (__half2*)(y + (size_t)row * CDIM + tid * 4);
    yp[0] = h01; yp[1] = h23;
}

// ---------------- weight transpose + half convert ----------------
__global__ __launch_bounds__(256)
void transpose_h(const float* __restrict__ S, __half* __restrict__ D, int K, int N)
{
    __shared__ float t[32][33];
    const int bx = blockIdx.x * 32;
    const int by = blockIdx.y * 32;
    const int x = threadIdx.x & 31, y = threadIdx.x >> 5;
    #pragma unroll
    for (int i = 0; i < 32; i += 8)
        t[y + i][x] = S[(size_t)(by + y + i) * N + bx + x];
    __syncthreads();
    #pragma unroll
    for (int i = 0; i < 32; i += 8)
        D[(size_t)(bx + y + i) * K + by + x] = __float2half_rn(t[x][y + i]);
}

// ---------------- fp16 mma.sync GEMM, cp.async double-buffered (R6-proven) ----------------
#define SKEWH 40
#define GST   (128 * SKEWH)
#define GSMEM_BYTES (4 * GST * 2)

template<int EPI, typename TOut>
__global__ __launch_bounds__(256, 2)
void gemm_mma(const __half* __restrict__ A, const __half* __restrict__ Bt,
              const float* __restrict__ bias, const float* __restrict__ res,
              TOut* __restrict__ C, int M, int N, int K)
{
    extern __shared__ __half sgm[];
    const uint32_t sAa = smem_u32(sgm);
    const uint32_t sBa = sAa + 2u * GST * 2u;

    const int tid = threadIdx.x;
    const int wid = tid >> 5, lane = tid & 31;
    const int wm = (wid & 1) * 64;
    const int wn = (wid >> 1) * 32;
    const int bm = blockIdx.y * 128;
    const int bn = blockIdx.x * 128;

    const int lrow = tid >> 2;
    const int lcol = (tid & 3) << 3;
    const __half* Ap = A  + (size_t)(bm + lrow) * K + lcol;
    const __half* Bp = Bt + (size_t)(bn + lrow) * K + lcol;
    const uint32_t soff = ((uint32_t)lrow * SKEWH + (uint32_t)lcol) * 2u;

    const int qr = lane >> 2;
    const int qc = lane & 3;
    const int nchunk = K / 32;

    float acc[4][4][4];
    #pragma unroll
    for (int i = 0; i < 4; i++)
        #pragma unroll
        for (int j = 0; j < 4; j++)
            #pragma unroll
            for (int r = 0; r < 4; r++) acc[i][j][r] = 0.f;

    {
        #pragma unroll
        for (int p = 0; p < 2; p++) {
            cp16(sAa + soff + p * 64 * SKEWH * 2, Ap + (size_t)(p * 64) * K);
            cp16(sBa + soff + p * 64 * SKEWH * 2, Bp + (size_t)(p * 64) * K);
        }
        asm volatile("cp.async.commit_group;");
    }

    for (int ch = 0; ch < nchunk; ch++) {
        if (ch + 1 < nchunk) {
            const int sn = (ch + 1) & 1;
            const int k0 = (ch + 1) * 32;
            #pragma unroll
            for (int p = 0; p < 2; p++) {
                cp16(sAa + (uint32_t)sn * GST * 2u + soff + p * 64 * SKEWH * 2,
                     Ap + (size_t)(p * 64) * K + k0);
                cp16(sBa + (uint32_t)sn * GST * 2u + soff + p * 64 * SKEWH * 2,
                     Bp + (size_t)(p * 64) * K + k0);
            }
        }
        asm volatile("cp.async.commit_group;");
        asm volatile("cp.async.wait_group 1;");
        __syncthreads();

        const int st = ch & 1;
        const __half* Asm = sgm + (size_t)st * GST;
        const __half* Bsm = sgm + (size_t)(2 + st) * GST;

        #pragma unroll
        for (int ks = 0; ks < 2; ks++) {
            const int kk = ks * 16;
            uint32_t bf[4][2];
            #pragma unroll
            for (int nt = 0; nt < 4; nt++) {
                const int n0 = wn + nt * 8 + qr;
                bf[nt][0] = *(const uint32_t*)&Bsm[n0 * SKEWH + kk + 2 * qc];
                bf[nt][1] = *(const uint32_t*)&Bsm[n0 * SKEWH + kk + 8 + 2 * qc];
            }
            #pragma unroll
            for (int mt = 0; mt < 4; mt++) {
                const int m0 = wm + mt * 16 + qr;
                const uint32_t a0 = *(const uint32_t*)&Asm[m0 * SKEWH + kk + 2 * qc];
                const uint32_t a1 = *(const uint32_t*)&Asm[(m0 + 8) * SKEWH + kk + 2 * qc];
                const uint32_t a2 = *(const uint32_t*)&Asm[m0 * SKEWH + kk + 8 + 2 * qc];
                const uint32_t a3 = *(const uint32_t*)&Asm[(m0 + 8) * SKEWH + kk + 8 + 2 * qc];
                #pragma unroll
                for (int nt = 0; nt < 4; nt++)
                    mma_f16(acc[mt][nt], a0, a1, a2, a3, bf[nt][0], bf[nt][1]);
            }
        }
        __syncthreads();
    }

    #pragma unroll
    for (int mt = 0; mt < 4; mt++) {
        #pragma unroll
        for (int half_ = 0; half_ < 2; half_++) {
            const int row = bm + wm + mt * 16 + qr + half_ * 8;
            const float* Rrow = res + (size_t)row * N;
            #pragma unroll
            for (int nt = 0; nt < 4; nt++) {
                const int col = bn + wn + nt * 8 + qc * 2;
                float v0 = acc[mt][nt][half_ * 2 + 0] + bias[col];
                float v1 = acc[mt][nt][half_ * 2 + 1] + bias[col + 1];
                if (EPI == 1) {
                    const float2 rv = *(const float2*)(Rrow + col);
                    v0 += rv.x; v1 += rv.y;
                }
                if (EPI == 2) {
                    v0 = 0.5f * v0 * (1.0f + erff(v0 * 0.70710678118654752f));
                    v1 = 0.5f * v1 * (1.0f + erff(v1 * 0.70710678118654752f));
                }
                TOut* Crow = C + (size_t)row * N;
                if (sizeof(TOut) == 2) {
                    *(__half2*)((__half*)Crow + col) = __floats2half2_rn(v0, v1);
                } else {
                    *(float2*)((float*)Crow + col) = make_float2(v0, v1);
                }
            }
        }
    }
}

// ---------------- memory projection -> half output ----------------
__global__ __launch_bounds__(256)
void memproj_kernel(const float* __restrict__ A, const float* __restrict__ B,
                    const float* __restrict__ bias, __half* __restrict__ C)
{
    __shared__ float Ast[16][64];
    __shared__ float Bs [16][64];
    const int tid = threadIdx.x;
    const int tx = tid & 15, ty = tid >> 4;
    const int bn = blockIdx.x * 64;
    const int ar = tid >> 2, ak = (tid & 3) << 2;
    const int bk = tid >> 4, bc = (tid & 15) << 2;

    float acc[4][4];
    #pragma unroll
    for (int i = 0; i < 4; i++)
        #pragma unroll
        for (int j = 0; j < 4; j++) acc[i][j] = 0.f;

    for (int k0 = 0; k0 < CDIM; k0 += 16) {
        const float4 av = *(const float4*)(A + (size_t)ar * CDIM + k0 + ak);
        const float4 bv = *(const float4*)(B + (size_t)(k0 + bk) * CDIM + bn + bc);
        __syncthreads();
        Ast[ak + 0][ar] = av.x;
        Ast[ak + 1][ar] = av.y;
        Ast[ak + 2][ar] = av.z;
        Ast[ak + 3][ar] = av.w;
        *(float4*)&Bs[bk][bc] = bv;
        __syncthreads();
        #pragma unroll
        for (int kk = 0; kk < 16; kk++) {
            const float4 a = *(const float4*)&Ast[kk][ty * 4];
            const float4 b = *(const float4*)&Bs[kk][tx * 4];
            const float arr[4] = {a.x, a.y, a.z, a.w};
            const float brr[4] = {b.x, b.y, b.z, b.w};
            #pragma unroll
            for (int i = 0; i < 4; i++)
                #pragma unroll
                for (int j = 0; j < 4; j++)
                    acc[i][j] = fmaf(arr[i], brr[j], acc[i][j]);
        }
    }
    #pragma unroll
    for (int i = 0; i < 4; i++) {
        const int col = bn + tx * 4;
        const float4 bsv = *(const float4*)(bias + col);
        __half2* cp = (__half2*)(C + (size_t)(ty * 4 + i) * CDIM + col);
        cp[0] = __floats2half2_rn(acc[i][0] + bsv.x, acc[i][1] + bsv.y);
        cp[1] = __floats2half2_rn(acc[i][2] + bsv.z, acc[i][3] + bsv.w);
    }
}

// ---------------- fp16 mma attention ----------------
#define QT   128
#define KC   64
#define DPH  72     // half elements per row (144 B = 9 x 16 B)

// smem halfs: Qsh[128][72] | Ksh[64][72] | Vth[64][72] | Psh[128][72]
#define ATTN_SMEM ((128*DPH + 64*DPH + 64*DPH + 128*DPH) * 2)

// load K chunk [64 rows x 64 halfs] + V chunk transposed, from half source
__device__ __forceinline__ void load_kv_h(const __half* __restrict__ kbase,
                                          const __half* __restrict__ vbase,
                                          size_t rstride, __half* Ksh, __half* Vth, int tid)
{
    const int r  = tid >> 2;
    const int c0 = (tid & 3) * 16;
    // K: straight copy, 16B chunks (dst 16B-aligned: r*144 + c0*2 with c0 in {0,16,32,48})
    {
        const uint4* kp = (const uint4*)(kbase + (size_t)r * rstride + c0);
        uint4* kd = (uint4*)&Ksh[r * DPH + c0];
        kd[0] = kp[0]; kd[1] = kp[1];
    }
    // V: transpose (row=key -> col), scalar half stores (same-word byte-merge ok)
    {
        const __half* vp = vbase + (size_t)r * rstride + c0;
        #pragma unroll
        for (int j = 0; j < 16; j++)
            Vth[(c0 + j) * DPH + r] = vp[j];
    }
}

// acc[16x64] += A[16 rows x 64k] @ B[64n x 64k]^T, half operands
__device__ __forceinline__ void tile_mma_16x64h(const __half* __restrict__ Asm, int m0,
                                                const __half* __restrict__ Bsm,
                                                int qr, int qc, float acc[8][4])
{
    #pragma unroll
    for (int ks = 0; ks < 4; ks++) {
        const int kk = ks * 16;
        const uint32_t a0 = *(const uint32_t*)&Asm[(m0 + qr)     * DPH + kk + 2 * qc];
        const uint32_t a1 = *(const uint32_t*)&Asm[(m0 + qr + 8) * DPH + kk + 2 * qc];
        const uint32_t a2 = *(const uint32_t*)&Asm[(m0 + qr)     * DPH + kk + 8 + 2 * qc];
        const uint32_t a3 = *(const uint32_t*)&Asm[(m0 + qr + 8) * DPH + kk + 8 + 2 * qc];
        #pragma unroll
        for (int nt = 0; nt < 8; nt++) {
            const uint32_t b0 = *(const uint32_t*)&Bsm[(nt * 8 + qr) * DPH + kk + 2 * qc];
            const uint32_t b1 = *(const uint32_t*)&Bsm[(nt * 8 + qr) * DPH + kk + 8 + 2 * qc];
            mma_f16(acc[nt], a0, a1, a2, a3, b0, b1);
        }
    }
}

__global__ __launch_bounds__(256)
void attn_mma(const __half* __restrict__ qkv, const __half* __restrict__ memp,
              __half* __restrict__ out)
{
    extern __shared__ __half smh[];
    __half* Qsh = smh;
    __half* Ksh = smh + 128 * DPH;
    __half* Vth = Ksh + 64 * DPH;
    __half* Psh = Vth + 64 * DPH;

    const int tid  = threadIdx.x;
    const int wid  = tid >> 5, lane = tid & 31;
    const int qr   = lane >> 2, qc = lane & 3;
    const int m0   = wid * 16;
    const int h    = blockIdx.y, b = blockIdx.z;
    const int row0 = blockIdx.x * QT;

    // Q load: 128 rows x 64 halfs, scaled by 0.125 (exact in fp16)
    {
        const int r  = tid >> 1;
        const int c0 = (tid & 1) * 32;
        const __half2 sc = __float2half2_rn(0.125f);
        const __half2* qp = (const __half2*)(qkv + ((size_t)(b * TSEQ + row0 + r)) * (3 * CDIM) + h * 64 + c0);
        __half2* qd = (__half2*)&Qsh[r * DPH + c0];
        #pragma unroll
        for (int j = 0; j < 16; j++)
            qd[j] = __hmul2(qp[j], sc);
    }

    float mM[2] = {-1e30f, -1e30f};
    float lL[2] = {0.f, 0.f};
    float oacc[8][4];
    #pragma unroll
    for (int nt = 0; nt < 8; nt++)
        #pragma unroll
        for (int r = 0; r < 4; r++) oacc[nt][r] = 0.f;

    for (int kc = 0; kc < TSEQ; kc += KC) {
        __syncthreads();
        load_kv_h(qkv + ((size_t)(b * TSEQ + kc)) * (3 * CDIM) + CDIM + h * 64,
                  qkv + ((size_t)(b * TSEQ + kc)) * (3 * CDIM) + 2 * CDIM + h * 64,
                  3 * CDIM, Ksh, Vth, tid);
        __syncthreads();

        float sacc[8][4];
        #pragma unroll
        for (int nt = 0; nt < 8; nt++)
            #pragma unroll
            for (int r = 0; r < 4; r++) sacc[nt][r] = 0.f;
        tile_mma_16x64h(Qsh, m0, Ksh, qr, qc, sacc);

        float mx0 = -1e30f, mx1 = -1e30f;
        #pragma unroll
        for (int nt = 0; nt < 8; nt++) {
            mx0 = fmaxf(mx0, fmaxf(sacc[nt][0], sacc[nt][1]));
            mx1 = fmaxf(mx1, fmaxf(sacc[nt][2], sacc[nt][3]));
        }
        #pragma unroll
        for (int off = 1; off < 4; off <<= 1) {
            mx0 = fmaxf(mx0, __shfl_xor_sync(0xffffffffu, mx0, off));
            mx1 = fmaxf(mx1, __shfl_xor_sync(0xffffffffu, mx1, off));
        }
        const float mn0 = fmaxf(mM[0], mx0);
        const float mn1 = fmaxf(mM[1], mx1);
        const float f0 = __expf(mM[0] - mn0);
        const float f1 = __expf(mM[1] - mn1);
        mM[0] = mn0; mM[1] = mn1;

        // P -> half (rounded BEFORE row-sum for numerator/denominator consistency)
        float rs0 = 0.f, rs1 = 0.f;
        #pragma unroll
        for (int nt = 0; nt < 8; nt++) {
            const __half2 p01 = __floats2half2_rn(__expf(sacc[nt][0] - mn0),
                                                  __expf(sacc[nt][1] - mn0));
            const __half2 p23 = __floats2half2_rn(__expf(sacc[nt][2] - mn1),
                                                  __expf(sacc[nt][3] - mn1));
            *(__half2*)&Psh[(m0 + qr)     * DPH + nt * 8 + 2 * qc] = p01;
            *(__half2*)&Psh[(m0 + qr + 8) * DPH + nt * 8 + 2 * qc] = p23;
            const float2 f01 = __half22float2(p01);
            const float2 f23 = __half22float2(p23);
            rs0 += f01.x + f01.y; rs1 += f23.x + f23.y;
        }
        #pragma unroll
        for (int off = 1; off < 4; off <<= 1) {
            rs0 += __shfl_xor_sync(0xffffffffu, rs0, off);
            rs1 += __shfl_xor_sync(0xffffffffu, rs1, off);
        }
        lL[0] = lL[0] * f0 + rs0;
        lL[1] = lL[1] * f1 + rs1;
        #pragma unroll
        for (int nt = 0; nt < 8; nt++) {
            oacc[nt][0] *= f0; oacc[nt][1] *= f0;
            oacc[nt][2] *= f1; oacc[nt][3] *= f1;
        }
        __syncwarp();

        tile_mma_16x64h(Psh, m0, Vth, qr, qc, oacc);
    }

    // ---- compressive memory attention (one chunk, independent softmax) ----
    __syncthreads();
    load_kv_h(memp + h * 64, memp + h * 64, CDIM, Ksh, Vth, tid);
    __syncthreads();

    float sacc[8][4];
    #pragma unroll
    for (int nt = 0; nt < 8; nt++)
        #pragma unroll
        for (int r = 0; r < 4; r++) sacc[nt][r] = 0.f;
    tile_mma_16x64h(Qsh, m0, Ksh, qr, qc, sacc);

    float mx0 = -1e30f, mx1 = -1e30f;
    #pragma unroll
    for (int nt = 0; nt < 8; nt++) {
        mx0 = fmaxf(mx0, fmaxf(sacc[nt][0], sacc[nt][1]));
        mx1 = fmaxf(mx1, fmaxf(sacc[nt][2], sacc[nt][3]));
    }
    #pragma unroll
    for (int off = 1; off < 4; off <<= 1) {
        mx0 = fmaxf(mx0, __shfl_xor_sync(0xffffffffu, mx0, off));
        mx1 = fmaxf(mx1, __shfl_xor_sync(0xffffffffu, mx1, off));
    }
    float rs0 = 0.f, rs1 = 0.f;
    #pragma unroll
    for (int nt = 0; nt < 8; nt++) {
        const __half2 p01 = __floats2half2_rn(__expf(sacc[nt][0] - mx0),
                                              __expf(sacc[nt][1] - mx0));
        const __half2 p23 = __floats2half2_rn(__expf(sacc[nt][2] - mx1),
                                              __expf(sacc[nt][3] - mx1));
        *(__half2*)&Psh[(m0 + qr)     * DPH + nt * 8 + 2 * qc] = p01;
        *(__half2*)&Psh[(m0 + qr + 8) * DPH + nt * 8 + 2 * qc] = p23;
        const float2 f01 = __half22float2(p01);
        const float2 f23 = __half22float2(p23);
        rs0 += f01.x + f01.y; rs1 += f23.x + f23.y;
    }
    #pragma unroll
    for (int off = 1; off < 4; off <<= 1) {
        rs0 += __shfl_xor_sync(0xffffffffu, rs0, off);
        rs1 += __shfl_xor_sync(0xffffffffu, rs1, off);
    }
    __syncwarp();

    float oacc2[8][4];
    #pragma unroll
    for (int nt = 0; nt < 8; nt++)
        #pragma unroll
        for (int r = 0; r < 4; r++) oacc2[nt][r] = 0.f;
    tile_mma_16x64h(Psh, m0, Vth, qr, qc, oacc2);

    const float i0 = 1.f / lL[0], i1 = 1.f / lL[1];
    const float j0 = 1.f / rs0,   j1 = 1.f / rs1;
    #pragma unroll
    for (int nt = 0; nt < 8; nt++) {
        const int col = h * 64 + nt * 8 + 2 * qc;
        const int r0 = b * TSEQ + row0 + m0 + qr;
        *(__half2*)(out + (size_t)r0 * CDIM + col) =
            __floats2half2_rn(oacc[nt][0] * i0 + oacc2[nt][0] * j0,
                              oacc[nt][1] * i0 + oacc2[nt][1] * j0);
        *(__half2*)(out + (size_t)(r0 + 8) * CDIM + col) =
            __floats2half2_rn(oacc[nt][2] * i1 + oacc2[nt][2] * j1,
                              oacc[nt][3] * i1 + oacc2[nt][3] * j1);
    }
}

// ---------------- launch ----------------
extern "C" void kernel_launch(void* const* d_in, const int* in_sizes, int n_in,
                              void* d_out, int out_size)
{
    const float* x      = (const float*)d_in[0];
    const float* memory = (const float*)d_in[1];
    const float* ln1_g  = (const float*)d_in[2];
    const float* ln1_b  = (const float*)d_in[3];
    const float* w_qkv  = (const float*)d_in[4];
    const float* b_qkv  = (const float*)d_in[5];
    const float* w_out  = (const float*)d_in[6];
    const float* b_out  = (const float*)d_in[7];
    const float* w_mem  = (const float*)d_in[8];
    const float* b_mem  = (const float*)d_in[9];
    const float* ln2_g  = (const float*)d_in[10];
    const float* ln2_b  = (const float*)d_in[11];
    const float* w_fc1  = (const float*)d_in[12];
    const float* b_fc1  = (const float*)d_in[13];
    const float* w_fc2  = (const float*)d_in[14];
    const float* b_fc2  = (const float*)d_in[15];
    float* out = (float*)d_out;

    __half *pH, *pQKV, *pMEMP, *pATTN, *pH2, *pHID;
    __half *pWQKVT, *pWOUTT, *pWFC1T, *pWFC2T;
    float *pX1;
    cudaGetSymbolAddress((void**)&pH,     g_H);
    cudaGetSymbolAddress((void**)&pQKV,   g_QKV);
    cudaGetSymbolAddress((void**)&pMEMP,  g_MEMP);
    cudaGetSymbolAddress((void**)&pATTN,  g_ATTN);
    cudaGetSymbolAddress((void**)&pX1,    g_X1);
    cudaGetSymbolAddress((void**)&pH2,    g_H2);
    cudaGetSymbolAddress((void**)&pHID,   g_HID);
    cudaGetSymbolAddress((void**)&pWQKVT, g_WQKVT);
    cudaGetSymbolAddress((void**)&pWOUTT, g_WOUTT);
    cudaGetSymbolAddress((void**)&pWFC1T, g_WFC1T);
    cudaGetSymbolAddress((void**)&pWFC2T, g_WFC2T);

    cudaFuncSetAttribute(attn_mma, cudaFuncAttributeMaxDynamicSharedMemorySize, ATTN_SMEM);
    cudaFuncSetAttribute(gemm_mma<0, __half>, cudaFuncAttributeMaxDynamicSharedMemorySize, GSMEM_BYTES);
    cudaFuncSetAttribute(gemm_mma<1, float>,  cudaFuncAttributeMaxDynamicSharedMemorySize, GSMEM_BYTES);
    cudaFuncSetAttribute(gemm_mma<2, __half>, cudaFuncAttributeMaxDynamicSharedMemorySize, GSMEM_BYTES);

    const int ROWS = BATCH * TSEQ;  // 4096

    transpose_h<<<dim3(3 * CDIM / 32, CDIM / 32), 256>>>(w_qkv, pWQKVT, CDIM, 3 * CDIM);
    transpose_h<<<dim3(CDIM / 32, CDIM / 32), 256>>>(w_out, pWOUTT, CDIM, CDIM);
    transpose_h<<<dim3(HIDDEN / 32, CDIM / 32), 256>>>(w_fc1, pWFC1T, CDIM, HIDDEN);
    transpose_h<<<dim3(CDIM / 32, HIDDEN / 32), 256>>>(w_fc2, pWFC2T, HIDDEN, CDIM);

    ln_kernel<<<ROWS, 256>>>(x, ln1_g, ln1_b, pH);
    memproj_kernel<<<CDIM / 64, 256>>>(memory, w_mem, b_mem, pMEMP);

    gemm_mma<0, __half><<<dim3(3 * CDIM / 128, ROWS / 128), 256, GSMEM_BYTES>>>(
        pH, pWQKVT, b_qkv, nullptr, pQKV, ROWS, 3 * CDIM, CDIM);

    attn_mma<<<dim3(TSEQ / QT, NHEAD, BATCH), 256, ATTN_SMEM>>>(pQKV, pMEMP, pATTN);

    gemm_mma<1, float><<<dim3(CDIM / 128, ROWS / 128), 256, GSMEM_BYTES>>>(
        pATTN, pWOUTT, b_out, x, pX1, ROWS, CDIM, CDIM);

    ln_kernel<<<ROWS, 256>>>(pX1, ln2_g, ln2_b, pH2);

    gemm_mma<2, __half><<<dim3(HIDDEN / 128, ROWS / 128), 256, GSMEM_BYTES>>>(
        pH2, pWFC1T, b_fc1, nullptr, pHID, ROWS, HIDDEN, CDIM);

    gemm_mma<1, float><<<dim3(CDIM / 128, ROWS / 128), 256, GSMEM_BYTES>>>(
        pHID, pWFC2T, b_fc2, pX1, out, ROWS, CDIM, HIDDEN);
}

// round 8
// speedup vs baseline: 5.3315x; 1.1421x over previous
#include <cuda_runtime.h>
#include <cuda_fp16.h>
#include <math.h>
#include <stdint.h>

#define CDIM   1024
#define TSEQ   2048
#define BATCH  2
#define NHEAD  16
#define HDIM   64
#define MMEM   64
#define HIDDEN 4096

// ---------------- scratch (device globals; no allocation) ----------------
__device__ __half g_H    [BATCH*TSEQ*CDIM];
__device__ __half g_QKV  [BATCH*TSEQ*3*CDIM];
__device__ __half g_MEMP [MMEM*CDIM];
__device__ __half g_ATTN [BATCH*TSEQ*CDIM];
__device__ float  g_X1   [BATCH*TSEQ*CDIM];
__device__ __half g_H2   [BATCH*TSEQ*CDIM];
__device__ __half g_HID  [BATCH*TSEQ*HIDDEN];
__device__ __half g_WQKVT[3*CDIM*CDIM];
__device__ __half g_WOUTT[CDIM*CDIM];
__device__ __half g_WFC1T[HIDDEN*CDIM];
__device__ __half g_WFC2T[CDIM*HIDDEN];

__device__ __forceinline__ uint32_t smem_u32(const void* p) {
    uint32_t a;
    asm("{ .reg .u64 t; cvta.to.shared.u64 t, %1; cvt.u32.u64 %0, t; }" : "=r"(a) : "l"(p));
    return a;
}
__device__ __forceinline__ void cp16(uint32_t dst, const void* src) {
    asm volatile("cp.async.cg.shared.global [%0], [%1], 16;" :: "r"(dst), "l"(src));
}
__device__ __forceinline__ void mma_f16(float* c, uint32_t a0, uint32_t a1,
                                        uint32_t a2, uint32_t a3,
                                        uint32_t b0, uint32_t b1)
{
    asm volatile(
        "mma.sync.aligned.m16n8k16.row.col.f32.f16.f16.f32 "
        "{%0,%1,%2,%3}, {%4,%5,%6,%7}, {%8,%9}, {%0,%1,%2,%3};"
        : "+f"(c[0]), "+f"(c[1]), "+f"(c[2]), "+f"(c[3])
        : "r"(a0), "r"(a1), "r"(a2), "r"(a3), "r"(b0), "r"(b1));
}
__device__ __forceinline__ void ldsm4(uint32_t* r, uint32_t addr) {
    asm volatile("ldmatrix.sync.aligned.m8n8.x4.shared.b16 {%0,%1,%2,%3}, [%4];"
        : "=r"(r[0]), "=r"(r[1]), "=r"(r[2]), "=r"(r[3]) : "r"(addr));
}

// ---------------- LayerNorm (half output) ----------------
__global__ __launch_bounds__(256)
void ln_kernel(const float* __restrict__ x, const float* __restrict__ g,
               const float* __restrict__ b, __half* __restrict__ y)
{
    __shared__ float red[18];
    const int row = blockIdx.x;
    const int tid = threadIdx.x;
    const float4 v = ((const float4*)(x + (size_t)row * CDIM))[tid];
    float s  = v.x + v.y + v.z + v.w;
    float ss = v.x*v.x + v.y*v.y + v.z*v.z + v.w*v.w;
    #pragma unroll
    for (int off = 16; off; off >>= 1) {
        s  += __shfl_xor_sync(0xffffffffu, s,  off);
        ss += __shfl_xor_sync(0xffffffffu, ss, off);
    }
    if ((tid & 31) == 0) { red[tid >> 5] = s; red[8 + (tid >> 5)] = ss; }
    __syncthreads();
    if (tid == 0) {
        float ts = 0.f, tss = 0.f;
        #pragma unroll
        for (int w = 0; w < 8; w++) { ts += red[w]; tss += red[8 + w]; }
        red[16] = ts; red[17] = tss;
    }
    __syncthreads();
    const float mu  = red[16] * (1.f / CDIM);
    const float var = red[17] * (1.f / CDIM) - mu * mu;
    const float inv = rsqrtf(var + 1e-5f);
    const float4 gv = ((const float4*)g)[tid];
    const float4 bv = ((const float4*)b)[tid];
    __half2 h01 = __floats2half2_rn((v.x - mu) * inv * gv.x + bv.x,
                                    (v.y - mu) * inv * gv.y + bv.y);
    __half2 h23 = __floats2half2_rn((v.z - mu) * inv * gv.z + bv.z,
                                    (v.w - mu) * inv * gv.w + bv.w);
    __half2* yp = (__half2*)(y + (size_t)row * CDIM + tid * 4);
    yp[0] = h01; yp[1] = h23;
}

// ---------------- weight transpose + half convert ----------------
__global__ __launch_bounds__(256)
void transpose_h(const float* __restrict__ S, __half* __restrict__ D, int K, int N)
{
    __shared__ float t[32][33];
    const int bx = blockIdx.x * 32;
    const int by = blockIdx.y * 32;
    const int x = threadIdx.x & 31, y = threadIdx.x >> 5;
    #pragma unroll
    for (int i = 0; i < 32; i += 8)
        t[y + i][x] = S[(size_t)(by + y + i) * N + bx + x];
    __syncthreads();
    #pragma unroll
    for (int i = 0; i < 32; i += 8)
        D[(size_t)(bx + y + i) * K + by + x] = __float2half_rn(t[x][y + i]);
}

// ---------------- fp16 mma GEMM, cp.async double-buffered + ldmatrix ----------------
#define SKEWH 40
#define GST   (128 * SKEWH)
#define GSMEM_BYTES (4 * GST * 2)

template<int EPI, typename TOut>
__global__ __launch_bounds__(256, 2)
void gemm_mma(const __half* __restrict__ A, const __half* __restrict__ Bt,
              const float* __restrict__ bias, const float* __restrict__ res,
              TOut* __restrict__ C, int M, int N, int K)
{
    extern __shared__ __half sgm[];
    const uint32_t sAa = smem_u32(sgm);
    const uint32_t sBa = sAa + 2u * GST * 2u;

    const int tid = threadIdx.x;
    const int wid = tid >> 5, lane = tid & 31;
    const int wm = (wid & 1) * 64;
    const int wn = (wid >> 1) * 32;
    const int bm = blockIdx.y * 128;
    const int bn = blockIdx.x * 128;

    const int lrow = tid >> 2;
    const int lcol = (tid & 3) << 3;
    const __half* Ap = A  + (size_t)(bm + lrow) * K + lcol;
    const __half* Bp = Bt + (size_t)(bn + lrow) * K + lcol;
    const uint32_t soff = ((uint32_t)lrow * SKEWH + (uint32_t)lcol) * 2u;

    const int qr = lane >> 2;
    const int qc = lane & 3;
    const int nchunk = K / 32;

    // ldmatrix per-lane base offsets (bytes)
    const int arow = lane & 15;
    const int acol = (lane >> 4) * 8;                       // halfs
    const int brow = (lane & 7) + ((lane & 16) ? 8 : 0);
    const int bcol = ((lane >> 3) & 1) * 8;                 // halfs
    const uint32_t aoffb = ((uint32_t)(wm + arow) * SKEWH + acol) * 2u;
    const uint32_t boffb = ((uint32_t)(wn + brow) * SKEWH + bcol) * 2u;

    float acc[4][4][4];
    #pragma unroll
    for (int i = 0; i < 4; i++)
        #pragma unroll
        for (int j = 0; j < 4; j++)
            #pragma unroll
            for (int r = 0; r < 4; r++) acc[i][j][r] = 0.f;

    {
        #pragma unroll
        for (int p = 0; p < 2; p++) {
            cp16(sAa + soff + p * 64 * SKEWH * 2, Ap + (size_t)(p * 64) * K);
            cp16(sBa + soff + p * 64 * SKEWH * 2, Bp + (size_t)(p * 64) * K);
        }
        asm volatile("cp.async.commit_group;");
    }

    for (int ch = 0; ch < nchunk; ch++) {
        if (ch + 1 < nchunk) {
            const int sn = (ch + 1) & 1;
            const int k0 = (ch + 1) * 32;
            #pragma unroll
            for (int p = 0; p < 2; p++) {
                cp16(sAa + (uint32_t)sn * GST * 2u + soff + p * 64 * SKEWH * 2,
                     Ap + (size_t)(p * 64) * K + k0);
                cp16(sBa + (uint32_t)sn * GST * 2u + soff + p * 64 * SKEWH * 2,
                     Bp + (size_t)(p * 64) * K + k0);
            }
        }
        asm volatile("cp.async.commit_group;");
        asm volatile("cp.async.wait_group 1;");
        __syncthreads();

        const int st = ch & 1;
        const uint32_t aB = sAa + (uint32_t)st * GST * 2u + aoffb;
        const uint32_t bB = sBa + (uint32_t)st * GST * 2u + boffb;

        #pragma unroll
        for (int ks = 0; ks < 2; ks++) {
            const uint32_t kb = ks * 32;   // 16 halfs = 32 bytes
            uint32_t bb0[4], bb1[4];
            ldsm4(bb0, bB + kb);                         // nt 0,1
            ldsm4(bb1, bB + 16u * SKEWH * 2u + kb);      // nt 2,3
            #pragma unroll
            for (int mt = 0; mt < 4; mt++) {
                uint32_t a[4];
                ldsm4(a, aB + (uint32_t)mt * 16u * SKEWH * 2u + kb);
                mma_f16(acc[mt][0], a[0], a[1], a[2], a[3], bb0[0], bb0[1]);
                mma_f16(acc[mt][1], a[0], a[1], a[2], a[3], bb0[2], bb0[3]);
                mma_f16(acc[mt][2], a[0], a[1], a[2], a[3], bb1[0], bb1[1]);
                mma_f16(acc[mt][3], a[0], a[1], a[2], a[3], bb1[2], bb1[3]);
            }
        }
        __syncthreads();
    }

    #pragma unroll
    for (int mt = 0; mt < 4; mt++) {
        #pragma unroll
        for (int half_ = 0; half_ < 2; half_++) {
            const int row = bm + wm + mt * 16 + qr + half_ * 8;
            const float* Rrow = res + (size_t)row * N;
            #pragma unroll
            for (int nt = 0; nt < 4; nt++) {
                const int col = bn + wn + nt * 8 + qc * 2;
                float v0 = acc[mt][nt][half_ * 2 + 0] + bias[col];
                float v1 = acc[mt][nt][half_ * 2 + 1] + bias[col + 1];
                if (EPI == 1) {
                    const float2 rv = *(const float2*)(Rrow + col);
                    v0 += rv.x; v1 += rv.y;
                }
                if (EPI == 2) {
                    v0 = 0.5f * v0 * (1.0f + erff(v0 * 0.70710678118654752f));
                    v1 = 0.5f * v1 * (1.0f + erff(v1 * 0.70710678118654752f));
                }
                TOut* Crow = C + (size_t)row * N;
                if (sizeof(TOut) == 2) {
                    *(__half2*)((__half*)Crow + col) = __floats2half2_rn(v0, v1);
                } else {
                    *(float2*)((float*)Crow + col) = make_float2(v0, v1);
                }
            }
        }
    }
}

// ---------------- memory projection -> half output ----------------
__global__ __launch_bounds__(256)
void memproj_kernel(const float* __restrict__ A, const float* __restrict__ B,
                    const float* __restrict__ bias, __half* __restrict__ C)
{
    __shared__ float Ast[16][64];
    __shared__ float Bs [16][64];
    const int tid = threadIdx.x;
    const int tx = tid & 15, ty = tid >> 4;
    const int bn = blockIdx.x * 64;
    const int ar = tid >> 2, ak = (tid & 3) << 2;
    const int bk = tid >> 4, bc = (tid & 15) << 2;

    float acc[4][4];
    #pragma unroll
    for (int i = 0; i < 4; i++)
        #pragma unroll
        for (int j = 0; j < 4; j++) acc[i][j] = 0.f;

    for (int k0 = 0; k0 < CDIM; k0 += 16) {
        const float4 av = *(const float4*)(A + (size_t)ar * CDIM + k0 + ak);
        const float4 bv = *(const float4*)(B + (size_t)(k0 + bk) * CDIM + bn + bc);
        __syncthreads();
        Ast[ak + 0][ar] = av.x;
        Ast[ak + 1][ar] = av.y;
        Ast[ak + 2][ar] = av.z;
        Ast[ak + 3][ar] = av.w;
        *(float4*)&Bs[bk][bc] = bv;
        __syncthreads();
        #pragma unroll
        for (int kk = 0; kk < 16; kk++) {
            const float4 a = *(const float4*)&Ast[kk][ty * 4];
            const float4 b = *(const float4*)&Bs[kk][tx * 4];
            const float arr[4] = {a.x, a.y, a.z, a.w};
            const float brr[4] = {b.x, b.y, b.z, b.w};
            #pragma unroll
            for (int i = 0; i < 4; i++)
                #pragma unroll
                for (int j = 0; j < 4; j++)
                    acc[i][j] = fmaf(arr[i], brr[j], acc[i][j]);
        }
    }
    #pragma unroll
    for (int i = 0; i < 4; i++) {
        const int col = bn + tx * 4;
        const float4 bsv = *(const float4*)(bias + col);
        __half2* cp = (__half2*)(C + (size_t)(ty * 4 + i) * CDIM + col);
        cp[0] = __floats2half2_rn(acc[i][0] + bsv.x, acc[i][1] + bsv.y);
        cp[1] = __floats2half2_rn(acc[i][2] + bsv.z, acc[i][3] + bsv.w);
    }
}

// ---------------- fp16 mma attention + ldmatrix ----------------
#define QT   128
#define KC   64
#define DPH  72
#define ATTN_SMEM ((128*DPH + 64*DPH + 64*DPH + 128*DPH) * 2)

__device__ __forceinline__ void load_kv_h(const __half* __restrict__ kbase,
                                          const __half* __restrict__ vbase,
                                          size_t rstride, __half* Ksh, __half* Vth, int tid)
{
    const int r  = tid >> 2;
    const int c0 = (tid & 3) * 16;
    {
        const uint4* kp = (const uint4*)(kbase + (size_t)r * rstride + c0);
        uint4* kd = (uint4*)&Ksh[r * DPH + c0];
        kd[0] = kp[0]; kd[1] = kp[1];
    }
    {
        const __half* vp = vbase + (size_t)r * rstride + c0;
        #pragma unroll
        for (int j = 0; j < 16; j++)
            Vth[(c0 + j) * DPH + r] = vp[j];
    }
}

// acc[16x64] += A[16 rows x 64k] @ B[64n x 64k]^T via ldmatrix fragments.
// aAddr/bAddr are per-lane smem byte addresses (see call sites).
__device__ __forceinline__ void tile_mma_16x64h(uint32_t aAddr, uint32_t bAddr,
                                                float acc[8][4])
{
    #pragma unroll
    for (int ks = 0; ks < 4; ks++) {
        const uint32_t kb = ks * 32;
        uint32_t a[4];
        ldsm4(a, aAddr + kb);
        #pragma unroll
        for (int p = 0; p < 4; p++) {
            uint32_t bb[4];
            ldsm4(bb, bAddr + (uint32_t)p * 16u * DPH * 2u + kb);
            mma_f16(acc[2 * p],     a[0], a[1], a[2], a[3], bb[0], bb[1]);
            mma_f16(acc[2 * p + 1], a[0], a[1], a[2], a[3], bb[2], bb[3]);
        }
    }
}

__global__ __launch_bounds__(256)
void attn_mma(const __half* __restrict__ qkv, const __half* __restrict__ memp,
              __half* __restrict__ out)
{
    extern __shared__ __half smh[];
    __half* Qsh = smh;
    __half* Ksh = smh + 128 * DPH;
    __half* Vth = Ksh + 64 * DPH;
    __half* Psh = Vth + 64 * DPH;

    const int tid  = threadIdx.x;
    const int wid  = tid >> 5, lane = tid & 31;
    const int qr   = lane >> 2, qc = lane & 3;
    const int m0   = wid * 16;
    const int h    = blockIdx.y, b = blockIdx.z;
    const int row0 = blockIdx.x * QT;

    // ldmatrix per-lane offsets
    const int arow = lane & 15;
    const int acol = (lane >> 4) * 8;
    const int brow = (lane & 7) + ((lane & 16) ? 8 : 0);
    const int bcol = ((lane >> 3) & 1) * 8;
    const uint32_t qAddr = smem_u32(Qsh) + ((uint32_t)(m0 + arow) * DPH + acol) * 2u;
    const uint32_t pAddr = smem_u32(Psh) + ((uint32_t)(m0 + arow) * DPH + acol) * 2u;
    const uint32_t kAddr = smem_u32(Ksh) + ((uint32_t)brow * DPH + bcol) * 2u;
    const uint32_t vAddr = smem_u32(Vth) + ((uint32_t)brow * DPH + bcol) * 2u;

    // Q load: scaled by 0.125
    {
        const int r  = tid >> 1;
        const int c0 = (tid & 1) * 32;
        const __half2 sc = __float2half2_rn(0.125f);
        const __half2* qp = (const __half2*)(qkv + ((size_t)(b * TSEQ + row0 + r)) * (3 * CDIM) + h * 64 + c0);
        __half2* qd = (__half2*)&Qsh[r * DPH + c0];
        #pragma unroll
        for (int j = 0; j < 16; j++)
            qd[j] = __hmul2(qp[j], sc);
    }

    float mM[2] = {-1e30f, -1e30f};
    float lL[2] = {0.f, 0.f};
    float oacc[8][4];
    #pragma unroll
    for (int nt = 0; nt < 8; nt++)
        #pragma unroll
        for (int r = 0; r < 4; r++) oacc[nt][r] = 0.f;

    for (int kc = 0; kc < TSEQ; kc += KC) {
        __syncthreads();
        load_kv_h(qkv + ((size_t)(b * TSEQ + kc)) * (3 * CDIM) + CDIM + h * 64,
                  qkv + ((size_t)(b * TSEQ + kc)) * (3 * CDIM) + 2 * CDIM + h * 64,
                  3 * CDIM, Ksh, Vth, tid);
        __syncthreads();

        float sacc[8][4];
        #pragma unroll
        for (int nt = 0; nt < 8; nt++)
            #pragma unroll
            for (int r = 0; r < 4; r++) sacc[nt][r] = 0.f;
        tile_mma_16x64h(qAddr, kAddr, sacc);

        float mx0 = -1e30f, mx1 = -1e30f;
        #pragma unroll
        for (int nt = 0; nt < 8; nt++) {
            mx0 = fmaxf(mx0, fmaxf(sacc[nt][0], sacc[nt][1]));
            mx1 = fmaxf(mx1, fmaxf(sacc[nt][2], sacc[nt][3]));
        }
        #pragma unroll
        for (int off = 1; off < 4; off <<= 1) {
            mx0 = fmaxf(mx0, __shfl_xor_sync(0xffffffffu, mx0, off));
            mx1 = fmaxf(mx1, __shfl_xor_sync(0xffffffffu, mx1, off));
        }
        const float mn0 = fmaxf(mM[0], mx0);
        const float mn1 = fmaxf(mM[1], mx1);
        const float f0 = __expf(mM[0] - mn0);
        const float f1 = __expf(mM[1] - mn1);
        mM[0] = mn0; mM[1] = mn1;

        float rs0 = 0.f, rs1 = 0.f;
        #pragma unroll
        for (int nt = 0; nt < 8; nt++) {
            const __half2 p01 = __floats2half2_rn(__expf(sacc[nt][0] - mn0),
                                                  __expf(sacc[nt][1] - mn0));
            const __half2 p23 = __floats2half2_rn(__expf(sacc[nt][2] - mn1),
                                                  __expf(sacc[nt][3] - mn1));
            *(__half2*)&Psh[(m0 + qr)     * DPH + nt * 8 + 2 * qc] = p01;
            *(__half2*)&Psh[(m0 + qr + 8) * DPH + nt * 8 + 2 * qc] = p23;
            const float2 f01 = __half22float2(p01);
            const float2 f23 = __half22float2(p23);
            rs0 += f01.x + f01.y; rs1 += f23.x + f23.y;
        }
        #pragma unroll
        for (int off = 1; off < 4; off <<= 1) {
            rs0 += __shfl_xor_sync(0xffffffffu, rs0, off);
            rs1 += __shfl_xor_sync(0xffffffffu, rs1, off);
        }
        lL[0] = lL[0] * f0 + rs0;
        lL[1] = lL[1] * f1 + rs1;
        #pragma unroll
        for (int nt = 0; nt < 8; nt++) {
            oacc[nt][0] *= f0; oacc[nt][1] *= f0;
            oacc[nt][2] *= f1; oacc[nt][3] *= f1;
        }
        __syncwarp();

        tile_mma_16x64h(pAddr, vAddr, oacc);
    }

    // ---- compressive memory attention ----
    __syncthreads();
    load_kv_h(memp + h * 64, memp + h * 64, CDIM, Ksh, Vth, tid);
    __syncthreads();

    float sacc[8][4];
    #pragma unroll
    for (int nt = 0; nt < 8; nt++)
        #pragma unroll
        for (int r = 0; r < 4; r++) sacc[nt][r] = 0.f;
    tile_mma_16x64h(qAddr, kAddr, sacc);

    float mx0 = -1e30f, mx1 = -1e30f;
    #pragma unroll
    for (int nt = 0; nt < 8; nt++) {
        mx0 = fmaxf(mx0, fmaxf(sacc[nt][0], sacc[nt][1]));
        mx1 = fmaxf(mx1, fmaxf(sacc[nt][2], sacc[nt][3]));
    }
    #pragma unroll
    for (int off = 1; off < 4; off <<= 1) {
        mx0 = fmaxf(mx0, __shfl_xor_sync(0xffffffffu, mx0, off));
        mx1 = fmaxf(mx1, __shfl_xor_sync(0xffffffffu, mx1, off));
    }
    float rs0 = 0.f, rs1 = 0.f;
    #pragma unroll
    for (int nt = 0; nt < 8; nt++) {
        const __half2 p01 = __floats2half2_rn(__expf(sacc[nt][0] - mx0),
                                              __expf(sacc[nt][1] - mx0));
        const __half2 p23 = __floats2half2_rn(__expf(sacc[nt][2] - mx1),
                                              __expf(sacc[nt][3] - mx1));
        *(__half2*)&Psh[(m0 + qr)     * DPH + nt * 8 + 2 * qc] = p01;
        *(__half2*)&Psh[(m0 + qr + 8) * DPH + nt * 8 + 2 * qc] = p23;
        const float2 f01 = __half22float2(p01);
        const float2 f23 = __half22float2(p23);
        rs0 += f01.x + f01.y; rs1 += f23.x + f23.y;
    }
    #pragma unroll
    for (int off = 1; off < 4; off <<= 1) {
        rs0 += __shfl_xor_sync(0xffffffffu, rs0, off);
        rs1 += __shfl_xor_sync(0xffffffffu, rs1, off);
    }
    __syncwarp();

    float oacc2[8][4];
    #pragma unroll
    for (int nt = 0; nt < 8; nt++)
        #pragma unroll
        for (int r = 0; r < 4; r++) oacc2[nt][r] = 0.f;
    tile_mma_16x64h(pAddr, vAddr, oacc2);

    const float i0 = 1.f / lL[0], i1 = 1.f / lL[1];
    const float j0 = 1.f / rs0,   j1 = 1.f / rs1;
    #pragma unroll
    for (int nt = 0; nt < 8; nt++) {
        const int col = h * 64 + nt * 8 + 2 * qc;
        const int r0 = b * TSEQ + row0 + m0 + qr;
        *(__half2*)(out + (size_t)r0 * CDIM + col) =
            __floats2half2_rn(oacc[nt][0] * i0 + oacc2[nt][0] * j0,
                              oacc[nt][1] * i0 + oacc2[nt][1] * j0);
        *(__half2*)(out + (size_t)(r0 + 8) * CDIM + col) =
            __floats2half2_rn(oacc[nt][2] * i1 + oacc2[nt][2] * j1,
                              oacc[nt][3] * i1 + oacc2[nt][3] * j1);
    }
}

// ---------------- launch ----------------
extern "C" void kernel_launch(void* const* d_in, const int* in_sizes, int n_in,
                              void* d_out, int out_size)
{
    const float* x      = (const float*)d_in[0];
    const float* memory = (const float*)d_in[1];
    const float* ln1_g  = (const float*)d_in[2];
    const float* ln1_b  = (const float*)d_in[3];
    const float* w_qkv  = (const float*)d_in[4];
    const float* b_qkv  = (const float*)d_in[5];
    const float* w_out  = (const float*)d_in[6];
    const float* b_out  = (const float*)d_in[7];
    const float* w_mem  = (const float*)d_in[8];
    const float* b_mem  = (const float*)d_in[9];
    const float* ln2_g  = (const float*)d_in[10];
    const float* ln2_b  = (const float*)d_in[11];
    const float* w_fc1  = (const float*)d_in[12];
    const float* b_fc1  = (const float*)d_in[13];
    const float* w_fc2  = (const float*)d_in[14];
    const float* b_fc2  = (const float*)d_in[15];
    float* out = (float*)d_out;

    __half *pH, *pQKV, *pMEMP, *pATTN, *pH2, *pHID;
    __half *pWQKVT, *pWOUTT, *pWFC1T, *pWFC2T;
    float *pX1;
    cudaGetSymbolAddress((void**)&pH,     g_H);
    cudaGetSymbolAddress((void**)&pQKV,   g_QKV);
    cudaGetSymbolAddress((void**)&pMEMP,  g_MEMP);
    cudaGetSymbolAddress((void**)&pATTN,  g_ATTN);
    cudaGetSymbolAddress((void**)&pX1,    g_X1);
    cudaGetSymbolAddress((void**)&pH2,    g_H2);
    cudaGetSymbolAddress((void**)&pHID,   g_HID);
    cudaGetSymbolAddress((void**)&pWQKVT, g_WQKVT);
    cudaGetSymbolAddress((void**)&pWOUTT, g_WOUTT);
    cudaGetSymbolAddress((void**)&pWFC1T, g_WFC1T);
    cudaGetSymbolAddress((void**)&pWFC2T, g_WFC2T);

    cudaFuncSetAttribute(attn_mma, cudaFuncAttributeMaxDynamicSharedMemorySize, ATTN_SMEM);
    cudaFuncSetAttribute(gemm_mma<0, __half>, cudaFuncAttributeMaxDynamicSharedMemorySize, GSMEM_BYTES);
    cudaFuncSetAttribute(gemm_mma<1, float>,  cudaFuncAttributeMaxDynamicSharedMemorySize, GSMEM_BYTES);
    cudaFuncSetAttribute(gemm_mma<2, __half>, cudaFuncAttributeMaxDynamicSharedMemorySize, GSMEM_BYTES);

    const int ROWS = BATCH * TSEQ;  // 4096

    transpose_h<<<dim3(3 * CDIM / 32, CDIM / 32), 256>>>(w_qkv, pWQKVT, CDIM, 3 * CDIM);
    transpose_h<<<dim3(CDIM / 32, CDIM / 32), 256>>>(w_out, pWOUTT, CDIM, CDIM);
    transpose_h<<<dim3(HIDDEN / 32, CDIM / 32), 256>>>(w_fc1, pWFC1T, CDIM, HIDDEN);
    transpose_h<<<dim3(CDIM / 32, HIDDEN / 32), 256>>>(w_fc2, pWFC2T, HIDDEN, CDIM);

    ln_kernel<<<ROWS, 256>>>(x, ln1_g, ln1_b, pH);
    memproj_kernel<<<CDIM / 64, 256>>>(memory, w_mem, b_mem, pMEMP);

    gemm_mma<0, __half><<<dim3(3 * CDIM / 128, ROWS / 128), 256, GSMEM_BYTES>>>(
        pH, pWQKVT, b_qkv, nullptr, pQKV, ROWS, 3 * CDIM, CDIM);

    attn_mma<<<dim3(TSEQ / QT, NHEAD, BATCH), 256, ATTN_SMEM>>>(pQKV, pMEMP, pATTN);

    gemm_mma<1, float><<<dim3(CDIM / 128, ROWS / 128), 256, GSMEM_BYTES>>>(
        pATTN, pWOUTT, b_out, x, pX1, ROWS, CDIM, CDIM);

    ln_kernel<<<ROWS, 256>>>(pX1, ln2_g, ln2_b, pH2);

    gemm_mma<2, __half><<<dim3(HIDDEN / 128, ROWS / 128), 256, GSMEM_BYTES>>>(
        pH2, pWFC1T, b_fc1, nullptr, pHID, ROWS, HIDDEN, CDIM);

    gemm_mma<1, float><<<dim3(CDIM / 128, ROWS / 128), 256, GSMEM_BYTES>>>(
        pHID, pWFC2T, b_fc2, pX1, out, ROWS, CDIM, HIDDEN);
}

// round 9
// speedup vs baseline: 6.1326x; 1.1503x over previous
#include <cuda_runtime.h>
#include <cuda_fp16.h>
#include <math.h>
#include <stdint.h>

#define CDIM   1024
#define TSEQ   2048
#define BATCH  2
#define NHEAD  16
#define HDIM   64
#define MMEM   64
#define HIDDEN 4096

// ---------------- scratch (device globals; no allocation) ----------------
__device__ __half g_H    [BATCH*TSEQ*CDIM];
__device__ __half g_QKV  [BATCH*TSEQ*3*CDIM];
__device__ __half g_MEMP [MMEM*CDIM];
__device__ __half g_ATTN [BATCH*TSEQ*CDIM];
__device__ float  g_X1   [BATCH*TSEQ*CDIM];
__device__ __half g_H2   [BATCH*TSEQ*CDIM];
__device__ __half g_HID  [BATCH*TSEQ*HIDDEN];
__device__ __half g_WQKVT[3*CDIM*CDIM];
__device__ __half g_WOUTT[CDIM*CDIM];
__device__ __half g_WFC1T[HIDDEN*CDIM];
__device__ __half g_WFC2T[CDIM*HIDDEN];

__device__ __forceinline__ uint32_t smem_u32(const void* p) {
    uint32_t a;
    asm("{ .reg .u64 t; cvta.to.shared.u64 t, %1; cvt.u32.u64 %0, t; }" : "=r"(a) : "l"(p));
    return a;
}
__device__ __forceinline__ void cp16(uint32_t dst, const void* src) {
    asm volatile("cp.async.cg.shared.global [%0], [%1], 16;" :: "r"(dst), "l"(src));
}
__device__ __forceinline__ void mma_f16(float* c, uint32_t a0, uint32_t a1,
                                        uint32_t a2, uint32_t a3,
                                        uint32_t b0, uint32_t b1)
{
    asm volatile(
        "mma.sync.aligned.m16n8k16.row.col.f32.f16.f16.f32 "
        "{%0,%1,%2,%3}, {%4,%5,%6,%7}, {%8,%9}, {%0,%1,%2,%3};"
        : "+f"(c[0]), "+f"(c[1]), "+f"(c[2]), "+f"(c[3])
        : "r"(a0), "r"(a1), "r"(a2), "r"(a3), "r"(b0), "r"(b1));
}
__device__ __forceinline__ void ldsm4(uint32_t* r, uint32_t addr) {
    asm volatile("ldmatrix.sync.aligned.m8n8.x4.shared.b16 {%0,%1,%2,%3}, [%4];"
        : "=r"(r[0]), "=r"(r[1]), "=r"(r[2]), "=r"(r[3]) : "r"(addr));
}
__device__ __forceinline__ void ldsm4t(uint32_t* r, uint32_t addr) {
    asm volatile("ldmatrix.sync.aligned.m8n8.x4.trans.shared.b16 {%0,%1,%2,%3}, [%4];"
        : "=r"(r[0]), "=r"(r[1]), "=r"(r[2]), "=r"(r[3]) : "r"(addr));
}

// ---------------- LayerNorm (half output) ----------------
__global__ __launch_bounds__(256)
void ln_kernel(const float* __restrict__ x, const float* __restrict__ g,
               const float* __restrict__ b, __half* __restrict__ y)
{
    __shared__ float red[18];
    const int row = blockIdx.x;
    const int tid = threadIdx.x;
    const float4 v = ((const float4*)(x + (size_t)row * CDIM))[tid];
    float s  = v.x + v.y + v.z + v.w;
    float ss = v.x*v.x + v.y*v.y + v.z*v.z + v.w*v.w;
    #pragma unroll
    for (int off = 16; off; off >>= 1) {
        s  += __shfl_xor_sync(0xffffffffu, s,  off);
        ss += __shfl_xor_sync(0xffffffffu, ss, off);
    }
    if ((tid & 31) == 0) { red[tid >> 5] = s; red[8 + (tid >> 5)] = ss; }
    __syncthreads();
    if (tid == 0) {
        float ts = 0.f, tss = 0.f;
        #pragma unroll
        for (int w = 0; w < 8; w++) { ts += red[w]; tss += red[8 + w]; }
        red[16] = ts; red[17] = tss;
    }
    __syncthreads();
    const float mu  = red[16] * (1.f / CDIM);
    const float var = red[17] * (1.f / CDIM) - mu * mu;
    const float inv = rsqrtf(var + 1e-5f);
    const float4 gv = ((const float4*)g)[tid];
    const float4 bv = ((const float4*)b)[tid];
    __half2 h01 = __floats2half2_rn((v.x - mu) * inv * gv.x + bv.x,
                                    (v.y - mu) * inv * gv.y + bv.y);
    __half2 h23 = __floats2half2_rn((v.z - mu) * inv * gv.z + bv.z,
                                    (v.w - mu) * inv * gv.w + bv.w);
    __half2* yp = (__half2*)(y + (size_t)row * CDIM + tid * 4);
    yp[0] = h01; yp[1] = h23;
}

// ---------------- weight transpose + half convert ----------------
__global__ __launch_bounds__(256)
void transpose_h(const float* __restrict__ S, __half* __restrict__ D, int K, int N)
{
    __shared__ float t[32][33];
    const int bx = blockIdx.x * 32;
    const int by = blockIdx.y * 32;
    const int x = threadIdx.x & 31, y = threadIdx.x >> 5;
    #pragma unroll
    for (int i = 0; i < 32; i += 8)
        t[y + i][x] = S[(size_t)(by + y + i) * N + bx + x];
    __syncthreads();
    #pragma unroll
    for (int i = 0; i < 32; i += 8)
        D[(size_t)(bx + y + i) * K + by + x] = __float2half_rn(t[x][y + i]);
}

// ---------------- fp16 mma GEMM: 3-stage cp.async + ldmatrix, single sync/chunk ----------------
#define SKEWH 40
#define GST   (128 * SKEWH)
#define GSMEM_BYTES (3 * 2 * GST * 2)   // 61440

template<int EPI, typename TOut>
__global__ __launch_bounds__(256, 2)
void gemm_mma(const __half* __restrict__ A, const __half* __restrict__ Bt,
              const float* __restrict__ bias, const float* __restrict__ res,
              TOut* __restrict__ C, int M, int N, int K)
{
    extern __shared__ __half sgm[];
    const uint32_t sAa = smem_u32(sgm);
    const uint32_t sBa = sAa + 3u * GST * 2u;

    const int tid = threadIdx.x;
    const int wid = tid >> 5, lane = tid & 31;
    const int wm = (wid & 1) * 64;
    const int wn = (wid >> 1) * 32;
    const int bm = blockIdx.y * 128;
    const int bn = blockIdx.x * 128;

    const int lrow = tid >> 2;
    const int lcol = (tid & 3) << 3;
    const __half* Ap = A  + (size_t)(bm + lrow) * K + lcol;
    const __half* Bp = Bt + (size_t)(bn + lrow) * K + lcol;
    const uint32_t soff = ((uint32_t)lrow * SKEWH + (uint32_t)lcol) * 2u;

    const int qr = lane >> 2;
    const int qc = lane & 3;
    const int nchunk = K / 32;

    const int arow = lane & 15;
    const int acol = (lane >> 4) * 8;
    const int brow = (lane & 7) + ((lane & 16) ? 8 : 0);
    const int bcol = ((lane >> 3) & 1) * 8;
    const uint32_t aoffb = ((uint32_t)(wm + arow) * SKEWH + acol) * 2u;
    const uint32_t boffb = ((uint32_t)(wn + brow) * SKEWH + bcol) * 2u;

    float acc[4][4][4];
    #pragma unroll
    for (int i = 0; i < 4; i++)
        #pragma unroll
        for (int j = 0; j < 4; j++)
            #pragma unroll
            for (int r = 0; r < 4; r++) acc[i][j][r] = 0.f;

    // prologue: chunks 0,1 into stages 0,1
    #pragma unroll
    for (int pc = 0; pc < 2; pc++) {
        const uint32_t sb = (uint32_t)pc * GST * 2u;
        #pragma unroll
        for (int p = 0; p < 2; p++) {
            cp16(sAa + sb + soff + p * 64 * SKEWH * 2, Ap + (size_t)(p * 64) * K + pc * 32);
            cp16(sBa + sb + soff + p * 64 * SKEWH * 2, Bp + (size_t)(p * 64) * K + pc * 32);
        }
        asm volatile("cp.async.commit_group;");
    }

    int sc = 0;  // stage of current chunk
    for (int ch = 0; ch < nchunk; ch++) {
        asm volatile("cp.async.wait_group 1;");
        __syncthreads();

        // issue chunk ch+2 into stage (sc+2)%3
        if (ch + 2 < nchunk) {
            int sw = sc + 2; if (sw >= 3) sw -= 3;
            const uint32_t sb = (uint32_t)sw * GST * 2u;
            const int k0 = (ch + 2) * 32;
            #pragma unroll
            for (int p = 0; p < 2; p++) {
                cp16(sAa + sb + soff + p * 64 * SKEWH * 2, Ap + (size_t)(p * 64) * K + k0);
                cp16(sBa + sb + soff + p * 64 * SKEWH * 2, Bp + (size_t)(p * 64) * K + k0);
            }
        }
        asm volatile("cp.async.commit_group;");

        const uint32_t aB = sAa + (uint32_t)sc * GST * 2u + aoffb;
        const uint32_t bB = sBa + (uint32_t)sc * GST * 2u + boffb;

        #pragma unroll
        for (int ks = 0; ks < 2; ks++) {
            const uint32_t kb = ks * 32;
            uint32_t bb0[4], bb1[4];
            ldsm4(bb0, bB + kb);
            ldsm4(bb1, bB + 16u * SKEWH * 2u + kb);
            #pragma unroll
            for (int mt = 0; mt < 4; mt++) {
                uint32_t a[4];
                ldsm4(a, aB + (uint32_t)mt * 16u * SKEWH * 2u + kb);
                mma_f16(acc[mt][0], a[0], a[1], a[2], a[3], bb0[0], bb0[1]);
                mma_f16(acc[mt][1], a[0], a[1], a[2], a[3], bb0[2], bb0[3]);
                mma_f16(acc[mt][2], a[0], a[1], a[2], a[3], bb1[0], bb1[1]);
                mma_f16(acc[mt][3], a[0], a[1], a[2], a[3], bb1[2], bb1[3]);
            }
        }
        if (++sc == 3) sc = 0;
    }

    #pragma unroll
    for (int mt = 0; mt < 4; mt++) {
        #pragma unroll
        for (int half_ = 0; half_ < 2; half_++) {
            const int row = bm + wm + mt * 16 + qr + half_ * 8;
            const float* Rrow = res + (size_t)row * N;
            #pragma unroll
            for (int nt = 0; nt < 4; nt++) {
                const int col = bn + wn + nt * 8 + qc * 2;
                float v0 = acc[mt][nt][half_ * 2 + 0] + bias[col];
                float v1 = acc[mt][nt][half_ * 2 + 1] + bias[col + 1];
                if (EPI == 1) {
                    const float2 rv = *(const float2*)(Rrow + col);
                    v0 += rv.x; v1 += rv.y;
                }
                if (EPI == 2) {
                    v0 = 0.5f * v0 * (1.0f + erff(v0 * 0.70710678118654752f));
                    v1 = 0.5f * v1 * (1.0f + erff(v1 * 0.70710678118654752f));
                }
                TOut* Crow = C + (size_t)row * N;
                if (sizeof(TOut) == 2) {
                    *(__half2*)((__half*)Crow + col) = __floats2half2_rn(v0, v1);
                } else {
                    *(float2*)((float*)Crow + col) = make_float2(v0, v1);
                }
            }
        }
    }
}

// ---------------- memory projection -> half output ----------------
__global__ __launch_bounds__(256)
void memproj_kernel(const float* __restrict__ A, const float* __restrict__ B,
                    const float* __restrict__ bias, __half* __restrict__ C)
{
    __shared__ float Ast[16][64];
    __shared__ float Bs [16][64];
    const int tid = threadIdx.x;
    const int tx = tid & 15, ty = tid >> 4;
    const int bn = blockIdx.x * 64;
    const int ar = tid >> 2, ak = (tid & 3) << 2;
    const int bk = tid >> 4, bc = (tid & 15) << 2;

    float acc[4][4];
    #pragma unroll
    for (int i = 0; i < 4; i++)
        #pragma unroll
        for (int j = 0; j < 4; j++) acc[i][j] = 0.f;

    for (int k0 = 0; k0 < CDIM; k0 += 16) {
        const float4 av = *(const float4*)(A + (size_t)ar * CDIM + k0 + ak);
        const float4 bv = *(const float4*)(B + (size_t)(k0 + bk) * CDIM + bn + bc);
        __syncthreads();
        Ast[ak + 0][ar] = av.x;
        Ast[ak + 1][ar] = av.y;
        Ast[ak + 2][ar] = av.z;
        Ast[ak + 3][ar] = av.w;
        *(float4*)&Bs[bk][bc] = bv;
        __syncthreads();
        #pragma unroll
        for (int kk = 0; kk < 16; kk++) {
            const float4 a = *(const float4*)&Ast[kk][ty * 4];
            const float4 b = *(const float4*)&Bs[kk][tx * 4];
            const float arr[4] = {a.x, a.y, a.z, a.w};
            const float brr[4] = {b.x, b.y, b.z, b.w};
            #pragma unroll
            for (int i = 0; i < 4; i++)
                #pragma unroll
                for (int j = 0; j < 4; j++)
                    acc[i][j] = fmaf(arr[i], brr[j], acc[i][j]);
        }
    }
    #pragma unroll
    for (int i = 0; i < 4; i++) {
        const int col = bn + tx * 4;
        const float4 bsv = *(const float4*)(bias + col);
        __half2* cp = (__half2*)(C + (size_t)(ty * 4 + i) * CDIM + col);
        cp[0] = __floats2half2_rn(acc[i][0] + bsv.x, acc[i][1] + bsv.y);
        cp[1] = __floats2half2_rn(acc[i][2] + bsv.z, acc[i][3] + bsv.w);
    }
}

// ---------------- fp16 mma attention: cp.async double-buffered K/V + ldmatrix(.trans) ----------------
#define QT   128
#define KC   64
#define DPH  72
// halfs: Qsh[128][72] | Kst[2][64][72] | Vst[2][64][72] | Psh[128][72]
#define ATTN_SMEM ((128*DPH + 2*64*DPH + 2*64*DPH + 128*DPH) * 2)   // 73728

// issue cp.async loads of one K row-chunk and one V row-chunk (rows as-is)
__device__ __forceinline__ void issue_kv(uint32_t kDst, uint32_t vDst,
                                         const __half* __restrict__ kSrc,
                                         const __half* __restrict__ vSrc,
                                         size_t rstride, int tid)
{
    const int r = tid >> 2;
    const uint32_t off = (uint32_t)r * DPH * 2u + (uint32_t)(tid & 3) * 32u;
    const __half* ks = kSrc + (size_t)r * rstride + (tid & 3) * 16;
    const __half* vs = vSrc + (size_t)r * rstride + (tid & 3) * 16;
    cp16(kDst + off,       ks);
    cp16(kDst + off + 16u, ks + 8);
    cp16(vDst + off,       vs);
    cp16(vDst + off + 16u, vs + 8);
}

// acc[16x64] += A[16m x 64k] @ K[64n x 64k]^T   (B normal fragments)
__device__ __forceinline__ void tile_mma_qk(uint32_t aAddr, uint32_t bAddr, float acc[8][4])
{
    #pragma unroll
    for (int ks = 0; ks < 4; ks++) {
        const uint32_t kb = ks * 32;
        uint32_t a[4];
        ldsm4(a, aAddr + kb);
        #pragma unroll
        for (int p = 0; p < 4; p++) {
            uint32_t bb[4];
            ldsm4(bb, bAddr + (uint32_t)p * 16u * DPH * 2u + kb);
            mma_f16(acc[2 * p],     a[0], a[1], a[2], a[3], bb[0], bb[1]);
            mma_f16(acc[2 * p + 1], a[0], a[1], a[2], a[3], bb[2], bb[3]);
        }
    }
}

// acc[16x64] += P[16m x 64key] @ V[64key x 64d]  (B via ldmatrix.trans on row-major V)
__device__ __forceinline__ void tile_mma_pv(uint32_t aAddr, uint32_t bAddr, float acc[8][4])
{
    #pragma unroll
    for (int ks = 0; ks < 4; ks++) {
        const uint32_t kb = ks * 32;                 // P cols (key) advance
        const uint32_t vb = (uint32_t)ks * 16u * DPH * 2u;  // V rows (key) advance
        uint32_t a[4];
        ldsm4(a, aAddr + kb);
        #pragma unroll
        for (int p = 0; p < 4; p++) {
            uint32_t bb[4];
            ldsm4t(bb, bAddr + vb + (uint32_t)p * 32u);      // V cols (d) advance
            mma_f16(acc[2 * p],     a[0], a[1], a[2], a[3], bb[0], bb[1]);
            mma_f16(acc[2 * p + 1], a[0], a[1], a[2], a[3], bb[2], bb[3]);
        }
    }
}

__global__ __launch_bounds__(256)
void attn_mma(const __half* __restrict__ qkv, const __half* __restrict__ memp,
              __half* __restrict__ out)
{
    extern __shared__ __half smh[];
    __half* Qsh = smh;
    __half* Kst = smh + 128 * DPH;          // 2 stages x 64 x DPH
    __half* Vst = Kst + 2 * 64 * DPH;
    __half* Psh = Vst + 2 * 64 * DPH;

    const int tid  = threadIdx.x;
    const int wid  = tid >> 5, lane = tid & 31;
    const int qr   = lane >> 2, qc = lane & 3;
    const int m0   = wid * 16;
    const int h    = blockIdx.y, b = blockIdx.z;
    const int row0 = blockIdx.x * QT;

    const int arow = lane & 15;
    const int acol = (lane >> 4) * 8;
    const int brow = (lane & 7) + ((lane & 16) ? 8 : 0);
    const int bcol = ((lane >> 3) & 1) * 8;

    const uint32_t qAddr = smem_u32(Qsh) + ((uint32_t)(m0 + arow) * DPH + acol) * 2u;
    const uint32_t pAddr = smem_u32(Psh) + ((uint32_t)(m0 + arow) * DPH + acol) * 2u;
    const uint32_t kBase = smem_u32(Kst);
    const uint32_t vBase = smem_u32(Vst);
    const uint32_t kFragOff = ((uint32_t)brow * DPH + bcol) * 2u;
    const uint32_t vFragOff = ((uint32_t)arow * DPH + acol) * 2u;   // trans: row=key, col=d
    const uint32_t stageB = 64u * DPH * 2u;

    const __half* kSrc0 = qkv + ((size_t)(b * TSEQ)) * (3 * CDIM) + CDIM + h * 64;
    const __half* vSrc0 = qkv + ((size_t)(b * TSEQ)) * (3 * CDIM) + 2 * CDIM + h * 64;

    // Q load: scaled by 0.125
    {
        const int r  = tid >> 1;
        const int c0 = (tid & 1) * 32;
        const __half2 sc = __float2half2_rn(0.125f);
        const __half2* qp = (const __half2*)(qkv + ((size_t)(b * TSEQ + row0 + r)) * (3 * CDIM) + h * 64 + c0);
        __half2* qd = (__half2*)&Qsh[r * DPH + c0];
        #pragma unroll
        for (int j = 0; j < 16; j++)
            qd[j] = __hmul2(qp[j], sc);
    }

    // prologue: chunk 0 into stage 0
    issue_kv(kBase, vBase, kSrc0, vSrc0, 3 * CDIM, tid);
    asm volatile("cp.async.commit_group;");

    float mM[2] = {-1e30f, -1e30f};
    float lL[2] = {0.f, 0.f};
    float oacc[8][4];
    #pragma unroll
    for (int nt = 0; nt < 8; nt++)
        #pragma unroll
        for (int r = 0; r < 4; r++) oacc[nt][r] = 0.f;

    const int NCH = TSEQ / KC;   // 32
    for (int ci = 0; ci < NCH; ci++) {
        asm volatile("cp.async.wait_group 0;");
        __syncthreads();   // chunk ci visible; all warps past iter ci-1 (stage (ci+1)&1 free)

        if (ci + 1 < NCH) {
            const int sn = (ci + 1) & 1;
            issue_kv(kBase + (uint32_t)sn * stageB, vBase + (uint32_t)sn * stageB,
                     kSrc0 + (size_t)(ci + 1) * KC * (3 * CDIM),
                     vSrc0 + (size_t)(ci + 1) * KC * (3 * CDIM),
                     3 * CDIM, tid);
        }
        asm volatile("cp.async.commit_group;");

        const int st = ci & 1;
        const uint32_t kAddr = kBase + (uint32_t)st * stageB + kFragOff;
        const uint32_t vAddr = vBase + (uint32_t)st * stageB + vFragOff;

        float sacc[8][4];
        #pragma unroll
        for (int nt = 0; nt < 8; nt++)
            #pragma unroll
            for (int r = 0; r < 4; r++) sacc[nt][r] = 0.f;
        tile_mma_qk(qAddr, kAddr, sacc);

        float mx0 = -1e30f, mx1 = -1e30f;
        #pragma unroll
        for (int nt = 0; nt < 8; nt++) {
            mx0 = fmaxf(mx0, fmaxf(sacc[nt][0], sacc[nt][1]));
            mx1 = fmaxf(mx1, fmaxf(sacc[nt][2], sacc[nt][3]));
        }
        #pragma unroll
        for (int off = 1; off < 4; off <<= 1) {
            mx0 = fmaxf(mx0, __shfl_xor_sync(0xffffffffu, mx0, off));
            mx1 = fmaxf(mx1, __shfl_xor_sync(0xffffffffu, mx1, off));
        }
        const float mn0 = fmaxf(mM[0], mx0);
        const float mn1 = fmaxf(mM[1], mx1);
        const float f0 = __expf(mM[0] - mn0);
        const float f1 = __expf(mM[1] - mn1);
        mM[0] = mn0; mM[1] = mn1;

        float rs0 = 0.f, rs1 = 0.f;
        #pragma unroll
        for (int nt = 0; nt < 8; nt++) {
            const __half2 p01 = __floats2half2_rn(__expf(sacc[nt][0] - mn0),
                                                  __expf(sacc[nt][1] - mn0));
            const __half2 p23 = __floats2half2_rn(__expf(sacc[nt][2] - mn1),
                                                  __expf(sacc[nt][3] - mn1));
            *(__half2*)&Psh[(m0 + qr)     * DPH + nt * 8 + 2 * qc] = p01;
            *(__half2*)&Psh[(m0 + qr + 8) * DPH + nt * 8 + 2 * qc] = p23;
            const float2 f01 = __half22float2(p01);
            const float2 f23 = __half22float2(p23);
            rs0 += f01.x + f01.y; rs1 += f23.x + f23.y;
        }
        #pragma unroll
        for (int off = 1; off < 4; off <<= 1) {
            rs0 += __shfl_xor_sync(0xffffffffu, rs0, off);
            rs1 += __shfl_xor_sync(0xffffffffu, rs1, off);
        }
        lL[0] = lL[0] * f0 + rs0;
        lL[1] = lL[1] * f1 + rs1;
        #pragma unroll
        for (int nt = 0; nt < 8; nt++) {
            oacc[nt][0] *= f0; oacc[nt][1] *= f0;
            oacc[nt][2] *= f1; oacc[nt][3] *= f1;
        }
        __syncwarp();

        tile_mma_pv(pAddr, vAddr, oacc);
    }

    // ---- compressive memory attention (stage 0; mem K == mem V) ----
    __syncthreads();   // all warps done reading stage 0 (last read iter NCH-2)
    issue_kv(kBase, vBase, memp + h * 64, memp + h * 64, CDIM, tid);
    asm volatile("cp.async.commit_group;");
    asm volatile("cp.async.wait_group 0;");
    __syncthreads();

    float sacc[8][4];
    #pragma unroll
    for (int nt = 0; nt < 8; nt++)
        #pragma unroll
        for (int r = 0; r < 4; r++) sacc[nt][r] = 0.f;
    tile_mma_qk(qAddr, kBase + kFragOff, sacc);

    float mx0 = -1e30f, mx1 = -1e30f;
    #pragma unroll
    for (int nt = 0; nt < 8; nt++) {
        mx0 = fmaxf(mx0, fmaxf(sacc[nt][0], sacc[nt][1]));
        mx1 = fmaxf(mx1, fmaxf(sacc[nt][2], sacc[nt][3]));
    }
    #pragma unroll
    for (int off = 1; off < 4; off <<= 1) {
        mx0 = fmaxf(mx0, __shfl_xor_sync(0xffffffffu, mx0, off));
        mx1 = fmaxf(mx1, __shfl_xor_sync(0xffffffffu, mx1, off));
    }
    float rs0 = 0.f, rs1 = 0.f;
    #pragma unroll
    for (int nt = 0; nt < 8; nt++) {
        const __half2 p01 = __floats2half2_rn(__expf(sacc[nt][0] - mx0),
                                              __expf(sacc[nt][1] - mx0));
        const __half2 p23 = __floats2half2_rn(__expf(sacc[nt][2] - mx1),
                                              __expf(sacc[nt][3] - mx1));
        *(__half2*)&Psh[(m0 + qr)     * DPH + nt * 8 + 2 * qc] = p01;
        *(__half2*)&Psh[(m0 + qr + 8) * DPH + nt * 8 + 2 * qc] = p23;
        const float2 f01 = __half22float2(p01);
        const float2 f23 = __half22float2(p23);
        rs0 += f01.x + f01.y; rs1 += f23.x + f23.y;
    }
    #pragma unroll
    for (int off = 1; off < 4; off <<= 1) {
        rs0 += __shfl_xor_sync(0xffffffffu, rs0, off);
        rs1 += __shfl_xor_sync(0xffffffffu, rs1, off);
    }
    __syncwarp();

    float oacc2[8][4];
    #pragma unroll
    for (int nt = 0; nt < 8; nt++)
        #pragma unroll
        for (int r = 0; r < 4; r++) oacc2[nt][r] = 0.f;
    tile_mma_pv(pAddr, vBase + vFragOff, oacc2);

    const float i0 = 1.f / lL[0], i1 = 1.f / lL[1];
    const float j0 = 1.f / rs0,   j1 = 1.f / rs1;
    #pragma unroll
    for (int nt = 0; nt < 8; nt++) {
        const int col = h * 64 + nt * 8 + 2 * qc;
        const int r0 = b * TSEQ + row0 + m0 + qr;
        *(__half2*)(out + (size_t)r0 * CDIM + col) =
            __floats2half2_rn(oacc[nt][0] * i0 + oacc2[nt][0] * j0,
                              oacc[nt][1] * i0 + oacc2[nt][1] * j0);
        *(__half2*)(out + (size_t)(r0 + 8) * CDIM + col) =
            __floats2half2_rn(oacc[nt][2] * i1 + oacc2[nt][2] * j1,
                              oacc[nt][3] * i1 + oacc2[nt][3] * j1);
    }
}

// ---------------- launch ----------------
extern "C" void kernel_launch(void* const* d_in, const int* in_sizes, int n_in,
                              void* d_out, int out_size)
{
    const float* x      = (const float*)d_in[0];
    const float* memory = (const float*)d_in[1];
    const float* ln1_g  = (const float*)d_in[2];
    const float* ln1_b  = (const float*)d_in[3];
    const float* w_qkv  = (const float*)d_in[4];
    const float* b_qkv  = (const float*)d_in[5];
    const float* w_out  = (const float*)d_in[6];
    const float* b_out  = (const float*)d_in[7];
    const float* w_mem  = (const float*)d_in[8];
    const float* b_mem  = (const float*)d_in[9];
    const float* ln2_g  = (const float*)d_in[10];
    const float* ln2_b  = (const float*)d_in[11];
    const float* w_fc1  = (const float*)d_in[12];
    const float* b_fc1  = (const float*)d_in[13];
    const float* w_fc2  = (const float*)d_in[14];
    const float* b_fc2  = (const float*)d_in[15];
    float* out = (float*)d_out;

    __half *pH, *pQKV, *pMEMP, *pATTN, *pH2, *pHID;
    __half *pWQKVT, *pWOUTT, *pWFC1T, *pWFC2T;
    float *pX1;
    cudaGetSymbolAddress((void**)&pH,     g_H);
    cudaGetSymbolAddress((void**)&pQKV,   g_QKV);
    cudaGetSymbolAddress((void**)&pMEMP,  g_MEMP);
    cudaGetSymbolAddress((void**)&pATTN,  g_ATTN);
    cudaGetSymbolAddress((void**)&pX1,    g_X1);
    cudaGetSymbolAddress((void**)&pH2,    g_H2);
    cudaGetSymbolAddress((void**)&pHID,   g_HID);
    cudaGetSymbolAddress((void**)&pWQKVT, g_WQKVT);
    cudaGetSymbolAddress((void**)&pWOUTT, g_WOUTT);
    cudaGetSymbolAddress((void**)&pWFC1T, g_WFC1T);
    cudaGetSymbolAddress((void**)&pWFC2T, g_WFC2T);

    cudaFuncSetAttribute(attn_mma, cudaFuncAttributeMaxDynamicSharedMemorySize, ATTN_SMEM);
    cudaFuncSetAttribute(gemm_mma<0, __half>, cudaFuncAttributeMaxDynamicSharedMemorySize, GSMEM_BYTES);
    cudaFuncSetAttribute(gemm_mma<1, float>,  cudaFuncAttributeMaxDynamicSharedMemorySize, GSMEM_BYTES);
    cudaFuncSetAttribute(gemm_mma<2, __half>, cudaFuncAttributeMaxDynamicSharedMemorySize, GSMEM_BYTES);

    const int ROWS = BATCH * TSEQ;  // 4096

    transpose_h<<<dim3(3 * CDIM / 32, CDIM / 32), 256>>>(w_qkv, pWQKVT, CDIM, 3 * CDIM);
    transpose_h<<<dim3(CDIM / 32, CDIM / 32), 256>>>(w_out, pWOUTT, CDIM, CDIM);
    transpose_h<<<dim3(HIDDEN / 32, CDIM / 32), 256>>>(w_fc1, pWFC1T, CDIM, HIDDEN);
    transpose_h<<<dim3(CDIM / 32, HIDDEN / 32), 256>>>(w_fc2, pWFC2T, HIDDEN, CDIM);

    ln_kernel<<<ROWS, 256>>>(x, ln1_g, ln1_b, pH);
    memproj_kernel<<<CDIM / 64, 256>>>(memory, w_mem, b_mem, pMEMP);

    gemm_mma<0, __half><<<dim3(3 * CDIM / 128, ROWS / 128), 256, GSMEM_BYTES>>>(
        pH, pWQKVT, b_qkv, nullptr, pQKV, ROWS, 3 * CDIM, CDIM);

    attn_mma<<<dim3(TSEQ / QT, NHEAD, BATCH), 256, ATTN_SMEM>>>(pQKV, pMEMP, pATTN);

    gemm_mma<1, float><<<dim3(CDIM / 128, ROWS / 128), 256, GSMEM_BYTES>>>(
        pATTN, pWOUTT, b_out, x, pX1, ROWS, CDIM, CDIM);

    ln_kernel<<<ROWS, 256>>>(pX1, ln2_g, ln2_b, pH2);

    gemm_mma<2, __half><<<dim3(HIDDEN / 128, ROWS / 128), 256, GSMEM_BYTES>>>(
        pH2, pWFC1T, b_fc1, nullptr, pHID, ROWS, HIDDEN, CDIM);

    gemm_mma<1, float><<<dim3(CDIM / 128, ROWS / 128), 256, GSMEM_BYTES>>>(
        pHID, pWFC2T, b_fc2, pX1, out, ROWS, CDIM, HIDDEN);
}